// round 1
// baseline (speedup 1.0000x reference)
#include <cuda_runtime.h>
#include <math.h>
#include <float.h>

// Problem constants
#define BB 2
#define NN 4096
#define KNBR 20
#define NPTS (BB*NN)            // 8192
#define NROWS (NPTS*KNBR)       // 163840
#define C1 128
#define C2 256
#define C3 512
#define CH 384
#define BN_EPS 1e-5f
#define STAT_BLOCKS 1024
#define ROWS_PER_STAT (NROWS/STAT_BLOCKS) // 160

// Scratch (static device globals; no runtime allocation)
__device__ int   g_idx[NROWS];
__device__ float g_part1[STAT_BLOCKS*2*C1];
__device__ float g_ss1[2*C1];              // scale[128], shift[128]
__device__ float g_fpre[(size_t)NROWS*C3]; // 335 MB pre-BN3 activations
__device__ float g_part3[STAT_BLOCKS*2*C3];
__device__ float g_ss3[2*C3];              // scale[512], shift[512]

// ---------------------------------------------------------------------------
// K1: KNN. One block per point. Build d2 row in smem, then 20 argmin rounds.
// Only the SET of 20 nearest matters downstream (BN + max pooling are
// neighbor-order invariant), so tie-break details are irrelevant.
// ---------------------------------------------------------------------------
__global__ void knn_kernel(const float* __restrict__ xyz) {
    __shared__ float sd[NN];
    __shared__ float rv[256];
    __shared__ int   ri[256];
    int p = blockIdx.x;
    int b = p >> 12, n = p & (NN-1);
    int t = threadIdx.x;
    const float* base = xyz + (size_t)b*NN*3;
    float cx = base[n*3+0], cy = base[n*3+1], cz = base[n*3+2];
    float pp = cx*cx + cy*cy + cz*cz;
    for (int m = t; m < NN; m += 256) {
        float qx = base[m*3+0], qy = base[m*3+1], qz = base[m*3+2];
        float qq = qx*qx + qy*qy + qz*qz;
        float pq = cx*qx + cy*qy + cz*qz;
        sd[m] = pp + qq - 2.f*pq;
    }
    __syncthreads();
    for (int round = 0; round < KNBR; ++round) {
        float bv = FLT_MAX; int bi = NN;
        for (int m = t; m < NN; m += 256) {
            float v = sd[m];
            if (v < bv) { bv = v; bi = m; }
        }
        rv[t] = bv; ri[t] = bi;
        __syncthreads();
        #pragma unroll
        for (int s = 128; s > 0; s >>= 1) {
            if (t < s) {
                float ov = rv[t+s]; int oi = ri[t+s];
                if (ov < rv[t] || (ov == rv[t] && oi < ri[t])) { rv[t] = ov; ri[t] = oi; }
            }
            __syncthreads();
        }
        if (t == 0) {
            g_idx[p*KNBR + round] = ri[0];
            sd[ri[0]] = FLT_MAX;
        }
        __syncthreads();
    }
}

// ---------------------------------------------------------------------------
// K2: BN1 stats, stage 1. Recompute h1 = edge@W1 + b1 on the fly (cheap),
// accumulate per-channel sum/sumsq per block (deterministic 2-stage reduce).
// ---------------------------------------------------------------------------
__global__ void stats1_kernel(const float* __restrict__ xyz,
                              const float* __restrict__ W1,
                              const float* __restrict__ b1) {
    __shared__ float se[ROWS_PER_STAT*6];
    int blk = blockIdx.x, t = threadIdx.x;   // 128 threads
    int row0 = blk * ROWS_PER_STAT;
    for (int r = t; r < ROWS_PER_STAT; r += 128) {
        int gr = row0 + r;
        int p  = gr / KNBR;
        int b  = p >> 12, n = p & (NN-1);
        int id = g_idx[gr];
        const float* cb = xyz + ((size_t)b*NN + n)*3;
        const float* nb = xyz + ((size_t)b*NN + id)*3;
        se[r*6+0] = nb[0]-cb[0];
        se[r*6+1] = nb[1]-cb[1];
        se[r*6+2] = nb[2]-cb[2];
        se[r*6+3] = cb[0]; se[r*6+4] = cb[1]; se[r*6+5] = cb[2];
    }
    __syncthreads();
    float w0 = W1[0*C1+t], w1 = W1[1*C1+t], w2 = W1[2*C1+t],
          w3 = W1[3*C1+t], w4 = W1[4*C1+t], w5 = W1[5*C1+t], bb = b1[t];
    float s = 0.f, q = 0.f;
    for (int r = 0; r < ROWS_PER_STAT; ++r) {
        float h = bb + se[r*6+0]*w0 + se[r*6+1]*w1 + se[r*6+2]*w2
                     + se[r*6+3]*w3 + se[r*6+4]*w4 + se[r*6+5]*w5;
        s += h; q += h*h;
    }
    g_part1[blk*(2*C1) + t]      = s;
    g_part1[blk*(2*C1) + C1 + t] = q;
}

__global__ void fin1_kernel(const float* __restrict__ g1,
                            const float* __restrict__ be1) {
    int c = threadIdx.x;   // 128
    float s = 0.f, q = 0.f;
    for (int i = 0; i < STAT_BLOCKS; ++i) {
        s += g_part1[i*(2*C1)+c];
        q += g_part1[i*(2*C1)+C1+c];
    }
    float mu  = s / (float)NROWS;
    float var = q / (float)NROWS - mu*mu;
    float sc  = g1[c] * rsqrtf(var + BN_EPS);
    g_ss1[c]     = sc;
    g_ss1[C1+c]  = be1[c] - mu*sc;
}

// ---------------------------------------------------------------------------
// K4: mega kernel. One block per point (20 neighbor rows).
//   A  = relu(bn1(edge@W1+b1))            [20x128] smem
//   h2 = A@W2 + b2                        [20x256] smem (+ per-point gmax)
//   fA = gmax@W3[0:256] + b3              [512]    smem (per point, NOT per k)
//   fpre = h2@W3[256:512] + fA  -> g_fpre [20x512] global
// 2 output cols per thread in the big GEMM: 1 LDS feeds 2 FMAs.
// ---------------------------------------------------------------------------
__global__ __launch_bounds__(256) void mega_kernel(
    const float* __restrict__ xyz,
    const float* __restrict__ W1, const float* __restrict__ b1,
    const float* __restrict__ W2, const float* __restrict__ b2,
    const float* __restrict__ W3, const float* __restrict__ b3) {
    __shared__ float sE[KNBR*6];
    __shared__ float sA[KNBR*C1];
    __shared__ float sH[KNBR*C2];
    __shared__ float sG[C2];
    __shared__ float sFA[C3];
    int p = blockIdx.x, t = threadIdx.x;
    int b = p >> 12, n = p & (NN-1);

    if (t < KNBR) {
        int id = g_idx[p*KNBR + t];
        const float* cb = xyz + ((size_t)b*NN + n)*3;
        const float* nb = xyz + ((size_t)b*NN + id)*3;
        sE[t*6+0] = nb[0]-cb[0]; sE[t*6+1] = nb[1]-cb[1]; sE[t*6+2] = nb[2]-cb[2];
        sE[t*6+3] = cb[0];       sE[t*6+4] = cb[1];       sE[t*6+5] = cb[2];
    }
    __syncthreads();

    for (int e = t; e < KNBR*C1; e += 256) {
        int r = e >> 7, c = e & (C1-1);
        float h = b1[c];
        #pragma unroll
        for (int d = 0; d < 6; ++d) h += sE[r*6+d]*W1[d*C1+c];
        sA[e] = fmaxf(h * g_ss1[c] + g_ss1[C1+c], 0.f);
    }
    __syncthreads();

    {   // h2 + gmax: one column per thread
        int c = t;
        float acc[KNBR];
        float bb = b2[c];
        #pragma unroll
        for (int r = 0; r < KNBR; ++r) acc[r] = bb;
        for (int j = 0; j < C1; ++j) {
            float w = W2[j*C2+c];
            #pragma unroll
            for (int r = 0; r < KNBR; ++r) acc[r] += sA[r*C1+j]*w;
        }
        float gm = acc[0];
        #pragma unroll
        for (int r = 0; r < KNBR; ++r) { sH[r*C2+c] = acc[r]; gm = fmaxf(gm, acc[r]); }
        sG[c] = gm;
    }
    __syncthreads();

    {   // fA = gmax @ W3a + b3 : two columns per thread
        int c0 = t, c1 = t + C2;
        float a0 = b3[c0], a1 = b3[c1];
        for (int j = 0; j < C2; ++j) {
            float g = sG[j];
            a0 += g * W3[j*C3+c0];
            a1 += g * W3[j*C3+c1];
        }
        sFA[c0] = a0; sFA[c1] = a1;
    }
    __syncthreads();

    {   // fpre = h2 @ W3b + fA : two columns per thread
        int c0 = t, c1 = t + C2;
        float acc0[KNBR], acc1[KNBR];
        #pragma unroll
        for (int r = 0; r < KNBR; ++r) { acc0[r] = 0.f; acc1[r] = 0.f; }
        for (int j = 0; j < C2; ++j) {
            float w0 = W3[(C2+j)*C3+c0];
            float w1 = W3[(C2+j)*C3+c1];
            #pragma unroll
            for (int r = 0; r < KNBR; ++r) {
                float a = sH[r*C2+j];
                acc0[r] += a*w0;
                acc1[r] += a*w1;
            }
        }
        float fa0 = sFA[c0], fa1 = sFA[c1];
        size_t base = (size_t)p*KNBR*C3;
        #pragma unroll
        for (int r = 0; r < KNBR; ++r) {
            g_fpre[base + r*C3 + c0] = acc0[r] + fa0;
            g_fpre[base + r*C3 + c1] = acc1[r] + fa1;
        }
    }
}

// ---------------------------------------------------------------------------
// K5/K6: BN3 stats (deterministic 2-stage)
// ---------------------------------------------------------------------------
__global__ void stats3_kernel() {
    int blk = blockIdx.x, t = threadIdx.x;   // 256 threads
    size_t row0 = (size_t)blk * ROWS_PER_STAT;
    float s0 = 0.f, q0 = 0.f, s1 = 0.f, q1 = 0.f;
    for (int r = 0; r < ROWS_PER_STAT; ++r) {
        size_t base = (row0 + r)*C3;
        float v0 = g_fpre[base + t];
        float v1 = g_fpre[base + C2 + t];
        s0 += v0; q0 += v0*v0;
        s1 += v1; q1 += v1*v1;
    }
    g_part3[blk*(2*C3) + t]           = s0;
    g_part3[blk*(2*C3) + C2 + t]      = s1;
    g_part3[blk*(2*C3) + C3 + t]      = q0;
    g_part3[blk*(2*C3) + C3 + C2 + t] = q1;
}

__global__ void fin3_kernel(const float* __restrict__ g3,
                            const float* __restrict__ be3) {
    int c = threadIdx.x;   // 512
    float s = 0.f, q = 0.f;
    for (int i = 0; i < STAT_BLOCKS; ++i) {
        s += g_part3[i*(2*C3)+c];
        q += g_part3[i*(2*C3)+C3+c];
    }
    float mu  = s / (float)NROWS;
    float var = q / (float)NROWS - mu*mu;
    float sc  = g3[c] * rsqrtf(var + BN_EPS);
    g_ss3[c]    = sc;
    g_ss3[C3+c] = be3[c] - mu*sc;
}

// ---------------------------------------------------------------------------
// K7: final. One block per point.
//   A = relu(bn3(fpre))  [20x512] smem (40KB)
//   out = max_r (A@W4)_r + b4, 2 cols/thread (192 threads, 384 cols).
// ---------------------------------------------------------------------------
__global__ __launch_bounds__(192) void final_kernel(
    const float* __restrict__ W4, const float* __restrict__ b4,
    float* __restrict__ out) {
    __shared__ float sA[KNBR*C3];
    int p = blockIdx.x, t = threadIdx.x;
    size_t base = (size_t)p*KNBR*C3;
    for (int e = t; e < KNBR*C3; e += 192) {
        int c = e & (C3-1);
        float v = g_fpre[base + e];
        sA[e] = fmaxf(v*g_ss3[c] + g_ss3[C3+c], 0.f);
    }
    __syncthreads();
    int c0 = t, c1 = t + 192;
    float acc0[KNBR], acc1[KNBR];
    #pragma unroll
    for (int r = 0; r < KNBR; ++r) { acc0[r] = 0.f; acc1[r] = 0.f; }
    for (int j = 0; j < C3; ++j) {
        float w0 = W4[j*CH+c0], w1 = W4[j*CH+c1];
        #pragma unroll
        for (int r = 0; r < KNBR; ++r) {
            float a = sA[r*C3+j];
            acc0[r] += a*w0;
            acc1[r] += a*w1;
        }
    }
    float m0 = acc0[0], m1 = acc1[0];
    #pragma unroll
    for (int r = 1; r < KNBR; ++r) { m0 = fmaxf(m0, acc0[r]); m1 = fmaxf(m1, acc1[r]); }
    out[(size_t)BB*NN*3 + (size_t)p*CH + c0] = m0 + b4[c0];
    out[(size_t)BB*NN*3 + (size_t)p*CH + c1] = m1 + b4[c1];
}

// Output tuple element 0: xyz passthrough
__global__ void copy_xyz_kernel(const float* __restrict__ xyz,
                                float* __restrict__ out) {
    int i = blockIdx.x*256 + threadIdx.x;
    if (i < BB*NN*3) out[i] = xyz[i];
}

extern "C" void kernel_launch(void* const* d_in, const int* in_sizes, int n_in,
                              void* d_out, int out_size) {
    (void)in_sizes; (void)n_in; (void)out_size;
    const float* xyz = (const float*)d_in[0];
    const float* W1  = (const float*)d_in[1];
    const float* b1  = (const float*)d_in[2];
    const float* g1  = (const float*)d_in[3];
    const float* be1 = (const float*)d_in[4];
    const float* W2  = (const float*)d_in[5];
    const float* b2  = (const float*)d_in[6];
    const float* W3  = (const float*)d_in[7];
    const float* b3  = (const float*)d_in[8];
    const float* g3  = (const float*)d_in[9];
    const float* be3 = (const float*)d_in[10];
    const float* W4  = (const float*)d_in[11];
    const float* b4  = (const float*)d_in[12];
    float* out = (float*)d_out;

    knn_kernel<<<NPTS, 256>>>(xyz);
    stats1_kernel<<<STAT_BLOCKS, 128>>>(xyz, W1, b1);
    fin1_kernel<<<1, C1>>>(g1, be1);
    mega_kernel<<<NPTS, 256>>>(xyz, W1, b1, W2, b2, W3, b3);
    stats3_kernel<<<STAT_BLOCKS, 256>>>();
    fin3_kernel<<<1, C3>>>(g3, be3);
    final_kernel<<<NPTS, 192>>>(W4, b4, out);
    copy_xyz_kernel<<<(BB*NN*3 + 255)/256, 256>>>(xyz, out);
}

// round 2
// speedup vs baseline: 2.3994x; 2.3994x over previous
#include <cuda_runtime.h>
#include <math.h>
#include <float.h>

// Problem constants
#define BB 2
#define NN 4096
#define KNBR 20
#define NPTS (BB*NN)            // 8192
#define NROWS (NPTS*KNBR)       // 163840
#define C1 128
#define C2 256
#define C3 512
#define CH 384
#define BN_EPS 1e-5f
#define STAT_BLOCKS 1024
#define ROWS_PER_STAT (NROWS/STAT_BLOCKS) // 160

typedef unsigned long long ull;

// f32x2 packed helpers (Blackwell sm_103a)
__device__ __forceinline__ ull fma2(ull a, ull b, ull c) {
    ull d; asm("fma.rn.f32x2 %0, %1, %2, %3;" : "=l"(d) : "l"(a), "l"(b), "l"(c)); return d;
}
__device__ __forceinline__ ull pack2(float lo, float hi) {
    ull d; asm("mov.b64 %0, {%1, %2};" : "=l"(d) : "f"(lo), "f"(hi)); return d;
}
__device__ __forceinline__ float2 unpack2(ull v) {
    float2 r; asm("mov.b64 {%0, %1}, %2;" : "=f"(r.x), "=f"(r.y) : "l"(v)); return r;
}

// Scratch (static device globals; no runtime allocation)
__device__ int   g_idx[NROWS];
__device__ float g_part1[STAT_BLOCKS*2*C1];
__device__ float g_ss1[2*C1];              // scale[128], shift[128]
__device__ float g_fpre[(size_t)NROWS*C3]; // 335 MB pre-BN3 activations [p][r][c]
__device__ float g_part3[STAT_BLOCKS*2*C3];
__device__ float g_ss3[2*C3];              // scale[512], shift[512]

// ---------------------------------------------------------------------------
// K1: KNN (unchanged from passing R1 — do not perturb distance math/ties)
// ---------------------------------------------------------------------------
__global__ void knn_kernel(const float* __restrict__ xyz) {
    __shared__ float sd[NN];
    __shared__ float rv[256];
    __shared__ int   ri[256];
    int p = blockIdx.x;
    int b = p >> 12, n = p & (NN-1);
    int t = threadIdx.x;
    const float* base = xyz + (size_t)b*NN*3;
    float cx = base[n*3+0], cy = base[n*3+1], cz = base[n*3+2];
    float pp = cx*cx + cy*cy + cz*cz;
    for (int m = t; m < NN; m += 256) {
        float qx = base[m*3+0], qy = base[m*3+1], qz = base[m*3+2];
        float qq = qx*qx + qy*qy + qz*qz;
        float pq = cx*qx + cy*qy + cz*qz;
        sd[m] = pp + qq - 2.f*pq;
    }
    __syncthreads();
    for (int round = 0; round < KNBR; ++round) {
        float bv = FLT_MAX; int bi = NN;
        for (int m = t; m < NN; m += 256) {
            float v = sd[m];
            if (v < bv) { bv = v; bi = m; }
        }
        rv[t] = bv; ri[t] = bi;
        __syncthreads();
        #pragma unroll
        for (int s = 128; s > 0; s >>= 1) {
            if (t < s) {
                float ov = rv[t+s]; int oi = ri[t+s];
                if (ov < rv[t] || (ov == rv[t] && oi < ri[t])) { rv[t] = ov; ri[t] = oi; }
            }
            __syncthreads();
        }
        if (t == 0) {
            g_idx[p*KNBR + round] = ri[0];
            sd[ri[0]] = FLT_MAX;
        }
        __syncthreads();
    }
}

// ---------------------------------------------------------------------------
// K2/K3: BN1 stats (deterministic 2-stage; unchanged)
// ---------------------------------------------------------------------------
__global__ void stats1_kernel(const float* __restrict__ xyz,
                              const float* __restrict__ W1,
                              const float* __restrict__ b1) {
    __shared__ float se[ROWS_PER_STAT*6];
    int blk = blockIdx.x, t = threadIdx.x;   // 128 threads
    int row0 = blk * ROWS_PER_STAT;
    for (int r = t; r < ROWS_PER_STAT; r += 128) {
        int gr = row0 + r;
        int p  = gr / KNBR;
        int b  = p >> 12, n = p & (NN-1);
        int id = g_idx[gr];
        const float* cb = xyz + ((size_t)b*NN + n)*3;
        const float* nb = xyz + ((size_t)b*NN + id)*3;
        se[r*6+0] = nb[0]-cb[0];
        se[r*6+1] = nb[1]-cb[1];
        se[r*6+2] = nb[2]-cb[2];
        se[r*6+3] = cb[0]; se[r*6+4] = cb[1]; se[r*6+5] = cb[2];
    }
    __syncthreads();
    float w0 = W1[0*C1+t], w1 = W1[1*C1+t], w2 = W1[2*C1+t],
          w3 = W1[3*C1+t], w4 = W1[4*C1+t], w5 = W1[5*C1+t], bb = b1[t];
    float s = 0.f, q = 0.f;
    for (int r = 0; r < ROWS_PER_STAT; ++r) {
        float h = bb + se[r*6+0]*w0 + se[r*6+1]*w1 + se[r*6+2]*w2
                     + se[r*6+3]*w3 + se[r*6+4]*w4 + se[r*6+5]*w5;
        s += h; q += h*h;
    }
    g_part1[blk*(2*C1) + t]      = s;
    g_part1[blk*(2*C1) + C1 + t] = q;
}

__global__ void fin1_kernel(const float* __restrict__ g1,
                            const float* __restrict__ be1) {
    int c = threadIdx.x;   // 128
    float s = 0.f, q = 0.f;
    for (int i = 0; i < STAT_BLOCKS; ++i) {
        s += g_part1[i*(2*C1)+c];
        q += g_part1[i*(2*C1)+C1+c];
    }
    float mu  = s / (float)NROWS;
    float var = q / (float)NROWS - mu*mu;
    float sc  = g1[c] * rsqrtf(var + BN_EPS);
    g_ss1[c]     = sc;
    g_ss1[C1+c]  = be1[c] - mu*sc;
}

// ---------------------------------------------------------------------------
// K4: mega kernel, f32x2 edition. One block (256 thr) per point.
// Transposed smem activations [col][20 rows] so LDS.128 yields two f32x2
// row-pair operands directly.
// ---------------------------------------------------------------------------
__global__ __launch_bounds__(256) void mega_kernel(
    const float* __restrict__ xyz,
    const float* __restrict__ W1, const float* __restrict__ b1,
    const float* __restrict__ W2, const float* __restrict__ b2,
    const float* __restrict__ W3, const float* __restrict__ b3) {
    __shared__ __align__(16) float sE[KNBR*6];
    __shared__ __align__(16) float sAT[C1*KNBR];   // 10KB, [c][r]
    __shared__ __align__(16) float sHT[C2*KNBR];   // 20KB, [c][r]
    __shared__ __align__(16) float sG[C2];
    __shared__ __align__(16) float sFA[C3];
    int p = blockIdx.x, t = threadIdx.x;
    int b = p >> 12, n = p & (NN-1);

    if (t < KNBR) {
        int id = g_idx[p*KNBR + t];
        const float* cb = xyz + ((size_t)b*NN + n)*3;
        const float* nb = xyz + ((size_t)b*NN + id)*3;
        sE[t*6+0] = nb[0]-cb[0]; sE[t*6+1] = nb[1]-cb[1]; sE[t*6+2] = nb[2]-cb[2];
        sE[t*6+3] = cb[0];       sE[t*6+4] = cb[1];       sE[t*6+5] = cb[2];
    }
    __syncthreads();

    // stage1: A = relu(bn1(edge@W1+b1)) -> sAT[c][r]
    for (int e = t; e < KNBR*C1; e += 256) {
        int c = e & (C1-1), r = e >> 7;
        float h = b1[c];
        #pragma unroll
        for (int d = 0; d < 6; ++d) h += sE[r*6+d]*W1[d*C1+c];
        sAT[c*KNBR + r] = fmaxf(h * g_ss1[c] + g_ss1[C1+c], 0.f);
    }
    __syncthreads();

    // stage2: h2 = A@W2 + b2 -> sHT[c][r]; gmax per col -> sG
    {
        int c = t;                       // one col per thread
        float bb = b2[c];
        ull bd = pack2(bb, bb);
        ull acc[10];
        #pragma unroll
        for (int i = 0; i < 10; ++i) acc[i] = bd;
        #pragma unroll 4
        for (int j = 0; j < C1; ++j) {
            float w = W2[j*C2 + c];
            ull wd = pack2(w, w);
            const ulonglong2* ap = (const ulonglong2*)&sAT[j*KNBR];
            #pragma unroll
            for (int g = 0; g < 5; ++g) {
                ulonglong2 aa = ap[g];
                acc[2*g]   = fma2(aa.x, wd, acc[2*g]);
                acc[2*g+1] = fma2(aa.y, wd, acc[2*g+1]);
            }
        }
        ull* hp = (ull*)&sHT[c*KNBR];
        float gm = -FLT_MAX;
        #pragma unroll
        for (int i = 0; i < 10; ++i) {
            hp[i] = acc[i];
            float2 v = unpack2(acc[i]);
            gm = fmaxf(gm, fmaxf(v.x, v.y));
        }
        sG[c] = gm;
    }
    __syncthreads();

    // fA = gmax @ W3[0:256] + b3 (per point, cols packed in pairs)
    {
        int c0 = 2*t;
        ull acc = pack2(b3[c0], b3[c0+1]);
        #pragma unroll 4
        for (int j = 0; j < C2; ++j) {
            float g = sG[j];
            ull gd = pack2(g, g);
            ull wv = *(const ull*)&W3[(size_t)j*C3 + c0];
            acc = fma2(gd, wv, acc);
        }
        *(float2*)&sFA[c0] = unpack2(acc);
    }
    __syncthreads();

    // fpre = h2 @ W3[256:512] + fA -> g_fpre[p][r][c]
    {
        int c0 = 2*t;
        ull a0[10], a1[10];
        #pragma unroll
        for (int i = 0; i < 10; ++i) { a0[i] = 0ull; a1[i] = 0ull; }
        #pragma unroll 2
        for (int j = 0; j < C2; ++j) {
            ull wv = *(const ull*)&W3[(size_t)(C2+j)*C3 + c0];
            float2 w = unpack2(wv);
            ull w0 = pack2(w.x, w.x), w1 = pack2(w.y, w.y);
            const ulonglong2* ap = (const ulonglong2*)&sHT[j*KNBR];
            #pragma unroll
            for (int g = 0; g < 5; ++g) {
                ulonglong2 aa = ap[g];
                a0[2*g]   = fma2(aa.x, w0, a0[2*g]);
                a0[2*g+1] = fma2(aa.y, w0, a0[2*g+1]);
                a1[2*g]   = fma2(aa.x, w1, a1[2*g]);
                a1[2*g+1] = fma2(aa.y, w1, a1[2*g+1]);
            }
        }
        float fa0 = sFA[c0], fa1 = sFA[c0+1];
        size_t base = (size_t)p*KNBR*C3 + c0;
        #pragma unroll
        for (int i = 0; i < 10; ++i) {
            float2 v0 = unpack2(a0[i]);   // col c0: rows 2i, 2i+1
            float2 v1 = unpack2(a1[i]);   // col c1: rows 2i, 2i+1
            float2 s0 = make_float2(v0.x + fa0, v1.x + fa1);
            float2 s1 = make_float2(v0.y + fa0, v1.y + fa1);
            *(float2*)&g_fpre[base + (size_t)(2*i)*C3]   = s0;
            *(float2*)&g_fpre[base + (size_t)(2*i+1)*C3] = s1;
        }
    }
}

// ---------------------------------------------------------------------------
// K5/K6: BN3 stats (deterministic 2-stage; unchanged)
// ---------------------------------------------------------------------------
__global__ void stats3_kernel() {
    int blk = blockIdx.x, t = threadIdx.x;   // 256 threads
    size_t row0 = (size_t)blk * ROWS_PER_STAT;
    float s0 = 0.f, q0 = 0.f, s1 = 0.f, q1 = 0.f;
    for (int r = 0; r < ROWS_PER_STAT; ++r) {
        size_t base = (row0 + r)*C3;
        float v0 = g_fpre[base + t];
        float v1 = g_fpre[base + C2 + t];
        s0 += v0; q0 += v0*v0;
        s1 += v1; q1 += v1*v1;
    }
    g_part3[blk*(2*C3) + t]           = s0;
    g_part3[blk*(2*C3) + C2 + t]      = s1;
    g_part3[blk*(2*C3) + C3 + t]      = q0;
    g_part3[blk*(2*C3) + C3 + C2 + t] = q1;
}

__global__ void fin3_kernel(const float* __restrict__ g3,
                            const float* __restrict__ be3) {
    int c = threadIdx.x;   // 512
    float s = 0.f, q = 0.f;
    for (int i = 0; i < STAT_BLOCKS; ++i) {
        s += g_part3[i*(2*C3)+c];
        q += g_part3[i*(2*C3)+C3+c];
    }
    float mu  = s / (float)NROWS;
    float var = q / (float)NROWS - mu*mu;
    float sc  = g3[c] * rsqrtf(var + BN_EPS);
    g_ss3[c]    = sc;
    g_ss3[C3+c] = be3[c] - mu*sc;
}

// ---------------------------------------------------------------------------
// K7: final, f32x2 edition. One block (192 thr) per point; 2 cols/thread.
//   sAT[c][r] = relu(bn3(fpre)), then out[c] = max_r (A@W4)[r][c] + b4[c]
// ---------------------------------------------------------------------------
__global__ __launch_bounds__(192) void final_kernel(
    const float* __restrict__ W4, const float* __restrict__ b4,
    float* __restrict__ out) {
    __shared__ __align__(16) float sAT[C3*KNBR];   // 40KB, [c][r]
    int p = blockIdx.x, t = threadIdx.x;
    size_t base = (size_t)p*KNBR*C3;
    for (int e = t; e < KNBR*C3; e += 192) {
        int c = e & (C3-1), r = e >> 9;
        float v = g_fpre[base + e];
        sAT[c*KNBR + r] = fmaxf(v*g_ss3[c] + g_ss3[C3+c], 0.f);
    }
    __syncthreads();
    int c0 = 2*t;
    ull a0[10], a1[10];
    #pragma unroll
    for (int i = 0; i < 10; ++i) { a0[i] = 0ull; a1[i] = 0ull; }
    #pragma unroll 2
    for (int j = 0; j < C3; ++j) {
        ull wv = *(const ull*)&W4[(size_t)j*CH + c0];
        float2 w = unpack2(wv);
        ull w0 = pack2(w.x, w.x), w1 = pack2(w.y, w.y);
        const ulonglong2* ap = (const ulonglong2*)&sAT[j*KNBR];
        #pragma unroll
        for (int g = 0; g < 5; ++g) {
            ulonglong2 aa = ap[g];
            a0[2*g]   = fma2(aa.x, w0, a0[2*g]);
            a0[2*g+1] = fma2(aa.y, w0, a0[2*g+1]);
            a1[2*g]   = fma2(aa.x, w1, a1[2*g]);
            a1[2*g+1] = fma2(aa.y, w1, a1[2*g+1]);
        }
    }
    float m0 = -FLT_MAX, m1 = -FLT_MAX;
    #pragma unroll
    for (int i = 0; i < 10; ++i) {
        float2 v0 = unpack2(a0[i]);
        float2 v1 = unpack2(a1[i]);
        m0 = fmaxf(m0, fmaxf(v0.x, v0.y));
        m1 = fmaxf(m1, fmaxf(v1.x, v1.y));
    }
    float2 res = make_float2(m0 + b4[c0], m1 + b4[c0+1]);
    *(float2*)&out[(size_t)BB*NN*3 + (size_t)p*CH + c0] = res;
}

// Output tuple element 0: xyz passthrough
__global__ void copy_xyz_kernel(const float* __restrict__ xyz,
                                float* __restrict__ out) {
    int i = blockIdx.x*256 + threadIdx.x;
    if (i < BB*NN*3) out[i] = xyz[i];
}

extern "C" void kernel_launch(void* const* d_in, const int* in_sizes, int n_in,
                              void* d_out, int out_size) {
    (void)in_sizes; (void)n_in; (void)out_size;
    const float* xyz = (const float*)d_in[0];
    const float* W1  = (const float*)d_in[1];
    const float* b1  = (const float*)d_in[2];
    const float* g1  = (const float*)d_in[3];
    const float* be1 = (const float*)d_in[4];
    const float* W2  = (const float*)d_in[5];
    const float* b2  = (const float*)d_in[6];
    const float* W3  = (const float*)d_in[7];
    const float* b3  = (const float*)d_in[8];
    const float* g3  = (const float*)d_in[9];
    const float* be3 = (const float*)d_in[10];
    const float* W4  = (const float*)d_in[11];
    const float* b4  = (const float*)d_in[12];
    float* out = (float*)d_out;

    knn_kernel<<<NPTS, 256>>>(xyz);
    stats1_kernel<<<STAT_BLOCKS, 128>>>(xyz, W1, b1);
    fin1_kernel<<<1, C1>>>(g1, be1);
    mega_kernel<<<NPTS, 256>>>(xyz, W1, b1, W2, b2, W3, b3);
    stats3_kernel<<<STAT_BLOCKS, 256>>>();
    fin3_kernel<<<1, C3>>>(g3, be3);
    final_kernel<<<NPTS, 192>>>(W4, b4, out);
    copy_xyz_kernel<<<(BB*NN*3 + 255)/256, 256>>>(xyz, out);
}

// round 5
// speedup vs baseline: 3.3454x; 1.3943x over previous
#include <cuda_runtime.h>
#include <math.h>
#include <float.h>
#include <stdint.h>

// Problem constants
#define BB 2
#define NN 4096
#define KNBR 20
#define NPTS (BB*NN)            // 8192
#define NROWS (NPTS*KNBR)       // 163840
#define C1 128
#define C2 256
#define C3 512
#define CH 384
#define BN_EPS 1e-5f
#define STAT_BLOCKS 1024
#define ROWS_PER_STAT (NROWS/STAT_BLOCKS) // 160

typedef unsigned long long ull;

// ---------------- f32x2 packed helpers ----------------
__device__ __forceinline__ ull fma2(ull a, ull b, ull c) {
    ull d; asm("fma.rn.f32x2 %0, %1, %2, %3;" : "=l"(d) : "l"(a), "l"(b), "l"(c)); return d;
}
__device__ __forceinline__ ull pack2(float lo, float hi) {
    ull d; asm("mov.b64 %0, {%1, %2};" : "=l"(d) : "f"(lo), "f"(hi)); return d;
}
__device__ __forceinline__ float2 unpack2(ull v) {
    float2 r; asm("mov.b64 {%0, %1}, %2;" : "=f"(r.x), "=f"(r.y) : "l"(v)); return r;
}
__device__ __forceinline__ uint32_t cvt_tf32(float f) {
    uint32_t r; asm("cvt.rna.tf32.f32 %0, %1;" : "=r"(r) : "f"(f)); return r;
}

// ---------------- scratch (static device globals) ----------------
__device__ int   g_idx[NROWS];
__device__ float g_part1[STAT_BLOCKS*2*C1];
__device__ float g_ss1[2*C1];
__device__ float g_fpre[(size_t)NROWS*C3];   // 335 MB
__device__ float g_part3[STAT_BLOCKS*2*C3];
__device__ float g_ss3[2*C3];
__device__ float g_F[(size_t)NROWS*CH];      // 240 MB GEMM output

// ---------------------------------------------------------------------------
// K1: KNN (unchanged — passing)
// ---------------------------------------------------------------------------
__global__ void knn_kernel(const float* __restrict__ xyz) {
    __shared__ float sd[NN];
    __shared__ float rv[256];
    __shared__ int   ri[256];
    int p = blockIdx.x;
    int b = p >> 12, n = p & (NN-1);
    int t = threadIdx.x;
    const float* base = xyz + (size_t)b*NN*3;
    float cx = base[n*3+0], cy = base[n*3+1], cz = base[n*3+2];
    float pp = cx*cx + cy*cy + cz*cz;
    for (int m = t; m < NN; m += 256) {
        float qx = base[m*3+0], qy = base[m*3+1], qz = base[m*3+2];
        float qq = qx*qx + qy*qy + qz*qz;
        float pq = cx*qx + cy*qy + cz*qz;
        sd[m] = pp + qq - 2.f*pq;
    }
    __syncthreads();
    for (int round = 0; round < KNBR; ++round) {
        float bv = FLT_MAX; int bi = NN;
        for (int m = t; m < NN; m += 256) {
            float v = sd[m];
            if (v < bv) { bv = v; bi = m; }
        }
        rv[t] = bv; ri[t] = bi;
        __syncthreads();
        #pragma unroll
        for (int s = 128; s > 0; s >>= 1) {
            if (t < s) {
                float ov = rv[t+s]; int oi = ri[t+s];
                if (ov < rv[t] || (ov == rv[t] && oi < ri[t])) { rv[t] = ov; ri[t] = oi; }
            }
            __syncthreads();
        }
        if (t == 0) {
            g_idx[p*KNBR + round] = ri[0];
            sd[ri[0]] = FLT_MAX;
        }
        __syncthreads();
    }
}

// ---------------------------------------------------------------------------
// BN1 stats (unchanged)
// ---------------------------------------------------------------------------
__global__ void stats1_kernel(const float* __restrict__ xyz,
                              const float* __restrict__ W1,
                              const float* __restrict__ b1) {
    __shared__ float se[ROWS_PER_STAT*6];
    int blk = blockIdx.x, t = threadIdx.x;
    int row0 = blk * ROWS_PER_STAT;
    for (int r = t; r < ROWS_PER_STAT; r += 128) {
        int gr = row0 + r;
        int p  = gr / KNBR;
        int b  = p >> 12, n = p & (NN-1);
        int id = g_idx[gr];
        const float* cb = xyz + ((size_t)b*NN + n)*3;
        const float* nb = xyz + ((size_t)b*NN + id)*3;
        se[r*6+0] = nb[0]-cb[0];
        se[r*6+1] = nb[1]-cb[1];
        se[r*6+2] = nb[2]-cb[2];
        se[r*6+3] = cb[0]; se[r*6+4] = cb[1]; se[r*6+5] = cb[2];
    }
    __syncthreads();
    float w0 = W1[0*C1+t], w1 = W1[1*C1+t], w2 = W1[2*C1+t],
          w3 = W1[3*C1+t], w4 = W1[4*C1+t], w5 = W1[5*C1+t], bb = b1[t];
    float s = 0.f, q = 0.f;
    for (int r = 0; r < ROWS_PER_STAT; ++r) {
        float h = bb + se[r*6+0]*w0 + se[r*6+1]*w1 + se[r*6+2]*w2
                     + se[r*6+3]*w3 + se[r*6+4]*w4 + se[r*6+5]*w5;
        s += h; q += h*h;
    }
    g_part1[blk*(2*C1) + t]      = s;
    g_part1[blk*(2*C1) + C1 + t] = q;
}

__global__ void fin1_kernel(const float* __restrict__ g1,
                            const float* __restrict__ be1) {
    int c = threadIdx.x;
    float s = 0.f, q = 0.f;
    for (int i = 0; i < STAT_BLOCKS; ++i) {
        s += g_part1[i*(2*C1)+c];
        q += g_part1[i*(2*C1)+C1+c];
    }
    float mu  = s / (float)NROWS;
    float var = q / (float)NROWS - mu*mu;
    float sc  = g1[c] * rsqrtf(var + BN_EPS);
    g_ss1[c]     = sc;
    g_ss1[C1+c]  = be1[c] - mu*sc;
}

// ---------------------------------------------------------------------------
// mega kernel: 128 threads/block, col-blocked f32x2
// ---------------------------------------------------------------------------
__global__ __launch_bounds__(128) void mega_kernel(
    const float* __restrict__ xyz,
    const float* __restrict__ W1, const float* __restrict__ b1,
    const float* __restrict__ W2, const float* __restrict__ b2,
    const float* __restrict__ W3, const float* __restrict__ b3) {
    __shared__ __align__(16) float sE[KNBR*6];
    __shared__ __align__(16) float sAT[C1*KNBR];   // [c][r]
    __shared__ __align__(16) float sHT[C2*KNBR];   // [c][r]
    __shared__ __align__(16) float sG[C2];
    __shared__ __align__(16) float sFA[C3];
    int p = blockIdx.x, t = threadIdx.x;
    int b = p >> 12, n = p & (NN-1);

    if (t < KNBR) {
        int id = g_idx[p*KNBR + t];
        const float* cb = xyz + ((size_t)b*NN + n)*3;
        const float* nb = xyz + ((size_t)b*NN + id)*3;
        sE[t*6+0] = nb[0]-cb[0]; sE[t*6+1] = nb[1]-cb[1]; sE[t*6+2] = nb[2]-cb[2];
        sE[t*6+3] = cb[0];       sE[t*6+4] = cb[1];       sE[t*6+5] = cb[2];
    }
    __syncthreads();

    // stage1: A = relu(bn1(edge@W1+b1)) -> sAT[c][r]
    for (int e = t; e < KNBR*C1; e += 128) {
        int c = e & (C1-1), r = e >> 7;
        float h = b1[c];
        #pragma unroll
        for (int d = 0; d < 6; ++d) h += sE[r*6+d]*W1[d*C1+c];
        sAT[c*KNBR + r] = fmaxf(h * g_ss1[c] + g_ss1[C1+c], 0.f);
    }
    __syncthreads();

    // stage2: h2 = A@W2 + b2 (2 cols/thread) -> sHT; gmax -> sG
    {
        int c0 = 2*t;
        float2 bb = *(const float2*)&b2[c0];
        ull b0 = pack2(bb.x, bb.x), b1d = pack2(bb.y, bb.y);
        ull a0[10], a1[10];
        #pragma unroll
        for (int i = 0; i < 10; ++i) { a0[i] = b0; a1[i] = b1d; }
        #pragma unroll 2
        for (int j = 0; j < C1; ++j) {
            ull wv = *(const ull*)&W2[j*C2 + c0];
            float2 w = unpack2(wv);
            ull w0 = pack2(w.x, w.x), w1 = pack2(w.y, w.y);
            const ulonglong2* ap = (const ulonglong2*)&sAT[j*KNBR];
            #pragma unroll
            for (int g = 0; g < 5; ++g) {
                ulonglong2 aa = ap[g];
                a0[2*g]   = fma2(aa.x, w0, a0[2*g]);
                a0[2*g+1] = fma2(aa.y, w0, a0[2*g+1]);
                a1[2*g]   = fma2(aa.x, w1, a1[2*g]);
                a1[2*g+1] = fma2(aa.y, w1, a1[2*g+1]);
            }
        }
        ull* h0 = (ull*)&sHT[c0*KNBR];
        ull* h1 = (ull*)&sHT[(c0+1)*KNBR];
        float g0 = -FLT_MAX, g1v = -FLT_MAX;
        #pragma unroll
        for (int i = 0; i < 10; ++i) {
            h0[i] = a0[i]; h1[i] = a1[i];
            float2 v0 = unpack2(a0[i]), v1 = unpack2(a1[i]);
            g0 = fmaxf(g0, fmaxf(v0.x, v0.y));
            g1v = fmaxf(g1v, fmaxf(v1.x, v1.y));
        }
        sG[c0] = g0; sG[c0+1] = g1v;
    }
    __syncthreads();

    // fA = gmax @ W3[0:256] + b3 (4 cols/thread)
    {
        int c0 = 4*t;
        float4 bb = *(const float4*)&b3[c0];
        ull aA = pack2(bb.x, bb.y), aB = pack2(bb.z, bb.w);
        #pragma unroll 4
        for (int j = 0; j < C2; ++j) {
            float g = sG[j];
            ull gd = pack2(g, g);
            ulonglong2 wv = *(const ulonglong2*)&W3[(size_t)j*C3 + c0];
            aA = fma2(gd, wv.x, aA);
            aB = fma2(gd, wv.y, aB);
        }
        float2 vA = unpack2(aA), vB = unpack2(aB);
        *(float4*)&sFA[c0] = make_float4(vA.x, vA.y, vB.x, vB.y);
    }
    __syncthreads();

    // fpre = h2 @ W3[256:512] + fA (4 cols/thread) -> g_fpre
    {
        int c0 = 4*t;
        ull a0[10], a1[10], a2[10], a3[10];
        #pragma unroll
        for (int i = 0; i < 10; ++i) { a0[i]=0ull; a1[i]=0ull; a2[i]=0ull; a3[i]=0ull; }
        for (int j = 0; j < C2; ++j) {
            ulonglong2 wv = *(const ulonglong2*)&W3[(size_t)(C2+j)*C3 + c0];
            float2 wA = unpack2(wv.x), wB = unpack2(wv.y);
            ull w0 = pack2(wA.x, wA.x), w1 = pack2(wA.y, wA.y);
            ull w2 = pack2(wB.x, wB.x), w3 = pack2(wB.y, wB.y);
            const ulonglong2* ap = (const ulonglong2*)&sHT[j*KNBR];
            #pragma unroll
            for (int g = 0; g < 5; ++g) {
                ulonglong2 aa = ap[g];
                a0[2*g]   = fma2(aa.x, w0, a0[2*g]);
                a0[2*g+1] = fma2(aa.y, w0, a0[2*g+1]);
                a1[2*g]   = fma2(aa.x, w1, a1[2*g]);
                a1[2*g+1] = fma2(aa.y, w1, a1[2*g+1]);
                a2[2*g]   = fma2(aa.x, w2, a2[2*g]);
                a2[2*g+1] = fma2(aa.y, w2, a2[2*g+1]);
                a3[2*g]   = fma2(aa.x, w3, a3[2*g]);
                a3[2*g+1] = fma2(aa.y, w3, a3[2*g+1]);
            }
        }
        float4 fa = *(const float4*)&sFA[c0];
        size_t base = (size_t)p*KNBR*C3 + c0;
        #pragma unroll
        for (int i = 0; i < 10; ++i) {
            float2 v0 = unpack2(a0[i]);
            float2 v1 = unpack2(a1[i]);
            float2 v2 = unpack2(a2[i]);
            float2 v3 = unpack2(a3[i]);
            *(float4*)&g_fpre[base + (size_t)(2*i)*C3] =
                make_float4(v0.x+fa.x, v1.x+fa.y, v2.x+fa.z, v3.x+fa.w);
            *(float4*)&g_fpre[base + (size_t)(2*i+1)*C3] =
                make_float4(v0.y+fa.x, v1.y+fa.y, v2.y+fa.z, v3.y+fa.w);
        }
    }
}

// ---------------------------------------------------------------------------
// BN3 stats (unchanged)
// ---------------------------------------------------------------------------
__global__ void stats3_kernel() {
    int blk = blockIdx.x, t = threadIdx.x;
    size_t row0 = (size_t)blk * ROWS_PER_STAT;
    float s0 = 0.f, q0 = 0.f, s1 = 0.f, q1 = 0.f;
    for (int r = 0; r < ROWS_PER_STAT; ++r) {
        size_t base = (row0 + r)*C3;
        float v0 = g_fpre[base + t];
        float v1 = g_fpre[base + C2 + t];
        s0 += v0; q0 += v0*v0;
        s1 += v1; q1 += v1*v1;
    }
    g_part3[blk*(2*C3) + t]           = s0;
    g_part3[blk*(2*C3) + C2 + t]      = s1;
    g_part3[blk*(2*C3) + C3 + t]      = q0;
    g_part3[blk*(2*C3) + C3 + C2 + t] = q1;
}

__global__ void fin3_kernel(const float* __restrict__ g3,
                            const float* __restrict__ be3) {
    int c = threadIdx.x;
    float s = 0.f, q = 0.f;
    for (int i = 0; i < STAT_BLOCKS; ++i) {
        s += g_part3[i*(2*C3)+c];
        q += g_part3[i*(2*C3)+C3+c];
    }
    float mu  = s / (float)NROWS;
    float var = q / (float)NROWS - mu*mu;
    float sc  = g3[c] * rsqrtf(var + BN_EPS);
    g_ss3[c]    = sc;
    g_ss3[C3+c] = be3[c] - mu*sc;
}

// ---------------------------------------------------------------------------
// mma.sync tf32 GEMM: F[163840,384] = relu(bn3(g_fpre))[163840,512] @ W4[512,384]
// CTA tile 128x64, 4 warps (warp tile 32x64), K-chunk 32.
// Smem pads: A stride 36 (conflict-free a-frag LDS), B stride 72.
// ---------------------------------------------------------------------------
#define GM_MT 128
#define GM_NT 64
#define GM_KC 32
#define SA_STR 36
#define SB_STR 72

__global__ __launch_bounds__(128) void gemm_final_kernel(const float* __restrict__ W4) {
    __shared__ __align__(16) float sA[GM_MT*SA_STR];   // 18.4 KB
    __shared__ __align__(16) float sB[GM_KC*SB_STR];   // 9.2 KB

    int t = threadIdx.x;
    int w = t >> 5, lane = t & 31;
    int g = lane >> 2, tig = lane & 3;
    size_t row0 = (size_t)blockIdx.x * GM_MT;
    int n0 = blockIdx.y * GM_NT;

    float acc[2][8][4];
    #pragma unroll
    for (int m = 0; m < 2; ++m)
        #pragma unroll
        for (int n = 0; n < 8; ++n)
            #pragma unroll
            for (int i = 0; i < 4; ++i) acc[m][n][i] = 0.f;

    // A-load indexing: 8 passes x 16 rows; 8 threads per row, float4 each
    int a_row = t >> 3, a_cb = (t & 7) * 4;
    // B-load indexing: 4 passes x 8 k-rows; 16 threads per k-row, float4 each
    int b_k = t >> 4, b_nb = (t & 15) * 4;

    for (int kk = 0; kk < C3; kk += GM_KC) {
        // stage A chunk with fused bn3+relu+tf32
        {
            float4 sc = *(const float4*)&g_ss3[kk + a_cb];
            float4 sh = *(const float4*)&g_ss3[C3 + kk + a_cb];
            #pragma unroll
            for (int pq = 0; pq < 8; ++pq) {
                int r = pq*16 + a_row;
                float4 v = *(const float4*)&g_fpre[(row0 + r)*C3 + kk + a_cb];
                uint4 o;
                o.x = cvt_tf32(fmaxf(v.x*sc.x + sh.x, 0.f));
                o.y = cvt_tf32(fmaxf(v.y*sc.y + sh.y, 0.f));
                o.z = cvt_tf32(fmaxf(v.z*sc.z + sh.z, 0.f));
                o.w = cvt_tf32(fmaxf(v.w*sc.w + sh.w, 0.f));
                *(uint4*)&sA[r*SA_STR + a_cb] = o;
            }
        }
        // stage B chunk (tf32-convert W4)
        {
            #pragma unroll
            for (int pq = 0; pq < 4; ++pq) {
                int k = pq*8 + b_k;
                float4 v = *(const float4*)&W4[(size_t)(kk + k)*CH + n0 + b_nb];
                uint4 o;
                o.x = cvt_tf32(v.x); o.y = cvt_tf32(v.y);
                o.z = cvt_tf32(v.z); o.w = cvt_tf32(v.w);
                *(uint4*)&sB[k*SB_STR + b_nb] = o;
            }
        }
        __syncthreads();

        #pragma unroll
        for (int ks = 0; ks < 4; ++ks) {
            int kb = ks*8;
            uint32_t af[2][4];
            #pragma unroll
            for (int m = 0; m < 2; ++m) {
                int mr = w*32 + m*16;
                af[m][0] = __float_as_uint(sA[(mr+g)*SA_STR   + kb + tig]);
                af[m][1] = __float_as_uint(sA[(mr+g+8)*SA_STR + kb + tig]);
                af[m][2] = __float_as_uint(sA[(mr+g)*SA_STR   + kb + tig + 4]);
                af[m][3] = __float_as_uint(sA[(mr+g+8)*SA_STR + kb + tig + 4]);
            }
            uint32_t bf[8][2];
            #pragma unroll
            for (int n = 0; n < 8; ++n) {
                bf[n][0] = __float_as_uint(sB[(kb+tig)*SB_STR   + n*8 + g]);
                bf[n][1] = __float_as_uint(sB[(kb+tig+4)*SB_STR + n*8 + g]);
            }
            #pragma unroll
            for (int m = 0; m < 2; ++m)
                #pragma unroll
                for (int n = 0; n < 8; ++n) {
                    asm volatile(
                        "mma.sync.aligned.m16n8k8.row.col.f32.tf32.tf32.f32 "
                        "{%0,%1,%2,%3}, {%4,%5,%6,%7}, {%8,%9}, {%0,%1,%2,%3};"
                        : "+f"(acc[m][n][0]), "+f"(acc[m][n][1]),
                          "+f"(acc[m][n][2]), "+f"(acc[m][n][3])
                        : "r"(af[m][0]), "r"(af[m][1]), "r"(af[m][2]), "r"(af[m][3]),
                          "r"(bf[n][0]), "r"(bf[n][1]));
                }
        }
        __syncthreads();
    }

    // epilogue: write accumulators to g_F
    #pragma unroll
    for (int m = 0; m < 2; ++m) {
        size_t r0 = row0 + w*32 + m*16 + g;
        #pragma unroll
        for (int n = 0; n < 8; ++n) {
            int col = n0 + n*8 + 2*tig;
            *(float2*)&g_F[r0*CH + col]     = make_float2(acc[m][n][0], acc[m][n][1]);
            *(float2*)&g_F[(r0+8)*CH + col] = make_float2(acc[m][n][2], acc[m][n][3]);
        }
    }
}

// ---------------------------------------------------------------------------
// maxpool: out[p][c] = max_r F[p*20+r][c] + b4[c]
// ---------------------------------------------------------------------------
__global__ void maxpool_kernel(const float* __restrict__ b4,
                               float* __restrict__ out) {
    int p = blockIdx.x, c = threadIdx.x;   // 384 threads
    const float* src = g_F + (size_t)p*KNBR*CH + c;
    float m = -FLT_MAX;
    #pragma unroll
    for (int r = 0; r < KNBR; ++r) m = fmaxf(m, src[(size_t)r*CH]);
    out[(size_t)BB*NN*3 + (size_t)p*CH + c] = m + b4[c];
}

// Output tuple element 0: xyz passthrough
__global__ void copy_xyz_kernel(const float* __restrict__ xyz,
                                float* __restrict__ out) {
    int i = blockIdx.x*256 + threadIdx.x;
    if (i < BB*NN*3) out[i] = xyz[i];
}

extern "C" void kernel_launch(void* const* d_in, const int* in_sizes, int n_in,
                              void* d_out, int out_size) {
    (void)in_sizes; (void)n_in; (void)out_size;
    const float* xyz = (const float*)d_in[0];
    const float* W1  = (const float*)d_in[1];
    const float* b1  = (const float*)d_in[2];
    const float* g1  = (const float*)d_in[3];
    const float* be1 = (const float*)d_in[4];
    const float* W2  = (const float*)d_in[5];
    const float* b2  = (const float*)d_in[6];
    const float* W3  = (const float*)d_in[7];
    const float* b3  = (const float*)d_in[8];
    const float* g3  = (const float*)d_in[9];
    const float* be3 = (const float*)d_in[10];
    const float* W4  = (const float*)d_in[11];
    const float* b4  = (const float*)d_in[12];
    float* out = (float*)d_out;

    knn_kernel<<<NPTS, 256>>>(xyz);
    stats1_kernel<<<STAT_BLOCKS, 128>>>(xyz, W1, b1);
    fin1_kernel<<<1, C1>>>(g1, be1);
    mega_kernel<<<NPTS, 128>>>(xyz, W1, b1, W2, b2, W3, b3);
    stats3_kernel<<<STAT_BLOCKS, 256>>>();
    fin3_kernel<<<1, C3>>>(g3, be3);
    {
        dim3 grid(NROWS/GM_MT, CH/GM_NT);   // 1280 x 6
        gemm_final_kernel<<<grid, 128>>>(W4);
    }
    maxpool_kernel<<<NPTS, CH>>>(b4, out);
    copy_xyz_kernel<<<(BB*NN*3 + 255)/256, 256>>>(xyz, out);
}

// round 6
// speedup vs baseline: 4.6239x; 1.3822x over previous
#include <cuda_runtime.h>
#include <math.h>
#include <float.h>
#include <stdint.h>

// Problem constants
#define BB 2
#define NN 4096
#define KNBR 20
#define NPTS (BB*NN)            // 8192
#define NROWS (NPTS*KNBR)       // 163840
#define C1 128
#define C2 256
#define C3 512
#define CH 384
#define BN_EPS 1e-5f
#define STAT_BLOCKS 1024
#define ROWS_PER_STAT (NROWS/STAT_BLOCKS) // 160

__device__ __forceinline__ uint32_t cvt_tf32(float f) {
    uint32_t r; asm("cvt.rna.tf32.f32 %0, %1;" : "=r"(r) : "f"(f)); return r;
}

// ---------------- scratch (static device globals) ----------------
__device__ int   g_idx[NROWS];
__device__ float g_part1[STAT_BLOCKS*2*C1];
__device__ float g_ss1[2*C1];
__device__ float g_A[(size_t)NROWS*C1];      // 84 MB  (tf32-rounded)
__device__ float g_H2[(size_t)NROWS*C2];     // 168 MB
__device__ float g_gmax[(size_t)NPTS*C2];    // 8 MB
__device__ float g_fA[(size_t)NPTS*C3];      // 16 MB
__device__ float g_fpre[(size_t)NROWS*C3];   // 335 MB
__device__ float g_part3[STAT_BLOCKS*2*C3];
__device__ float g_ss3[2*C3];
__device__ float g_F[(size_t)NROWS*CH];      // 240 MB

// ---------------------------------------------------------------------------
// K1: KNN (unchanged — passing)
// ---------------------------------------------------------------------------
__global__ void knn_kernel(const float* __restrict__ xyz) {
    __shared__ float sd[NN];
    __shared__ float rv[256];
    __shared__ int   ri[256];
    int p = blockIdx.x;
    int b = p >> 12, n = p & (NN-1);
    int t = threadIdx.x;
    const float* base = xyz + (size_t)b*NN*3;
    float cx = base[n*3+0], cy = base[n*3+1], cz = base[n*3+2];
    float pp = cx*cx + cy*cy + cz*cz;
    for (int m = t; m < NN; m += 256) {
        float qx = base[m*3+0], qy = base[m*3+1], qz = base[m*3+2];
        float qq = qx*qx + qy*qy + qz*qz;
        float pq = cx*qx + cy*qy + cz*qz;
        sd[m] = pp + qq - 2.f*pq;
    }
    __syncthreads();
    for (int round = 0; round < KNBR; ++round) {
        float bv = FLT_MAX; int bi = NN;
        for (int m = t; m < NN; m += 256) {
            float v = sd[m];
            if (v < bv) { bv = v; bi = m; }
        }
        rv[t] = bv; ri[t] = bi;
        __syncthreads();
        #pragma unroll
        for (int s = 128; s > 0; s >>= 1) {
            if (t < s) {
                float ov = rv[t+s]; int oi = ri[t+s];
                if (ov < rv[t] || (ov == rv[t] && oi < ri[t])) { rv[t] = ov; ri[t] = oi; }
            }
            __syncthreads();
        }
        if (t == 0) {
            g_idx[p*KNBR + round] = ri[0];
            sd[ri[0]] = FLT_MAX;
        }
        __syncthreads();
    }
}

// ---------------------------------------------------------------------------
// BN1 stats (unchanged)
// ---------------------------------------------------------------------------
__global__ void stats1_kernel(const float* __restrict__ xyz,
                              const float* __restrict__ W1,
                              const float* __restrict__ b1) {
    __shared__ float se[ROWS_PER_STAT*6];
    int blk = blockIdx.x, t = threadIdx.x;
    int row0 = blk * ROWS_PER_STAT;
    for (int r = t; r < ROWS_PER_STAT; r += 128) {
        int gr = row0 + r;
        int p  = gr / KNBR;
        int b  = p >> 12, n = p & (NN-1);
        int id = g_idx[gr];
        const float* cb = xyz + ((size_t)b*NN + n)*3;
        const float* nb = xyz + ((size_t)b*NN + id)*3;
        se[r*6+0] = nb[0]-cb[0];
        se[r*6+1] = nb[1]-cb[1];
        se[r*6+2] = nb[2]-cb[2];
        se[r*6+3] = cb[0]; se[r*6+4] = cb[1]; se[r*6+5] = cb[2];
    }
    __syncthreads();
    float w0 = W1[0*C1+t], w1 = W1[1*C1+t], w2 = W1[2*C1+t],
          w3 = W1[3*C1+t], w4 = W1[4*C1+t], w5 = W1[5*C1+t], bb = b1[t];
    float s = 0.f, q = 0.f;
    for (int r = 0; r < ROWS_PER_STAT; ++r) {
        float h = bb + se[r*6+0]*w0 + se[r*6+1]*w1 + se[r*6+2]*w2
                     + se[r*6+3]*w3 + se[r*6+4]*w4 + se[r*6+5]*w5;
        s += h; q += h*h;
    }
    g_part1[blk*(2*C1) + t]      = s;
    g_part1[blk*(2*C1) + C1 + t] = q;
}

__global__ void fin1_kernel(const float* __restrict__ g1,
                            const float* __restrict__ be1) {
    int c = threadIdx.x;
    float s = 0.f, q = 0.f;
    for (int i = 0; i < STAT_BLOCKS; ++i) {
        s += g_part1[i*(2*C1)+c];
        q += g_part1[i*(2*C1)+C1+c];
    }
    float mu  = s / (float)NROWS;
    float var = q / (float)NROWS - mu*mu;
    float sc  = g1[c] * rsqrtf(var + BN_EPS);
    g_ss1[c]     = sc;
    g_ss1[C1+c]  = be1[c] - mu*sc;
}

// ---------------------------------------------------------------------------
// edge kernel: A[row][c] = tf32(relu(bn1(edge@W1+b1))). One row per block.
// ---------------------------------------------------------------------------
__global__ __launch_bounds__(128) void edge_kernel(
    const float* __restrict__ xyz,
    const float* __restrict__ W1, const float* __restrict__ b1) {
    int row = blockIdx.x, t = threadIdx.x;
    int p = row / KNBR;
    int b = p >> 12, n = p & (NN-1);
    int id = g_idx[row];
    const float* cb = xyz + ((size_t)b*NN + n)*3;
    const float* nb = xyz + ((size_t)b*NN + id)*3;
    float e0 = nb[0]-cb[0], e1 = nb[1]-cb[1], e2 = nb[2]-cb[2];
    float e3 = cb[0], e4 = cb[1], e5 = cb[2];
    float h = b1[t] + e0*W1[0*C1+t] + e1*W1[1*C1+t] + e2*W1[2*C1+t]
                    + e3*W1[3*C1+t] + e4*W1[4*C1+t] + e5*W1[5*C1+t];
    h = fmaxf(h * g_ss1[t] + g_ss1[C1+t], 0.f);
    g_A[(size_t)row*C1 + t] = __uint_as_float(cvt_tf32(h));
}

// ===========================================================================
// Shared mma.sync tile config: CTA 128x64, 4 warps, K-chunk 32
// ===========================================================================
#define GM_MT 128
#define GM_NT 64
#define GM_KC 32
#define SA_STR 36
#define SB_STR 72

#define MMA_TF32(acc, af, bf) \
    asm volatile( \
        "mma.sync.aligned.m16n8k8.row.col.f32.tf32.tf32.f32 " \
        "{%0,%1,%2,%3}, {%4,%5,%6,%7}, {%8,%9}, {%0,%1,%2,%3};" \
        : "+f"((acc)[0]), "+f"((acc)[1]), "+f"((acc)[2]), "+f"((acc)[3]) \
        : "r"((af)[0]), "r"((af)[1]), "r"((af)[2]), "r"((af)[3]), \
          "r"((bf)[0]), "r"((bf)[1]))

// ---------------------------------------------------------------------------
// gemm2: H2[NROWS,256] = A[NROWS,128] @ W2[128,256] + b2
// ---------------------------------------------------------------------------
__global__ __launch_bounds__(128) void gemm2_kernel(
    const float* __restrict__ W2, const float* __restrict__ b2) {
    __shared__ __align__(16) float sA[GM_MT*SA_STR];
    __shared__ __align__(16) float sB[GM_KC*SB_STR];
    int t = threadIdx.x;
    int w = t >> 5, lane = t & 31;
    int g = lane >> 2, tig = lane & 3;
    size_t row0 = (size_t)blockIdx.x * GM_MT;
    int n0 = blockIdx.y * GM_NT;

    float acc[2][8][4] = {};
    int a_row = t >> 3, a_cb = (t & 7) * 4;
    int b_k = t >> 4, b_nb = (t & 15) * 4;

    for (int kk = 0; kk < C1; kk += GM_KC) {
        #pragma unroll
        for (int pq = 0; pq < 8; ++pq) {
            int r = pq*16 + a_row;
            float4 v = *(const float4*)&g_A[(row0 + r)*C1 + kk + a_cb];
            *(float4*)&sA[r*SA_STR + a_cb] = v;   // already tf32-rounded
        }
        #pragma unroll
        for (int pq = 0; pq < 4; ++pq) {
            int k = pq*8 + b_k;
            float4 v = *(const float4*)&W2[(size_t)(kk + k)*C2 + n0 + b_nb];
            uint4 o;
            o.x = cvt_tf32(v.x); o.y = cvt_tf32(v.y);
            o.z = cvt_tf32(v.z); o.w = cvt_tf32(v.w);
            *(uint4*)&sB[k*SB_STR + b_nb] = o;
        }
        __syncthreads();
        #pragma unroll
        for (int ks = 0; ks < 4; ++ks) {
            int kb = ks*8;
            uint32_t af[2][4];
            #pragma unroll
            for (int m = 0; m < 2; ++m) {
                int mr = w*32 + m*16;
                af[m][0] = __float_as_uint(sA[(mr+g)*SA_STR   + kb + tig]);
                af[m][1] = __float_as_uint(sA[(mr+g+8)*SA_STR + kb + tig]);
                af[m][2] = __float_as_uint(sA[(mr+g)*SA_STR   + kb + tig + 4]);
                af[m][3] = __float_as_uint(sA[(mr+g+8)*SA_STR + kb + tig + 4]);
            }
            uint32_t bf[8][2];
            #pragma unroll
            for (int n = 0; n < 8; ++n) {
                bf[n][0] = __float_as_uint(sB[(kb+tig)*SB_STR   + n*8 + g]);
                bf[n][1] = __float_as_uint(sB[(kb+tig+4)*SB_STR + n*8 + g]);
            }
            #pragma unroll
            for (int m = 0; m < 2; ++m)
                #pragma unroll
                for (int n = 0; n < 8; ++n) MMA_TF32(acc[m][n], af[m], bf[n]);
        }
        __syncthreads();
    }
    #pragma unroll
    for (int m = 0; m < 2; ++m) {
        size_t r0 = row0 + w*32 + m*16 + g;
        #pragma unroll
        for (int n = 0; n < 8; ++n) {
            int col = n0 + n*8 + 2*tig;
            float2 bb = *(const float2*)&b2[col];
            *(float2*)&g_H2[r0*C2 + col]     = make_float2(acc[m][n][0]+bb.x, acc[m][n][1]+bb.y);
            *(float2*)&g_H2[(r0+8)*C2 + col] = make_float2(acc[m][n][2]+bb.x, acc[m][n][3]+bb.y);
        }
    }
}

// ---------------------------------------------------------------------------
// gmax: gmax[p][c] = max_r H2[p*20+r][c]
// ---------------------------------------------------------------------------
__global__ void gmax_kernel() {
    int p = blockIdx.x, c = threadIdx.x;   // 256 threads
    const float* src = g_H2 + (size_t)p*KNBR*C2 + c;
    float m = -FLT_MAX;
    #pragma unroll
    for (int r = 0; r < KNBR; ++r) m = fmaxf(m, src[(size_t)r*C2]);
    g_gmax[(size_t)p*C2 + c] = m;
}

// ---------------------------------------------------------------------------
// gemmFA: fA[NPTS,512] = gmax[NPTS,256] @ W3[0:256] + b3
// ---------------------------------------------------------------------------
__global__ __launch_bounds__(128) void gemmFA_kernel(
    const float* __restrict__ W3, const float* __restrict__ b3) {
    __shared__ __align__(16) float sA[GM_MT*SA_STR];
    __shared__ __align__(16) float sB[GM_KC*SB_STR];
    int t = threadIdx.x;
    int w = t >> 5, lane = t & 31;
    int g = lane >> 2, tig = lane & 3;
    size_t row0 = (size_t)blockIdx.x * GM_MT;
    int n0 = blockIdx.y * GM_NT;

    float acc[2][8][4] = {};
    int a_row = t >> 3, a_cb = (t & 7) * 4;
    int b_k = t >> 4, b_nb = (t & 15) * 4;

    for (int kk = 0; kk < C2; kk += GM_KC) {
        #pragma unroll
        for (int pq = 0; pq < 8; ++pq) {
            int r = pq*16 + a_row;
            float4 v = *(const float4*)&g_gmax[(row0 + r)*C2 + kk + a_cb];
            uint4 o;
            o.x = cvt_tf32(v.x); o.y = cvt_tf32(v.y);
            o.z = cvt_tf32(v.z); o.w = cvt_tf32(v.w);
            *(uint4*)&sA[r*SA_STR + a_cb] = o;
        }
        #pragma unroll
        for (int pq = 0; pq < 4; ++pq) {
            int k = pq*8 + b_k;
            float4 v = *(const float4*)&W3[(size_t)(kk + k)*C3 + n0 + b_nb];
            uint4 o;
            o.x = cvt_tf32(v.x); o.y = cvt_tf32(v.y);
            o.z = cvt_tf32(v.z); o.w = cvt_tf32(v.w);
            *(uint4*)&sB[k*SB_STR + b_nb] = o;
        }
        __syncthreads();
        #pragma unroll
        for (int ks = 0; ks < 4; ++ks) {
            int kb = ks*8;
            uint32_t af[2][4];
            #pragma unroll
            for (int m = 0; m < 2; ++m) {
                int mr = w*32 + m*16;
                af[m][0] = __float_as_uint(sA[(mr+g)*SA_STR   + kb + tig]);
                af[m][1] = __float_as_uint(sA[(mr+g+8)*SA_STR + kb + tig]);
                af[m][2] = __float_as_uint(sA[(mr+g)*SA_STR   + kb + tig + 4]);
                af[m][3] = __float_as_uint(sA[(mr+g+8)*SA_STR + kb + tig + 4]);
            }
            uint32_t bf[8][2];
            #pragma unroll
            for (int n = 0; n < 8; ++n) {
                bf[n][0] = __float_as_uint(sB[(kb+tig)*SB_STR   + n*8 + g]);
                bf[n][1] = __float_as_uint(sB[(kb+tig+4)*SB_STR + n*8 + g]);
            }
            #pragma unroll
            for (int m = 0; m < 2; ++m)
                #pragma unroll
                for (int n = 0; n < 8; ++n) MMA_TF32(acc[m][n], af[m], bf[n]);
        }
        __syncthreads();
    }
    #pragma unroll
    for (int m = 0; m < 2; ++m) {
        size_t r0 = row0 + w*32 + m*16 + g;
        #pragma unroll
        for (int n = 0; n < 8; ++n) {
            int col = n0 + n*8 + 2*tig;
            float2 bb = *(const float2*)&b3[col];
            *(float2*)&g_fA[r0*C3 + col]     = make_float2(acc[m][n][0]+bb.x, acc[m][n][1]+bb.y);
            *(float2*)&g_fA[(r0+8)*C3 + col] = make_float2(acc[m][n][2]+bb.x, acc[m][n][3]+bb.y);
        }
    }
}

// ---------------------------------------------------------------------------
// gemm3: fpre[NROWS,512] = H2[NROWS,256] @ W3[256:512] + fA[row/20]
// ---------------------------------------------------------------------------
__global__ __launch_bounds__(128) void gemm3_kernel(const float* __restrict__ W3) {
    __shared__ __align__(16) float sA[GM_MT*SA_STR];
    __shared__ __align__(16) float sB[GM_KC*SB_STR];
    int t = threadIdx.x;
    int w = t >> 5, lane = t & 31;
    int g = lane >> 2, tig = lane & 3;
    size_t row0 = (size_t)blockIdx.x * GM_MT;
    int n0 = blockIdx.y * GM_NT;

    float acc[2][8][4] = {};
    int a_row = t >> 3, a_cb = (t & 7) * 4;
    int b_k = t >> 4, b_nb = (t & 15) * 4;

    for (int kk = 0; kk < C2; kk += GM_KC) {
        #pragma unroll
        for (int pq = 0; pq < 8; ++pq) {
            int r = pq*16 + a_row;
            float4 v = *(const float4*)&g_H2[(row0 + r)*C2 + kk + a_cb];
            uint4 o;
            o.x = cvt_tf32(v.x); o.y = cvt_tf32(v.y);
            o.z = cvt_tf32(v.z); o.w = cvt_tf32(v.w);
            *(uint4*)&sA[r*SA_STR + a_cb] = o;
        }
        #pragma unroll
        for (int pq = 0; pq < 4; ++pq) {
            int k = pq*8 + b_k;
            float4 v = *(const float4*)&W3[(size_t)(C2 + kk + k)*C3 + n0 + b_nb];
            uint4 o;
            o.x = cvt_tf32(v.x); o.y = cvt_tf32(v.y);
            o.z = cvt_tf32(v.z); o.w = cvt_tf32(v.w);
            *(uint4*)&sB[k*SB_STR + b_nb] = o;
        }
        __syncthreads();
        #pragma unroll
        for (int ks = 0; ks < 4; ++ks) {
            int kb = ks*8;
            uint32_t af[2][4];
            #pragma unroll
            for (int m = 0; m < 2; ++m) {
                int mr = w*32 + m*16;
                af[m][0] = __float_as_uint(sA[(mr+g)*SA_STR   + kb + tig]);
                af[m][1] = __float_as_uint(sA[(mr+g+8)*SA_STR + kb + tig]);
                af[m][2] = __float_as_uint(sA[(mr+g)*SA_STR   + kb + tig + 4]);
                af[m][3] = __float_as_uint(sA[(mr+g+8)*SA_STR + kb + tig + 4]);
            }
            uint32_t bf[8][2];
            #pragma unroll
            for (int n = 0; n < 8; ++n) {
                bf[n][0] = __float_as_uint(sB[(kb+tig)*SB_STR   + n*8 + g]);
                bf[n][1] = __float_as_uint(sB[(kb+tig+4)*SB_STR + n*8 + g]);
            }
            #pragma unroll
            for (int m = 0; m < 2; ++m)
                #pragma unroll
                for (int n = 0; n < 8; ++n) MMA_TF32(acc[m][n], af[m], bf[n]);
        }
        __syncthreads();
    }
    #pragma unroll
    for (int m = 0; m < 2; ++m) {
        size_t rA = row0 + w*32 + m*16 + g;
        size_t rB = rA + 8;
        size_t pA = rA / KNBR, pB = rB / KNBR;
        #pragma unroll
        for (int n = 0; n < 8; ++n) {
            int col = n0 + n*8 + 2*tig;
            float2 fa = *(const float2*)&g_fA[pA*C3 + col];
            float2 fb = *(const float2*)&g_fA[pB*C3 + col];
            *(float2*)&g_fpre[rA*C3 + col] = make_float2(acc[m][n][0]+fa.x, acc[m][n][1]+fa.y);
            *(float2*)&g_fpre[rB*C3 + col] = make_float2(acc[m][n][2]+fb.x, acc[m][n][3]+fb.y);
        }
    }
}

// ---------------------------------------------------------------------------
// BN3 stats (unchanged)
// ---------------------------------------------------------------------------
__global__ void stats3_kernel() {
    int blk = blockIdx.x, t = threadIdx.x;
    size_t row0 = (size_t)blk * ROWS_PER_STAT;
    float s0 = 0.f, q0 = 0.f, s1 = 0.f, q1 = 0.f;
    for (int r = 0; r < ROWS_PER_STAT; ++r) {
        size_t base = (row0 + r)*C3;
        float v0 = g_fpre[base + t];
        float v1 = g_fpre[base + C2 + t];
        s0 += v0; q0 += v0*v0;
        s1 += v1; q1 += v1*v1;
    }
    g_part3[blk*(2*C3) + t]           = s0;
    g_part3[blk*(2*C3) + C2 + t]      = s1;
    g_part3[blk*(2*C3) + C3 + t]      = q0;
    g_part3[blk*(2*C3) + C3 + C2 + t] = q1;
}

__global__ void fin3_kernel(const float* __restrict__ g3,
                            const float* __restrict__ be3) {
    int c = threadIdx.x;
    float s = 0.f, q = 0.f;
    for (int i = 0; i < STAT_BLOCKS; ++i) {
        s += g_part3[i*(2*C3)+c];
        q += g_part3[i*(2*C3)+C3+c];
    }
    float mu  = s / (float)NROWS;
    float var = q / (float)NROWS - mu*mu;
    float sc  = g3[c] * rsqrtf(var + BN_EPS);
    g_ss3[c]    = sc;
    g_ss3[C3+c] = be3[c] - mu*sc;
}

// ---------------------------------------------------------------------------
// gemm_final (unchanged from R5 — passing)
// ---------------------------------------------------------------------------
__global__ __launch_bounds__(128) void gemm_final_kernel(const float* __restrict__ W4) {
    __shared__ __align__(16) float sA[GM_MT*SA_STR];
    __shared__ __align__(16) float sB[GM_KC*SB_STR];
    int t = threadIdx.x;
    int w = t >> 5, lane = t & 31;
    int g = lane >> 2, tig = lane & 3;
    size_t row0 = (size_t)blockIdx.x * GM_MT;
    int n0 = blockIdx.y * GM_NT;

    float acc[2][8][4] = {};
    int a_row = t >> 3, a_cb = (t & 7) * 4;
    int b_k = t >> 4, b_nb = (t & 15) * 4;

    for (int kk = 0; kk < C3; kk += GM_KC) {
        {
            float4 sc = *(const float4*)&g_ss3[kk + a_cb];
            float4 sh = *(const float4*)&g_ss3[C3 + kk + a_cb];
            #pragma unroll
            for (int pq = 0; pq < 8; ++pq) {
                int r = pq*16 + a_row;
                float4 v = *(const float4*)&g_fpre[(row0 + r)*C3 + kk + a_cb];
                uint4 o;
                o.x = cvt_tf32(fmaxf(v.x*sc.x + sh.x, 0.f));
                o.y = cvt_tf32(fmaxf(v.y*sc.y + sh.y, 0.f));
                o.z = cvt_tf32(fmaxf(v.z*sc.z + sh.z, 0.f));
                o.w = cvt_tf32(fmaxf(v.w*sc.w + sh.w, 0.f));
                *(uint4*)&sA[r*SA_STR + a_cb] = o;
            }
        }
        {
            #pragma unroll
            for (int pq = 0; pq < 4; ++pq) {
                int k = pq*8 + b_k;
                float4 v = *(const float4*)&W4[(size_t)(kk + k)*CH + n0 + b_nb];
                uint4 o;
                o.x = cvt_tf32(v.x); o.y = cvt_tf32(v.y);
                o.z = cvt_tf32(v.z); o.w = cvt_tf32(v.w);
                *(uint4*)&sB[k*SB_STR + b_nb] = o;
            }
        }
        __syncthreads();
        #pragma unroll
        for (int ks = 0; ks < 4; ++ks) {
            int kb = ks*8;
            uint32_t af[2][4];
            #pragma unroll
            for (int m = 0; m < 2; ++m) {
                int mr = w*32 + m*16;
                af[m][0] = __float_as_uint(sA[(mr+g)*SA_STR   + kb + tig]);
                af[m][1] = __float_as_uint(sA[(mr+g+8)*SA_STR + kb + tig]);
                af[m][2] = __float_as_uint(sA[(mr+g)*SA_STR   + kb + tig + 4]);
                af[m][3] = __float_as_uint(sA[(mr+g+8)*SA_STR + kb + tig + 4]);
            }
            uint32_t bf[8][2];
            #pragma unroll
            for (int n = 0; n < 8; ++n) {
                bf[n][0] = __float_as_uint(sB[(kb+tig)*SB_STR   + n*8 + g]);
                bf[n][1] = __float_as_uint(sB[(kb+tig+4)*SB_STR + n*8 + g]);
            }
            #pragma unroll
            for (int m = 0; m < 2; ++m)
                #pragma unroll
                for (int n = 0; n < 8; ++n) MMA_TF32(acc[m][n], af[m], bf[n]);
        }
        __syncthreads();
    }
    #pragma unroll
    for (int m = 0; m < 2; ++m) {
        size_t r0 = row0 + w*32 + m*16 + g;
        #pragma unroll
        for (int n = 0; n < 8; ++n) {
            int col = n0 + n*8 + 2*tig;
            *(float2*)&g_F[r0*CH + col]     = make_float2(acc[m][n][0], acc[m][n][1]);
            *(float2*)&g_F[(r0+8)*CH + col] = make_float2(acc[m][n][2], acc[m][n][3]);
        }
    }
}

// ---------------------------------------------------------------------------
// maxpool / copy (unchanged)
// ---------------------------------------------------------------------------
__global__ void maxpool_kernel(const float* __restrict__ b4,
                               float* __restrict__ out) {
    int p = blockIdx.x, c = threadIdx.x;
    const float* src = g_F + (size_t)p*KNBR*CH + c;
    float m = -FLT_MAX;
    #pragma unroll
    for (int r = 0; r < KNBR; ++r) m = fmaxf(m, src[(size_t)r*CH]);
    out[(size_t)BB*NN*3 + (size_t)p*CH + c] = m + b4[c];
}

__global__ void copy_xyz_kernel(const float* __restrict__ xyz,
                                float* __restrict__ out) {
    int i = blockIdx.x*256 + threadIdx.x;
    if (i < BB*NN*3) out[i] = xyz[i];
}

extern "C" void kernel_launch(void* const* d_in, const int* in_sizes, int n_in,
                              void* d_out, int out_size) {
    (void)in_sizes; (void)n_in; (void)out_size;
    const float* xyz = (const float*)d_in[0];
    const float* W1  = (const float*)d_in[1];
    const float* b1  = (const float*)d_in[2];
    const float* g1  = (const float*)d_in[3];
    const float* be1 = (const float*)d_in[4];
    const float* W2  = (const float*)d_in[5];
    const float* b2  = (const float*)d_in[6];
    const float* W3  = (const float*)d_in[7];
    const float* b3  = (const float*)d_in[8];
    const float* g3  = (const float*)d_in[9];
    const float* be3 = (const float*)d_in[10];
    const float* W4  = (const float*)d_in[11];
    const float* b4  = (const float*)d_in[12];
    float* out = (float*)d_out;

    knn_kernel<<<NPTS, 256>>>(xyz);
    stats1_kernel<<<STAT_BLOCKS, 128>>>(xyz, W1, b1);
    fin1_kernel<<<1, C1>>>(g1, be1);
    edge_kernel<<<NROWS, 128>>>(xyz, W1, b1);
    {
        dim3 grid2(NROWS/GM_MT, C2/GM_NT);   // 1280 x 4
        gemm2_kernel<<<grid2, 128>>>(W2, b2);
    }
    gmax_kernel<<<NPTS, C2>>>();
    {
        dim3 gridFA(NPTS/GM_MT, C3/GM_NT);   // 64 x 8
        gemmFA_kernel<<<gridFA, 128>>>(W3, b3);
    }
    {
        dim3 grid3(NROWS/GM_MT, C3/GM_NT);   // 1280 x 8
        gemm3_kernel<<<grid3, 128>>>(W3);
    }
    stats3_kernel<<<STAT_BLOCKS, 256>>>();
    fin3_kernel<<<1, C3>>>(g3, be3);
    {
        dim3 grid4(NROWS/GM_MT, CH/GM_NT);   // 1280 x 6
        gemm_final_kernel<<<grid4, 128>>>(W4);
    }
    maxpool_kernel<<<NPTS, CH>>>(b4, out);
    copy_xyz_kernel<<<(BB*NN*3 + 255)/256, 256>>>(xyz, out);
}

// round 7
// speedup vs baseline: 5.2292x; 1.1309x over previous
#include <cuda_runtime.h>
#include <math.h>
#include <float.h>
#include <stdint.h>

// Problem constants
#define BB 2
#define NN 4096
#define KNBR 20
#define NPTS (BB*NN)            // 8192
#define NROWS (NPTS*KNBR)       // 163840
#define C1 128
#define C2 256
#define C3 512
#define CH 384
#define BN_EPS 1e-5f
#define STAT_BLOCKS 1024
#define ROWS_PER_STAT (NROWS/STAT_BLOCKS) // 160

__device__ __forceinline__ uint32_t cvt_tf32(float f) {
    uint32_t r; asm("cvt.rna.tf32.f32 %0, %1;" : "=r"(r) : "f"(f)); return r;
}
__device__ __forceinline__ void cp16(float* dst, const float* src) {
    uint32_t s = (uint32_t)__cvta_generic_to_shared(dst);
    asm volatile("cp.async.cg.shared.global [%0], [%1], 16;" :: "r"(s), "l"(src));
}
#define CP_COMMIT() asm volatile("cp.async.commit_group;" ::: "memory")
#define CP_WAIT(n)  asm volatile("cp.async.wait_group %0;" :: "n"(n) : "memory")

// order-preserving float<->uint for atomicMax
__device__ __forceinline__ unsigned fenc(float f) {
    int b = __float_as_int(f);
    return (b < 0) ? ~((unsigned)b) : (((unsigned)b) | 0x80000000u);
}
__device__ __forceinline__ float fdec(unsigned k) {
    return (k & 0x80000000u) ? __int_as_float((int)(k ^ 0x80000000u))
                             : __int_as_float((int)(~k));
}

// ---------------- scratch (static device globals) ----------------
__device__ int   g_idx[NROWS];
__device__ float g_part1[STAT_BLOCKS*2*C1];
__device__ float g_ss1[2*C1];
__device__ float g_A[(size_t)NROWS*C1];      // tf32-rounded
__device__ float g_H2[(size_t)NROWS*C2];     // tf32-rounded
__device__ float g_gmax[(size_t)NPTS*C2];
__device__ float g_fA[(size_t)NPTS*C3];
__device__ float g_fpre[(size_t)NROWS*C3];   // 335 MB (raw fp32)
__device__ float g_part3[STAT_BLOCKS*2*C3];
__device__ float g_ss3[2*C3];
__device__ float g_w3r[C2*C3];               // rounded W3[256:512]
__device__ float g_w4r[C3*CH];               // rounded W4

// ---------------------------------------------------------------------------
// K1: KNN (unchanged — passing)
// ---------------------------------------------------------------------------
__global__ void knn_kernel(const float* __restrict__ xyz) {
    __shared__ float sd[NN];
    __shared__ float rv[256];
    __shared__ int   ri[256];
    int p = blockIdx.x;
    int b = p >> 12, n = p & (NN-1);
    int t = threadIdx.x;
    const float* base = xyz + (size_t)b*NN*3;
    float cx = base[n*3+0], cy = base[n*3+1], cz = base[n*3+2];
    float pp = cx*cx + cy*cy + cz*cz;
    for (int m = t; m < NN; m += 256) {
        float qx = base[m*3+0], qy = base[m*3+1], qz = base[m*3+2];
        float qq = qx*qx + qy*qy + qz*qz;
        float pq = cx*qx + cy*qy + cz*qz;
        sd[m] = pp + qq - 2.f*pq;
    }
    __syncthreads();
    for (int round = 0; round < KNBR; ++round) {
        float bv = FLT_MAX; int bi = NN;
        for (int m = t; m < NN; m += 256) {
            float v = sd[m];
            if (v < bv) { bv = v; bi = m; }
        }
        rv[t] = bv; ri[t] = bi;
        __syncthreads();
        #pragma unroll
        for (int s = 128; s > 0; s >>= 1) {
            if (t < s) {
                float ov = rv[t+s]; int oi = ri[t+s];
                if (ov < rv[t] || (ov == rv[t] && oi < ri[t])) { rv[t] = ov; ri[t] = oi; }
            }
            __syncthreads();
        }
        if (t == 0) {
            g_idx[p*KNBR + round] = ri[0];
            sd[ri[0]] = FLT_MAX;
        }
        __syncthreads();
    }
}

// ---------------------------------------------------------------------------
// BN1 stats (unchanged)
// ---------------------------------------------------------------------------
__global__ void stats1_kernel(const float* __restrict__ xyz,
                              const float* __restrict__ W1,
                              const float* __restrict__ b1) {
    __shared__ float se[ROWS_PER_STAT*6];
    int blk = blockIdx.x, t = threadIdx.x;
    int row0 = blk * ROWS_PER_STAT;
    for (int r = t; r < ROWS_PER_STAT; r += 128) {
        int gr = row0 + r;
        int p  = gr / KNBR;
        int b  = p >> 12, n = p & (NN-1);
        int id = g_idx[gr];
        const float* cb = xyz + ((size_t)b*NN + n)*3;
        const float* nb = xyz + ((size_t)b*NN + id)*3;
        se[r*6+0] = nb[0]-cb[0];
        se[r*6+1] = nb[1]-cb[1];
        se[r*6+2] = nb[2]-cb[2];
        se[r*6+3] = cb[0]; se[r*6+4] = cb[1]; se[r*6+5] = cb[2];
    }
    __syncthreads();
    float w0 = W1[0*C1+t], w1 = W1[1*C1+t], w2 = W1[2*C1+t],
          w3 = W1[3*C1+t], w4 = W1[4*C1+t], w5 = W1[5*C1+t], bb = b1[t];
    float s = 0.f, q = 0.f;
    for (int r = 0; r < ROWS_PER_STAT; ++r) {
        float h = bb + se[r*6+0]*w0 + se[r*6+1]*w1 + se[r*6+2]*w2
                     + se[r*6+3]*w3 + se[r*6+4]*w4 + se[r*6+5]*w5;
        s += h; q += h*h;
    }
    g_part1[blk*(2*C1) + t]      = s;
    g_part1[blk*(2*C1) + C1 + t] = q;
}

__global__ void fin1_kernel(const float* __restrict__ g1,
                            const float* __restrict__ be1) {
    int c = threadIdx.x;
    float s = 0.f, q = 0.f;
    for (int i = 0; i < STAT_BLOCKS; ++i) {
        s += g_part1[i*(2*C1)+c];
        q += g_part1[i*(2*C1)+C1+c];
    }
    float mu  = s / (float)NROWS;
    float var = q / (float)NROWS - mu*mu;
    float sc  = g1[c] * rsqrtf(var + BN_EPS);
    g_ss1[c]     = sc;
    g_ss1[C1+c]  = be1[c] - mu*sc;
}

// ---------------------------------------------------------------------------
// edge16: 16 rows per block, 256 threads; weights loaded once per 8 outputs
// ---------------------------------------------------------------------------
__global__ __launch_bounds__(256) void edge_kernel(
    const float* __restrict__ xyz,
    const float* __restrict__ W1, const float* __restrict__ b1) {
    __shared__ float sE[16*6];
    int row0 = blockIdx.x * 16, t = threadIdx.x;
    if (t < 96) {
        int r = t / 6, d = t - r*6;
        int row = row0 + r;
        int p = row / KNBR;
        int b = p >> 12, n = p & (NN-1);
        float v;
        if (d < 3) {
            int id = g_idx[row];
            v = xyz[((size_t)b*NN + id)*3 + d] - xyz[((size_t)b*NN + n)*3 + d];
        } else {
            v = xyz[((size_t)b*NN + n)*3 + (d-3)];
        }
        sE[r*6 + d] = v;
    }
    __syncthreads();
    int c = t & (C1-1), h = t >> 7;
    float w0 = W1[0*C1+c], w1 = W1[1*C1+c], w2 = W1[2*C1+c],
          w3 = W1[3*C1+c], w4 = W1[4*C1+c], w5 = W1[5*C1+c];
    float bb = b1[c], sc = g_ss1[c], sh = g_ss1[C1+c];
    #pragma unroll
    for (int rr = 0; rr < 8; ++rr) {
        int r = h*8 + rr;
        float hv = bb + sE[r*6+0]*w0 + sE[r*6+1]*w1 + sE[r*6+2]*w2
                      + sE[r*6+3]*w3 + sE[r*6+4]*w4 + sE[r*6+5]*w5;
        hv = fmaxf(hv*sc + sh, 0.f);
        g_A[(size_t)(row0 + r)*C1 + c] = __uint_as_float(cvt_tf32(hv));
    }
}

// ---------------------------------------------------------------------------
// weight prep: rounded copies for cp.async GEMMs
// ---------------------------------------------------------------------------
__global__ void w3r_kernel(const float* __restrict__ W3) {
    int i = blockIdx.x*256 + threadIdx.x;
    if (i < C2*C3) g_w3r[i] = __uint_as_float(cvt_tf32(W3[(size_t)C2*C3 + i]));
}
__global__ void w4r_kernel(const float* __restrict__ W4) {
    int i = blockIdx.x*256 + threadIdx.x;
    if (i < C3*CH) g_w4r[i] = __uint_as_float(cvt_tf32(W4[i]));
}

// ===========================================================================
// mma tile config: CTA 128x64, 4 warps, K-chunk 32
// ===========================================================================
#define GM_MT 128
#define GM_NT 64
#define GM_KC 32
#define SA_STR 36
#define SB_STR 72
#define A_BUF (GM_MT*SA_STR)   // 4608 floats
#define B_BUF (GM_KC*SB_STR)   // 2304 floats

#define MMA_TF32(acc, af, bf) \
    asm volatile( \
        "mma.sync.aligned.m16n8k8.row.col.f32.tf32.tf32.f32 " \
        "{%0,%1,%2,%3}, {%4,%5,%6,%7}, {%8,%9}, {%0,%1,%2,%3};" \
        : "+f"((acc)[0]), "+f"((acc)[1]), "+f"((acc)[2]), "+f"((acc)[3]) \
        : "r"((af)[0]), "r"((af)[1]), "r"((af)[2]), "r"((af)[3]), \
          "r"((bf)[0]), "r"((bf)[1]))

// ---------------------------------------------------------------------------
// gemm2: H2 = A @ W2 + b2, stored tf32-rounded (non-pipelined; small)
// ---------------------------------------------------------------------------
__global__ __launch_bounds__(128) void gemm2_kernel(
    const float* __restrict__ W2, const float* __restrict__ b2) {
    __shared__ __align__(16) float sA[GM_MT*SA_STR];
    __shared__ __align__(16) float sB[GM_KC*SB_STR];
    int t = threadIdx.x;
    int w = t >> 5, lane = t & 31;
    int g = lane >> 2, tig = lane & 3;
    size_t row0 = (size_t)blockIdx.x * GM_MT;
    int n0 = blockIdx.y * GM_NT;

    float acc[2][8][4] = {};
    int a_row = t >> 3, a_cb = (t & 7) * 4;
    int b_k = t >> 4, b_nb = (t & 15) * 4;

    for (int kk = 0; kk < C1; kk += GM_KC) {
        #pragma unroll
        for (int pq = 0; pq < 8; ++pq) {
            int r = pq*16 + a_row;
            float4 v = *(const float4*)&g_A[(row0 + r)*C1 + kk + a_cb];
            *(float4*)&sA[r*SA_STR + a_cb] = v;
        }
        #pragma unroll
        for (int pq = 0; pq < 4; ++pq) {
            int k = pq*8 + b_k;
            float4 v = *(const float4*)&W2[(size_t)(kk + k)*C2 + n0 + b_nb];
            uint4 o;
            o.x = cvt_tf32(v.x); o.y = cvt_tf32(v.y);
            o.z = cvt_tf32(v.z); o.w = cvt_tf32(v.w);
            *(uint4*)&sB[k*SB_STR + b_nb] = o;
        }
        __syncthreads();
        #pragma unroll
        for (int ks = 0; ks < 4; ++ks) {
            int kb = ks*8;
            uint32_t af[2][4];
            #pragma unroll
            for (int m = 0; m < 2; ++m) {
                int mr = w*32 + m*16;
                af[m][0] = __float_as_uint(sA[(mr+g)*SA_STR   + kb + tig]);
                af[m][1] = __float_as_uint(sA[(mr+g+8)*SA_STR + kb + tig]);
                af[m][2] = __float_as_uint(sA[(mr+g)*SA_STR   + kb + tig + 4]);
                af[m][3] = __float_as_uint(sA[(mr+g+8)*SA_STR + kb + tig + 4]);
            }
            uint32_t bf[8][2];
            #pragma unroll
            for (int n = 0; n < 8; ++n) {
                bf[n][0] = __float_as_uint(sB[(kb+tig)*SB_STR   + n*8 + g]);
                bf[n][1] = __float_as_uint(sB[(kb+tig+4)*SB_STR + n*8 + g]);
            }
            #pragma unroll
            for (int m = 0; m < 2; ++m)
                #pragma unroll
                for (int n = 0; n < 8; ++n) MMA_TF32(acc[m][n], af[m], bf[n]);
        }
        __syncthreads();
    }
    #pragma unroll
    for (int m = 0; m < 2; ++m) {
        size_t r0 = row0 + w*32 + m*16 + g;
        #pragma unroll
        for (int n = 0; n < 8; ++n) {
            int col = n0 + n*8 + 2*tig;
            float2 bb = *(const float2*)&b2[col];
            uint2 o0 = make_uint2(cvt_tf32(acc[m][n][0]+bb.x), cvt_tf32(acc[m][n][1]+bb.y));
            uint2 o1 = make_uint2(cvt_tf32(acc[m][n][2]+bb.x), cvt_tf32(acc[m][n][3]+bb.y));
            *(uint2*)&g_H2[r0*C2 + col]     = o0;
            *(uint2*)&g_H2[(r0+8)*C2 + col] = o1;
        }
    }
}

// ---------------------------------------------------------------------------
// gmax: gmax[p][c] = max_r H2[p*20+r][c]   (H2 rounded; max of rounded ==
// rounded max — monotone elementwise rounding, matches prior behavior)
// ---------------------------------------------------------------------------
__global__ void gmax_kernel() {
    int p = blockIdx.x, c = threadIdx.x;
    const float* src = g_H2 + (size_t)p*KNBR*C2 + c;
    float m = -FLT_MAX;
    #pragma unroll
    for (int r = 0; r < KNBR; ++r) m = fmaxf(m, src[(size_t)r*C2]);
    g_gmax[(size_t)p*C2 + c] = m;
}

// ---------------------------------------------------------------------------
// gemmFA: fA = gmax @ W3[0:256] + b3 (unchanged; tiny)
// ---------------------------------------------------------------------------
__global__ __launch_bounds__(128) void gemmFA_kernel(
    const float* __restrict__ W3, const float* __restrict__ b3) {
    __shared__ __align__(16) float sA[GM_MT*SA_STR];
    __shared__ __align__(16) float sB[GM_KC*SB_STR];
    int t = threadIdx.x;
    int w = t >> 5, lane = t & 31;
    int g = lane >> 2, tig = lane & 3;
    size_t row0 = (size_t)blockIdx.x * GM_MT;
    int n0 = blockIdx.y * GM_NT;

    float acc[2][8][4] = {};
    int a_row = t >> 3, a_cb = (t & 7) * 4;
    int b_k = t >> 4, b_nb = (t & 15) * 4;

    for (int kk = 0; kk < C2; kk += GM_KC) {
        #pragma unroll
        for (int pq = 0; pq < 8; ++pq) {
            int r = pq*16 + a_row;
            float4 v = *(const float4*)&g_gmax[(row0 + r)*C2 + kk + a_cb];
            *(float4*)&sA[r*SA_STR + a_cb] = v;   // already rounded
        }
        #pragma unroll
        for (int pq = 0; pq < 4; ++pq) {
            int k = pq*8 + b_k;
            float4 v = *(const float4*)&W3[(size_t)(kk + k)*C3 + n0 + b_nb];
            uint4 o;
            o.x = cvt_tf32(v.x); o.y = cvt_tf32(v.y);
            o.z = cvt_tf32(v.z); o.w = cvt_tf32(v.w);
            *(uint4*)&sB[k*SB_STR + b_nb] = o;
        }
        __syncthreads();
        #pragma unroll
        for (int ks = 0; ks < 4; ++ks) {
            int kb = ks*8;
            uint32_t af[2][4];
            #pragma unroll
            for (int m = 0; m < 2; ++m) {
                int mr = w*32 + m*16;
                af[m][0] = __float_as_uint(sA[(mr+g)*SA_STR   + kb + tig]);
                af[m][1] = __float_as_uint(sA[(mr+g+8)*SA_STR + kb + tig]);
                af[m][2] = __float_as_uint(sA[(mr+g)*SA_STR   + kb + tig + 4]);
                af[m][3] = __float_as_uint(sA[(mr+g+8)*SA_STR + kb + tig + 4]);
            }
            uint32_t bf[8][2];
            #pragma unroll
            for (int n = 0; n < 8; ++n) {
                bf[n][0] = __float_as_uint(sB[(kb+tig)*SB_STR   + n*8 + g]);
                bf[n][1] = __float_as_uint(sB[(kb+tig+4)*SB_STR + n*8 + g]);
            }
            #pragma unroll
            for (int m = 0; m < 2; ++m)
                #pragma unroll
                for (int n = 0; n < 8; ++n) MMA_TF32(acc[m][n], af[m], bf[n]);
        }
        __syncthreads();
    }
    #pragma unroll
    for (int m = 0; m < 2; ++m) {
        size_t r0 = row0 + w*32 + m*16 + g;
        #pragma unroll
        for (int n = 0; n < 8; ++n) {
            int col = n0 + n*8 + 2*tig;
            float2 bb = *(const float2*)&b3[col];
            *(float2*)&g_fA[r0*C3 + col]     = make_float2(acc[m][n][0]+bb.x, acc[m][n][1]+bb.y);
            *(float2*)&g_fA[(r0+8)*C3 + col] = make_float2(acc[m][n][2]+bb.x, acc[m][n][3]+bb.y);
        }
    }
}

// ---------------------------------------------------------------------------
// gemm3 (cp.async pipelined): fpre = H2 @ W3r + fA[row/20]
// ---------------------------------------------------------------------------
__global__ __launch_bounds__(128) void gemm3_kernel() {
    extern __shared__ __align__(16) float dyn[];
    float* bufA = dyn;              // 2 x A_BUF
    float* bufB = dyn + 2*A_BUF;    // 2 x B_BUF
    int t = threadIdx.x;
    int w = t >> 5, lane = t & 31;
    int g = lane >> 2, tig = lane & 3;
    size_t row0 = (size_t)blockIdx.x * GM_MT;
    int n0 = blockIdx.y * GM_NT;

    float acc[2][8][4] = {};
    int a_row = t >> 3, a_cb = (t & 7) * 4;
    int b_k = t >> 4, b_nb = (t & 15) * 4;

    const int NC = C2/GM_KC;  // 8

    // stage chunk 0 into buffer 0
    {
        float* A = bufA; float* B = bufB;
        #pragma unroll
        for (int pq = 0; pq < 8; ++pq) {
            int r = pq*16 + a_row;
            cp16(&A[r*SA_STR + a_cb], &g_H2[(row0 + r)*C2 + a_cb]);
        }
        #pragma unroll
        for (int pq = 0; pq < 4; ++pq) {
            int k = pq*8 + b_k;
            cp16(&B[k*SB_STR + b_nb], &g_w3r[(size_t)k*C3 + n0 + b_nb]);
        }
        CP_COMMIT();
    }

    int buf = 0;
    for (int c = 0; c < NC; ++c) {
        if (c + 1 < NC) {
            int kk = (c+1)*GM_KC;
            float* A = bufA + (buf^1)*A_BUF;
            float* B = bufB + (buf^1)*B_BUF;
            #pragma unroll
            for (int pq = 0; pq < 8; ++pq) {
                int r = pq*16 + a_row;
                cp16(&A[r*SA_STR + a_cb], &g_H2[(row0 + r)*C2 + kk + a_cb]);
            }
            #pragma unroll
            for (int pq = 0; pq < 4; ++pq) {
                int k = pq*8 + b_k;
                cp16(&B[k*SB_STR + b_nb], &g_w3r[(size_t)(kk + k)*C3 + n0 + b_nb]);
            }
            CP_COMMIT();
            CP_WAIT(1);
        } else {
            CP_WAIT(0);
        }
        __syncthreads();

        float* A = bufA + buf*A_BUF;
        float* B = bufB + buf*B_BUF;
        #pragma unroll
        for (int ks = 0; ks < 4; ++ks) {
            int kb = ks*8;
            uint32_t af[2][4];
            #pragma unroll
            for (int m = 0; m < 2; ++m) {
                int mr = w*32 + m*16;
                af[m][0] = __float_as_uint(A[(mr+g)*SA_STR   + kb + tig]);
                af[m][1] = __float_as_uint(A[(mr+g+8)*SA_STR + kb + tig]);
                af[m][2] = __float_as_uint(A[(mr+g)*SA_STR   + kb + tig + 4]);
                af[m][3] = __float_as_uint(A[(mr+g+8)*SA_STR + kb + tig + 4]);
            }
            uint32_t bf[8][2];
            #pragma unroll
            for (int n = 0; n < 8; ++n) {
                bf[n][0] = __float_as_uint(B[(kb+tig)*SB_STR   + n*8 + g]);
                bf[n][1] = __float_as_uint(B[(kb+tig+4)*SB_STR + n*8 + g]);
            }
            #pragma unroll
            for (int m = 0; m < 2; ++m)
                #pragma unroll
                for (int n = 0; n < 8; ++n) MMA_TF32(acc[m][n], af[m], bf[n]);
        }
        __syncthreads();
        buf ^= 1;
    }

    #pragma unroll
    for (int m = 0; m < 2; ++m) {
        size_t rA = row0 + w*32 + m*16 + g;
        size_t rB = rA + 8;
        size_t pA = rA / KNBR, pB = rB / KNBR;
        #pragma unroll
        for (int n = 0; n < 8; ++n) {
            int col = n0 + n*8 + 2*tig;
            float2 fa = *(const float2*)&g_fA[pA*C3 + col];
            float2 fb = *(const float2*)&g_fA[pB*C3 + col];
            *(float2*)&g_fpre[rA*C3 + col] = make_float2(acc[m][n][0]+fa.x, acc[m][n][1]+fa.y);
            *(float2*)&g_fpre[rB*C3 + col] = make_float2(acc[m][n][2]+fb.x, acc[m][n][3]+fb.y);
        }
    }
}

// ---------------------------------------------------------------------------
// BN3 stats (float4)
// ---------------------------------------------------------------------------
__global__ void stats3_kernel() {
    int blk = blockIdx.x, t = threadIdx.x;   // 128 threads
    int c4 = t*4;
    size_t row0 = (size_t)blk * ROWS_PER_STAT;
    float4 s = make_float4(0.f,0.f,0.f,0.f);
    float4 q = make_float4(0.f,0.f,0.f,0.f);
    for (int r = 0; r < ROWS_PER_STAT; ++r) {
        float4 v = *(const float4*)&g_fpre[(row0 + r)*C3 + c4];
        s.x += v.x; s.y += v.y; s.z += v.z; s.w += v.w;
        q.x += v.x*v.x; q.y += v.y*v.y; q.z += v.z*v.z; q.w += v.w*v.w;
    }
    *(float4*)&g_part3[blk*(2*C3) + c4]      = s;
    *(float4*)&g_part3[blk*(2*C3) + C3 + c4] = q;
}

__global__ void fin3_kernel(const float* __restrict__ g3,
                            const float* __restrict__ be3) {
    int c = threadIdx.x;   // 512
    float s = 0.f, q = 0.f;
    for (int i = 0; i < STAT_BLOCKS; ++i) {
        s += g_part3[i*(2*C3)+c];
        q += g_part3[i*(2*C3)+C3+c];
    }
    float mu  = s / (float)NROWS;
    float var = q / (float)NROWS - mu*mu;
    float sc  = g3[c] * rsqrtf(var + BN_EPS);
    g_ss3[c]    = sc;
    g_ss3[C3+c] = be3[c] - mu*sc;
}

// ---------------------------------------------------------------------------
// init keys (output feature region used as atomicMax key storage)
// ---------------------------------------------------------------------------
__global__ void initkeys_kernel(unsigned* __restrict__ keys) {
    int i = blockIdx.x*256 + threadIdx.x;
    if (i < NPTS*CH) keys[i] = 0u;
}

// ---------------------------------------------------------------------------
// gemm_final (cp.async pipelined, bn3 at fragment load, fused atomic maxpool)
// ---------------------------------------------------------------------------
__global__ __launch_bounds__(128) void gemm_final_kernel(unsigned* __restrict__ keys) {
    extern __shared__ __align__(16) float dyn[];
    float* bufA = dyn;                       // 2 x A_BUF
    float* bufB = dyn + 2*A_BUF;             // 2 x B_BUF
    float* sS   = dyn + 2*A_BUF + 2*B_BUF;   // 1024: [scale 512][shift 512]
    int t = threadIdx.x;
    int w = t >> 5, lane = t & 31;
    int g = lane >> 2, tig = lane & 3;
    size_t row0 = (size_t)blockIdx.x * GM_MT;
    int n0 = blockIdx.y * GM_NT;

    float acc[2][8][4] = {};
    int a_row = t >> 3, a_cb = (t & 7) * 4;
    int b_k = t >> 4, b_nb = (t & 15) * 4;

    for (int i = t; i < 2*C3; i += 128) sS[i] = g_ss3[i];

    const int NC = C3/GM_KC;  // 16

    {
        float* A = bufA; float* B = bufB;
        #pragma unroll
        for (int pq = 0; pq < 8; ++pq) {
            int r = pq*16 + a_row;
            cp16(&A[r*SA_STR + a_cb], &g_fpre[(row0 + r)*C3 + a_cb]);
        }
        #pragma unroll
        for (int pq = 0; pq < 4; ++pq) {
            int k = pq*8 + b_k;
            cp16(&B[k*SB_STR + b_nb], &g_w4r[(size_t)k*CH + n0 + b_nb]);
        }
        CP_COMMIT();
    }

    int buf = 0;
    for (int c = 0; c < NC; ++c) {
        if (c + 1 < NC) {
            int kk = (c+1)*GM_KC;
            float* A = bufA + (buf^1)*A_BUF;
            float* B = bufB + (buf^1)*B_BUF;
            #pragma unroll
            for (int pq = 0; pq < 8; ++pq) {
                int r = pq*16 + a_row;
                cp16(&A[r*SA_STR + a_cb], &g_fpre[(row0 + r)*C3 + kk + a_cb]);
            }
            #pragma unroll
            for (int pq = 0; pq < 4; ++pq) {
                int k = pq*8 + b_k;
                cp16(&B[k*SB_STR + b_nb], &g_w4r[(size_t)(kk + k)*CH + n0 + b_nb]);
            }
            CP_COMMIT();
            CP_WAIT(1);
        } else {
            CP_WAIT(0);
        }
        __syncthreads();

        float* A = bufA + buf*A_BUF;
        float* B = bufB + buf*B_BUF;
        int kk = c*GM_KC;
        #pragma unroll
        for (int ks = 0; ks < 4; ++ks) {
            int kb = ks*8;
            int ka = kk + kb + tig;
            float sc0 = sS[ka],   sh0 = sS[C3 + ka];
            float sc4 = sS[ka+4], sh4 = sS[C3 + ka + 4];
            uint32_t af[2][4];
            #pragma unroll
            for (int m = 0; m < 2; ++m) {
                int mr = w*32 + m*16;
                af[m][0] = cvt_tf32(fmaxf(A[(mr+g)*SA_STR   + kb + tig]*sc0 + sh0, 0.f));
                af[m][1] = cvt_tf32(fmaxf(A[(mr+g+8)*SA_STR + kb + tig]*sc0 + sh0, 0.f));
                af[m][2] = cvt_tf32(fmaxf(A[(mr+g)*SA_STR   + kb + tig + 4]*sc4 + sh4, 0.f));
                af[m][3] = cvt_tf32(fmaxf(A[(mr+g+8)*SA_STR + kb + tig + 4]*sc4 + sh4, 0.f));
            }
            uint32_t bf[8][2];
            #pragma unroll
            for (int n = 0; n < 8; ++n) {
                bf[n][0] = __float_as_uint(B[(kb+tig)*SB_STR   + n*8 + g]);
                bf[n][1] = __float_as_uint(B[(kb+tig+4)*SB_STR + n*8 + g]);
            }
            #pragma unroll
            for (int m = 0; m < 2; ++m)
                #pragma unroll
                for (int n = 0; n < 8; ++n) MMA_TF32(acc[m][n], af[m], bf[n]);
        }
        __syncthreads();
        buf ^= 1;
    }

    // fused maxpool epilogue: atomicMax on order-preserving keys
    #pragma unroll
    for (int m = 0; m < 2; ++m) {
        size_t rA = row0 + w*32 + m*16 + g;
        size_t rB = rA + 8;
        size_t pA = rA / KNBR, pB = rB / KNBR;
        #pragma unroll
        for (int n = 0; n < 8; ++n) {
            int col = n0 + n*8 + 2*tig;
            atomicMax(&keys[pA*CH + col],     fenc(acc[m][n][0]));
            atomicMax(&keys[pA*CH + col + 1], fenc(acc[m][n][1]));
            atomicMax(&keys[pB*CH + col],     fenc(acc[m][n][2]));
            atomicMax(&keys[pB*CH + col + 1], fenc(acc[m][n][3]));
        }
    }
}

// ---------------------------------------------------------------------------
// decode keys in place + add b4
// ---------------------------------------------------------------------------
__global__ void decode_kernel(float* __restrict__ out, const float* __restrict__ b4) {
    int i = blockIdx.x*256 + threadIdx.x;
    if (i < NPTS*CH) {
        int c = i % CH;
        unsigned k = ((const unsigned*)(out + (size_t)BB*NN*3))[i];
        out[(size_t)BB*NN*3 + i] = fdec(k) + b4[c];
    }
}

__global__ void copy_xyz_kernel(const float* __restrict__ xyz,
                                float* __restrict__ out) {
    int i = blockIdx.x*256 + threadIdx.x;
    if (i < BB*NN*3) out[i] = xyz[i];
}

extern "C" void kernel_launch(void* const* d_in, const int* in_sizes, int n_in,
                              void* d_out, int out_size) {
    (void)in_sizes; (void)n_in; (void)out_size;
    const float* xyz = (const float*)d_in[0];
    const float* W1  = (const float*)d_in[1];
    const float* b1  = (const float*)d_in[2];
    const float* g1  = (const float*)d_in[3];
    const float* be1 = (const float*)d_in[4];
    const float* W2  = (const float*)d_in[5];
    const float* b2  = (const float*)d_in[6];
    const float* W3  = (const float*)d_in[7];
    const float* b3  = (const float*)d_in[8];
    const float* g3  = (const float*)d_in[9];
    const float* be3 = (const float*)d_in[10];
    const float* W4  = (const float*)d_in[11];
    const float* b4  = (const float*)d_in[12];
    float* out = (float*)d_out;
    unsigned* keys = (unsigned*)(out + (size_t)BB*NN*3);

    static int smem_set = 0;
    if (!smem_set) {
        cudaFuncSetAttribute(gemm3_kernel, cudaFuncAttributeMaxDynamicSharedMemorySize,
                             (2*A_BUF + 2*B_BUF) * 4);
        cudaFuncSetAttribute(gemm_final_kernel, cudaFuncAttributeMaxDynamicSharedMemorySize,
                             (2*A_BUF + 2*B_BUF + 2*C3) * 4);
        smem_set = 1;
    }

    knn_kernel<<<NPTS, 256>>>(xyz);
    stats1_kernel<<<STAT_BLOCKS, 128>>>(xyz, W1, b1);
    fin1_kernel<<<1, C1>>>(g1, be1);
    edge_kernel<<<NROWS/16, 256>>>(xyz, W1, b1);
    w3r_kernel<<<(C2*C3 + 255)/256, 256>>>(W3);
    w4r_kernel<<<(C3*CH + 255)/256, 256>>>(W4);
    {
        dim3 grid2(NROWS/GM_MT, C2/GM_NT);
        gemm2_kernel<<<grid2, 128>>>(W2, b2);
    }
    gmax_kernel<<<NPTS, C2>>>();
    {
        dim3 gridFA(NPTS/GM_MT, C3/GM_NT);
        gemmFA_kernel<<<gridFA, 128>>>(W3, b3);
    }
    {
        dim3 grid3(NROWS/GM_MT, C3/GM_NT);
        gemm3_kernel<<<grid3, 128, (2*A_BUF + 2*B_BUF)*4>>>();
    }
    stats3_kernel<<<STAT_BLOCKS, 128>>>();
    fin3_kernel<<<1, C3>>>(g3, be3);
    initkeys_kernel<<<(NPTS*CH + 255)/256, 256>>>(keys);
    {
        dim3 grid4(NROWS/GM_MT, CH/GM_NT);
        gemm_final_kernel<<<grid4, 128, (2*A_BUF + 2*B_BUF + 2*C3)*4>>>(keys);
    }
    decode_kernel<<<(NPTS*CH + 255)/256, 256>>>(out, b4);
    copy_xyz_kernel<<<(BB*NN*3 + 255)/256, 256>>>(xyz, out);
}

// round 8
// speedup vs baseline: 5.3328x; 1.0198x over previous
#include <cuda_runtime.h>
#include <math.h>
#include <float.h>
#include <stdint.h>

// Problem constants
#define BB 2
#define NN 4096
#define KNBR 20
#define NPTS (BB*NN)            // 8192
#define NROWS (NPTS*KNBR)       // 163840
#define C1 128
#define C2 256
#define C3 512
#define CH 384
#define BN_EPS 1e-5f
#define STAT_BLOCKS 1024
#define ROWS_PER_STAT (NROWS/STAT_BLOCKS) // 160

__device__ __forceinline__ uint32_t cvt_tf32(float f) {
    uint32_t r; asm("cvt.rna.tf32.f32 %0, %1;" : "=r"(r) : "f"(f)); return r;
}
__device__ __forceinline__ void cp16(float* dst, const float* src) {
    uint32_t s = (uint32_t)__cvta_generic_to_shared(dst);
    asm volatile("cp.async.cg.shared.global [%0], [%1], 16;" :: "r"(s), "l"(src));
}
#define CP_COMMIT() asm volatile("cp.async.commit_group;" ::: "memory")
#define CP_WAIT(n)  asm volatile("cp.async.wait_group %0;" :: "n"(n) : "memory")

// order-preserving float<->uint for atomicMax
__device__ __forceinline__ unsigned fenc(float f) {
    int b = __float_as_int(f);
    return (b < 0) ? ~((unsigned)b) : (((unsigned)b) | 0x80000000u);
}
__device__ __forceinline__ float fdec(unsigned k) {
    return (k & 0x80000000u) ? __int_as_float((int)(k ^ 0x80000000u))
                             : __int_as_float((int)(~k));
}

// ---------------- scratch (static device globals) ----------------
__device__ int   g_idx[NROWS];
__device__ float g_part1[STAT_BLOCKS*2*C1];
__device__ float g_ss1[2*C1];
__device__ float g_A[(size_t)NROWS*C1];      // tf32-rounded
__device__ float g_H2[(size_t)NROWS*C2];     // tf32-rounded
__device__ float g_gmax[(size_t)NPTS*C2];
__device__ float g_fA[(size_t)NPTS*C3];
__device__ float g_fpre[(size_t)NROWS*C3];   // 335 MB (raw fp32)
__device__ float g_p3[(size_t)(NROWS/128)*2*C3];   // per-row-tile BN3 partials
__device__ float g_ss3[2*C3];
__device__ float g_w3r[C2*C3];               // rounded W3[256:512]
__device__ float g_w4r[C3*CH];               // rounded W4

// ---------------------------------------------------------------------------
// K1: KNN (unchanged — passing)
// ---------------------------------------------------------------------------
__global__ void knn_kernel(const float* __restrict__ xyz) {
    __shared__ float sd[NN];
    __shared__ float rv[256];
    __shared__ int   ri[256];
    int p = blockIdx.x;
    int b = p >> 12, n = p & (NN-1);
    int t = threadIdx.x;
    const float* base = xyz + (size_t)b*NN*3;
    float cx = base[n*3+0], cy = base[n*3+1], cz = base[n*3+2];
    float pp = cx*cx + cy*cy + cz*cz;
    for (int m = t; m < NN; m += 256) {
        float qx = base[m*3+0], qy = base[m*3+1], qz = base[m*3+2];
        float qq = qx*qx + qy*qy + qz*qz;
        float pq = cx*qx + cy*qy + cz*qz;
        sd[m] = pp + qq - 2.f*pq;
    }
    __syncthreads();
    for (int round = 0; round < KNBR; ++round) {
        float bv = FLT_MAX; int bi = NN;
        for (int m = t; m < NN; m += 256) {
            float v = sd[m];
            if (v < bv) { bv = v; bi = m; }
        }
        rv[t] = bv; ri[t] = bi;
        __syncthreads();
        #pragma unroll
        for (int s = 128; s > 0; s >>= 1) {
            if (t < s) {
                float ov = rv[t+s]; int oi = ri[t+s];
                if (ov < rv[t] || (ov == rv[t] && oi < ri[t])) { rv[t] = ov; ri[t] = oi; }
            }
            __syncthreads();
        }
        if (t == 0) {
            g_idx[p*KNBR + round] = ri[0];
            sd[ri[0]] = FLT_MAX;
        }
        __syncthreads();
    }
}

// ---------------------------------------------------------------------------
// BN1 stats (unchanged)
// ---------------------------------------------------------------------------
__global__ void stats1_kernel(const float* __restrict__ xyz,
                              const float* __restrict__ W1,
                              const float* __restrict__ b1) {
    __shared__ float se[ROWS_PER_STAT*6];
    int blk = blockIdx.x, t = threadIdx.x;
    int row0 = blk * ROWS_PER_STAT;
    for (int r = t; r < ROWS_PER_STAT; r += 128) {
        int gr = row0 + r;
        int p  = gr / KNBR;
        int b  = p >> 12, n = p & (NN-1);
        int id = g_idx[gr];
        const float* cb = xyz + ((size_t)b*NN + n)*3;
        const float* nb = xyz + ((size_t)b*NN + id)*3;
        se[r*6+0] = nb[0]-cb[0];
        se[r*6+1] = nb[1]-cb[1];
        se[r*6+2] = nb[2]-cb[2];
        se[r*6+3] = cb[0]; se[r*6+4] = cb[1]; se[r*6+5] = cb[2];
    }
    __syncthreads();
    float w0 = W1[0*C1+t], w1 = W1[1*C1+t], w2 = W1[2*C1+t],
          w3 = W1[3*C1+t], w4 = W1[4*C1+t], w5 = W1[5*C1+t], bb = b1[t];
    float s = 0.f, q = 0.f;
    for (int r = 0; r < ROWS_PER_STAT; ++r) {
        float h = bb + se[r*6+0]*w0 + se[r*6+1]*w1 + se[r*6+2]*w2
                     + se[r*6+3]*w3 + se[r*6+4]*w4 + se[r*6+5]*w5;
        s += h; q += h*h;
    }
    g_part1[blk*(2*C1) + t]      = s;
    g_part1[blk*(2*C1) + C1 + t] = q;
}

__global__ void fin1_kernel(const float* __restrict__ g1,
                            const float* __restrict__ be1) {
    int c = threadIdx.x;
    float s = 0.f, q = 0.f;
    for (int i = 0; i < STAT_BLOCKS; ++i) {
        s += g_part1[i*(2*C1)+c];
        q += g_part1[i*(2*C1)+C1+c];
    }
    float mu  = s / (float)NROWS;
    float var = q / (float)NROWS - mu*mu;
    float sc  = g1[c] * rsqrtf(var + BN_EPS);
    g_ss1[c]     = sc;
    g_ss1[C1+c]  = be1[c] - mu*sc;
}

// ---------------------------------------------------------------------------
// edge16 (unchanged from R7)
// ---------------------------------------------------------------------------
__global__ __launch_bounds__(256) void edge_kernel(
    const float* __restrict__ xyz,
    const float* __restrict__ W1, const float* __restrict__ b1) {
    __shared__ float sE[16*6];
    int row0 = blockIdx.x * 16, t = threadIdx.x;
    if (t < 96) {
        int r = t / 6, d = t - r*6;
        int row = row0 + r;
        int p = row / KNBR;
        int b = p >> 12, n = p & (NN-1);
        float v;
        if (d < 3) {
            int id = g_idx[row];
            v = xyz[((size_t)b*NN + id)*3 + d] - xyz[((size_t)b*NN + n)*3 + d];
        } else {
            v = xyz[((size_t)b*NN + n)*3 + (d-3)];
        }
        sE[r*6 + d] = v;
    }
    __syncthreads();
    int c = t & (C1-1), h = t >> 7;
    float w0 = W1[0*C1+c], w1 = W1[1*C1+c], w2 = W1[2*C1+c],
          w3 = W1[3*C1+c], w4 = W1[4*C1+c], w5 = W1[5*C1+c];
    float bb = b1[c], sc = g_ss1[c], sh = g_ss1[C1+c];
    #pragma unroll
    for (int rr = 0; rr < 8; ++rr) {
        int r = h*8 + rr;
        float hv = bb + sE[r*6+0]*w0 + sE[r*6+1]*w1 + sE[r*6+2]*w2
                      + sE[r*6+3]*w3 + sE[r*6+4]*w4 + sE[r*6+5]*w5;
        hv = fmaxf(hv*sc + sh, 0.f);
        g_A[(size_t)(row0 + r)*C1 + c] = __uint_as_float(cvt_tf32(hv));
    }
}

// ---------------------------------------------------------------------------
// weight prep
// ---------------------------------------------------------------------------
__global__ void w3r_kernel(const float* __restrict__ W3) {
    int i = blockIdx.x*256 + threadIdx.x;
    if (i < C2*C3) g_w3r[i] = __uint_as_float(cvt_tf32(W3[(size_t)C2*C3 + i]));
}
__global__ void w4r_kernel(const float* __restrict__ W4) {
    int i = blockIdx.x*256 + threadIdx.x;
    if (i < C3*CH) g_w4r[i] = __uint_as_float(cvt_tf32(W4[i]));
}

// ===========================================================================
// mma tile config: CTA 128x64, 4 warps, K-chunk 32.
// GRID CONVENTION (all GEMMs): blockIdx.x = col-tile (fast), blockIdx.y =
// row-tile (slow) — consecutive CTAs share one A tile, A streams DRAM once.
// ===========================================================================
#define GM_MT 128
#define GM_NT 64
#define GM_KC 32
#define SA_STR 36
#define SB_STR 72
#define A_BUF (GM_MT*SA_STR)   // 4608 floats
#define B_BUF (GM_KC*SB_STR)   // 2304 floats

#define MMA_TF32(acc, af, bf) \
    asm volatile( \
        "mma.sync.aligned.m16n8k8.row.col.f32.tf32.tf32.f32 " \
        "{%0,%1,%2,%3}, {%4,%5,%6,%7}, {%8,%9}, {%0,%1,%2,%3};" \
        : "+f"((acc)[0]), "+f"((acc)[1]), "+f"((acc)[2]), "+f"((acc)[3]) \
        : "r"((af)[0]), "r"((af)[1]), "r"((af)[2]), "r"((af)[3]), \
          "r"((bf)[0]), "r"((bf)[1]))

// ---------------------------------------------------------------------------
// gemm2: H2 = A @ W2 + b2, stored tf32-rounded
// ---------------------------------------------------------------------------
__global__ __launch_bounds__(128) void gemm2_kernel(
    const float* __restrict__ W2, const float* __restrict__ b2) {
    __shared__ __align__(16) float sA[GM_MT*SA_STR];
    __shared__ __align__(16) float sB[GM_KC*SB_STR];
    int t = threadIdx.x;
    int w = t >> 5, lane = t & 31;
    int g = lane >> 2, tig = lane & 3;
    size_t row0 = (size_t)blockIdx.y * GM_MT;
    int n0 = blockIdx.x * GM_NT;

    float acc[2][8][4] = {};
    int a_row = t >> 3, a_cb = (t & 7) * 4;
    int b_k = t >> 4, b_nb = (t & 15) * 4;

    for (int kk = 0; kk < C1; kk += GM_KC) {
        #pragma unroll
        for (int pq = 0; pq < 8; ++pq) {
            int r = pq*16 + a_row;
            float4 v = *(const float4*)&g_A[(row0 + r)*C1 + kk + a_cb];
            *(float4*)&sA[r*SA_STR + a_cb] = v;
        }
        #pragma unroll
        for (int pq = 0; pq < 4; ++pq) {
            int k = pq*8 + b_k;
            float4 v = *(const float4*)&W2[(size_t)(kk + k)*C2 + n0 + b_nb];
            uint4 o;
            o.x = cvt_tf32(v.x); o.y = cvt_tf32(v.y);
            o.z = cvt_tf32(v.z); o.w = cvt_tf32(v.w);
            *(uint4*)&sB[k*SB_STR + b_nb] = o;
        }
        __syncthreads();
        #pragma unroll
        for (int ks = 0; ks < 4; ++ks) {
            int kb = ks*8;
            uint32_t af[2][4];
            #pragma unroll
            for (int m = 0; m < 2; ++m) {
                int mr = w*32 + m*16;
                af[m][0] = __float_as_uint(sA[(mr+g)*SA_STR   + kb + tig]);
                af[m][1] = __float_as_uint(sA[(mr+g+8)*SA_STR + kb + tig]);
                af[m][2] = __float_as_uint(sA[(mr+g)*SA_STR   + kb + tig + 4]);
                af[m][3] = __float_as_uint(sA[(mr+g+8)*SA_STR + kb + tig + 4]);
            }
            uint32_t bf[8][2];
            #pragma unroll
            for (int n = 0; n < 8; ++n) {
                bf[n][0] = __float_as_uint(sB[(kb+tig)*SB_STR   + n*8 + g]);
                bf[n][1] = __float_as_uint(sB[(kb+tig+4)*SB_STR + n*8 + g]);
            }
            #pragma unroll
            for (int m = 0; m < 2; ++m)
                #pragma unroll
                for (int n = 0; n < 8; ++n) MMA_TF32(acc[m][n], af[m], bf[n]);
        }
        __syncthreads();
    }
    #pragma unroll
    for (int m = 0; m < 2; ++m) {
        size_t r0 = row0 + w*32 + m*16 + g;
        #pragma unroll
        for (int n = 0; n < 8; ++n) {
            int col = n0 + n*8 + 2*tig;
            float2 bb = *(const float2*)&b2[col];
            uint2 o0 = make_uint2(cvt_tf32(acc[m][n][0]+bb.x), cvt_tf32(acc[m][n][1]+bb.y));
            uint2 o1 = make_uint2(cvt_tf32(acc[m][n][2]+bb.x), cvt_tf32(acc[m][n][3]+bb.y));
            *(uint2*)&g_H2[r0*C2 + col]     = o0;
            *(uint2*)&g_H2[(r0+8)*C2 + col] = o1;
        }
    }
}

// ---------------------------------------------------------------------------
// gmax (unchanged)
// ---------------------------------------------------------------------------
__global__ void gmax_kernel() {
    int p = blockIdx.x, c = threadIdx.x;
    const float* src = g_H2 + (size_t)p*KNBR*C2 + c;
    float m = -FLT_MAX;
    #pragma unroll
    for (int r = 0; r < KNBR; ++r) m = fmaxf(m, src[(size_t)r*C2]);
    g_gmax[(size_t)p*C2 + c] = m;
}

// ---------------------------------------------------------------------------
// gemmFA: fA = gmax @ W3[0:256] + b3
// ---------------------------------------------------------------------------
__global__ __launch_bounds__(128) void gemmFA_kernel(
    const float* __restrict__ W3, const float* __restrict__ b3) {
    __shared__ __align__(16) float sA[GM_MT*SA_STR];
    __shared__ __align__(16) float sB[GM_KC*SB_STR];
    int t = threadIdx.x;
    int w = t >> 5, lane = t & 31;
    int g = lane >> 2, tig = lane & 3;
    size_t row0 = (size_t)blockIdx.y * GM_MT;
    int n0 = blockIdx.x * GM_NT;

    float acc[2][8][4] = {};
    int a_row = t >> 3, a_cb = (t & 7) * 4;
    int b_k = t >> 4, b_nb = (t & 15) * 4;

    for (int kk = 0; kk < C2; kk += GM_KC) {
        #pragma unroll
        for (int pq = 0; pq < 8; ++pq) {
            int r = pq*16 + a_row;
            float4 v = *(const float4*)&g_gmax[(row0 + r)*C2 + kk + a_cb];
            *(float4*)&sA[r*SA_STR + a_cb] = v;
        }
        #pragma unroll
        for (int pq = 0; pq < 4; ++pq) {
            int k = pq*8 + b_k;
            float4 v = *(const float4*)&W3[(size_t)(kk + k)*C3 + n0 + b_nb];
            uint4 o;
            o.x = cvt_tf32(v.x); o.y = cvt_tf32(v.y);
            o.z = cvt_tf32(v.z); o.w = cvt_tf32(v.w);
            *(uint4*)&sB[k*SB_STR + b_nb] = o;
        }
        __syncthreads();
        #pragma unroll
        for (int ks = 0; ks < 4; ++ks) {
            int kb = ks*8;
            uint32_t af[2][4];
            #pragma unroll
            for (int m = 0; m < 2; ++m) {
                int mr = w*32 + m*16;
                af[m][0] = __float_as_uint(sA[(mr+g)*SA_STR   + kb + tig]);
                af[m][1] = __float_as_uint(sA[(mr+g+8)*SA_STR + kb + tig]);
                af[m][2] = __float_as_uint(sA[(mr+g)*SA_STR   + kb + tig + 4]);
                af[m][3] = __float_as_uint(sA[(mr+g+8)*SA_STR + kb + tig + 4]);
            }
            uint32_t bf[8][2];
            #pragma unroll
            for (int n = 0; n < 8; ++n) {
                bf[n][0] = __float_as_uint(sB[(kb+tig)*SB_STR   + n*8 + g]);
                bf[n][1] = __float_as_uint(sB[(kb+tig+4)*SB_STR + n*8 + g]);
            }
            #pragma unroll
            for (int m = 0; m < 2; ++m)
                #pragma unroll
                for (int n = 0; n < 8; ++n) MMA_TF32(acc[m][n], af[m], bf[n]);
        }
        __syncthreads();
    }
    #pragma unroll
    for (int m = 0; m < 2; ++m) {
        size_t r0 = row0 + w*32 + m*16 + g;
        #pragma unroll
        for (int n = 0; n < 8; ++n) {
            int col = n0 + n*8 + 2*tig;
            float2 bb = *(const float2*)&b3[col];
            *(float2*)&g_fA[r0*C3 + col]     = make_float2(acc[m][n][0]+bb.x, acc[m][n][1]+bb.y);
            *(float2*)&g_fA[(r0+8)*C3 + col] = make_float2(acc[m][n][2]+bb.x, acc[m][n][3]+bb.y);
        }
    }
}

// ---------------------------------------------------------------------------
// gemm3 (cp.async pipelined + fused BN3-stat partials):
//   fpre = H2 @ W3r + fA[row/20];  g_p3[ytile] += per-column sum/sumsq
// ---------------------------------------------------------------------------
#define G3_SMEM ((2*A_BUF + 2*B_BUF + 4*64*2)*4)
__global__ __launch_bounds__(128) void gemm3_kernel() {
    extern __shared__ __align__(16) float dyn[];
    float* bufA = dyn;                        // 2 x A_BUF
    float* bufB = dyn + 2*A_BUF;              // 2 x B_BUF
    float* sstat = dyn + 2*A_BUF + 2*B_BUF;   // [4 warps][64 cols][2] = 512 floats
    int t = threadIdx.x;
    int w = t >> 5, lane = t & 31;
    int g = lane >> 2, tig = lane & 3;
    size_t row0 = (size_t)blockIdx.y * GM_MT;
    int n0 = blockIdx.x * GM_NT;

    float acc[2][8][4] = {};
    int a_row = t >> 3, a_cb = (t & 7) * 4;
    int b_k = t >> 4, b_nb = (t & 15) * 4;

    const int NC = C2/GM_KC;  // 8

    {
        float* A = bufA; float* B = bufB;
        #pragma unroll
        for (int pq = 0; pq < 8; ++pq) {
            int r = pq*16 + a_row;
            cp16(&A[r*SA_STR + a_cb], &g_H2[(row0 + r)*C2 + a_cb]);
        }
        #pragma unroll
        for (int pq = 0; pq < 4; ++pq) {
            int k = pq*8 + b_k;
            cp16(&B[k*SB_STR + b_nb], &g_w3r[(size_t)k*C3 + n0 + b_nb]);
        }
        CP_COMMIT();
    }

    int buf = 0;
    for (int c = 0; c < NC; ++c) {
        if (c + 1 < NC) {
            int kk = (c+1)*GM_KC;
            float* A = bufA + (buf^1)*A_BUF;
            float* B = bufB + (buf^1)*B_BUF;
            #pragma unroll
            for (int pq = 0; pq < 8; ++pq) {
                int r = pq*16 + a_row;
                cp16(&A[r*SA_STR + a_cb], &g_H2[(row0 + r)*C2 + kk + a_cb]);
            }
            #pragma unroll
            for (int pq = 0; pq < 4; ++pq) {
                int k = pq*8 + b_k;
                cp16(&B[k*SB_STR + b_nb], &g_w3r[(size_t)(kk + k)*C3 + n0 + b_nb]);
            }
            CP_COMMIT();
            CP_WAIT(1);
        } else {
            CP_WAIT(0);
        }
        __syncthreads();

        float* A = bufA + buf*A_BUF;
        float* B = bufB + buf*B_BUF;
        #pragma unroll
        for (int ks = 0; ks < 4; ++ks) {
            int kb = ks*8;
            uint32_t af[2][4];
            #pragma unroll
            for (int m = 0; m < 2; ++m) {
                int mr = w*32 + m*16;
                af[m][0] = __float_as_uint(A[(mr+g)*SA_STR   + kb + tig]);
                af[m][1] = __float_as_uint(A[(mr+g+8)*SA_STR + kb + tig]);
                af[m][2] = __float_as_uint(A[(mr+g)*SA_STR   + kb + tig + 4]);
                af[m][3] = __float_as_uint(A[(mr+g+8)*SA_STR + kb + tig + 4]);
            }
            uint32_t bf[8][2];
            #pragma unroll
            for (int n = 0; n < 8; ++n) {
                bf[n][0] = __float_as_uint(B[(kb+tig)*SB_STR   + n*8 + g]);
                bf[n][1] = __float_as_uint(B[(kb+tig+4)*SB_STR + n*8 + g]);
            }
            #pragma unroll
            for (int m = 0; m < 2; ++m)
                #pragma unroll
                for (int n = 0; n < 8; ++n) MMA_TF32(acc[m][n], af[m], bf[n]);
        }
        __syncthreads();
        buf ^= 1;
    }

    // epilogue: add fA, write fpre, accumulate column stats
    float sloc[8][2], qloc[8][2];
    #pragma unroll
    for (int n = 0; n < 8; ++n) { sloc[n][0]=0.f; sloc[n][1]=0.f; qloc[n][0]=0.f; qloc[n][1]=0.f; }
    #pragma unroll
    for (int m = 0; m < 2; ++m) {
        size_t rA = row0 + w*32 + m*16 + g;
        size_t rB = rA + 8;
        size_t pA = rA / KNBR, pB = rB / KNBR;
        #pragma unroll
        for (int n = 0; n < 8; ++n) {
            int col = n0 + n*8 + 2*tig;
            float2 fa = *(const float2*)&g_fA[pA*C3 + col];
            float2 fb = *(const float2*)&g_fA[pB*C3 + col];
            float v0 = acc[m][n][0]+fa.x, v1 = acc[m][n][1]+fa.y;
            float v2 = acc[m][n][2]+fb.x, v3 = acc[m][n][3]+fb.y;
            *(float2*)&g_fpre[rA*C3 + col] = make_float2(v0, v1);
            *(float2*)&g_fpre[rB*C3 + col] = make_float2(v2, v3);
            sloc[n][0] += v0 + v2;   qloc[n][0] += v0*v0 + v2*v2;
            sloc[n][1] += v1 + v3;   qloc[n][1] += v1*v1 + v3*v3;
        }
    }
    #pragma unroll
    for (int n = 0; n < 8; ++n)
        #pragma unroll
        for (int j = 0; j < 2; ++j) {
            float s = sloc[n][j], q = qloc[n][j];
            #pragma unroll
            for (int mk = 4; mk <= 16; mk <<= 1) {
                s += __shfl_xor_sync(0xffffffffu, s, mk);
                q += __shfl_xor_sync(0xffffffffu, q, mk);
            }
            if (g == 0) {
                int ci = n*8 + 2*tig + j;
                sstat[(w*64 + ci)*2 + 0] = s;
                sstat[(w*64 + ci)*2 + 1] = q;
            }
        }
    __syncthreads();
    if (t < 128) {
        int ci = t >> 1, which = t & 1;
        float v = sstat[(0*64+ci)*2+which] + sstat[(1*64+ci)*2+which]
                + sstat[(2*64+ci)*2+which] + sstat[(3*64+ci)*2+which];
        g_p3[(size_t)blockIdx.y*(2*C3) + (size_t)which*C3 + n0 + ci] = v;
    }
}

// ---------------------------------------------------------------------------
// fin3: reduce per-row-tile partials (1280) into BN3 scale/shift
// ---------------------------------------------------------------------------
__global__ void fin3_kernel(const float* __restrict__ g3,
                            const float* __restrict__ be3) {
    int c = threadIdx.x;   // 512
    float s = 0.f, q = 0.f;
    for (int i = 0; i < NROWS/128; ++i) {
        s += g_p3[(size_t)i*(2*C3) + c];
        q += g_p3[(size_t)i*(2*C3) + C3 + c];
    }
    float mu  = s / (float)NROWS;
    float var = q / (float)NROWS - mu*mu;
    float sc  = g3[c] * rsqrtf(var + BN_EPS);
    g_ss3[c]    = sc;
    g_ss3[C3+c] = be3[c] - mu*sc;
}

// ---------------------------------------------------------------------------
// init keys
// ---------------------------------------------------------------------------
__global__ void initkeys_kernel(unsigned* __restrict__ keys) {
    int i = blockIdx.x*256 + threadIdx.x;
    if (i < NPTS*CH) keys[i] = 0u;
}

// ---------------------------------------------------------------------------
// gemm_final (cp.async pipelined, bn3 at fragment load, fused atomic maxpool)
// ---------------------------------------------------------------------------
#define GF_SMEM ((2*A_BUF + 2*B_BUF + 2*C3)*4)
__global__ __launch_bounds__(128) void gemm_final_kernel(unsigned* __restrict__ keys) {
    extern __shared__ __align__(16) float dyn[];
    float* bufA = dyn;
    float* bufB = dyn + 2*A_BUF;
    float* sS   = dyn + 2*A_BUF + 2*B_BUF;
    int t = threadIdx.x;
    int w = t >> 5, lane = t & 31;
    int g = lane >> 2, tig = lane & 3;
    size_t row0 = (size_t)blockIdx.y * GM_MT;
    int n0 = blockIdx.x * GM_NT;

    float acc[2][8][4] = {};
    int a_row = t >> 3, a_cb = (t & 7) * 4;
    int b_k = t >> 4, b_nb = (t & 15) * 4;

    for (int i = t; i < 2*C3; i += 128) sS[i] = g_ss3[i];

    const int NC = C3/GM_KC;  // 16

    {
        float* A = bufA; float* B = bufB;
        #pragma unroll
        for (int pq = 0; pq < 8; ++pq) {
            int r = pq*16 + a_row;
            cp16(&A[r*SA_STR + a_cb], &g_fpre[(row0 + r)*C3 + a_cb]);
        }
        #pragma unroll
        for (int pq = 0; pq < 4; ++pq) {
            int k = pq*8 + b_k;
            cp16(&B[k*SB_STR + b_nb], &g_w4r[(size_t)k*CH + n0 + b_nb]);
        }
        CP_COMMIT();
    }

    int buf = 0;
    for (int c = 0; c < NC; ++c) {
        if (c + 1 < NC) {
            int kk = (c+1)*GM_KC;
            float* A = bufA + (buf^1)*A_BUF;
            float* B = bufB + (buf^1)*B_BUF;
            #pragma unroll
            for (int pq = 0; pq < 8; ++pq) {
                int r = pq*16 + a_row;
                cp16(&A[r*SA_STR + a_cb], &g_fpre[(row0 + r)*C3 + kk + a_cb]);
            }
            #pragma unroll
            for (int pq = 0; pq < 4; ++pq) {
                int k = pq*8 + b_k;
                cp16(&B[k*SB_STR + b_nb], &g_w4r[(size_t)(kk + k)*CH + n0 + b_nb]);
            }
            CP_COMMIT();
            CP_WAIT(1);
        } else {
            CP_WAIT(0);
        }
        __syncthreads();

        float* A = bufA + buf*A_BUF;
        float* B = bufB + buf*B_BUF;
        int kk = c*GM_KC;
        #pragma unroll
        for (int ks = 0; ks < 4; ++ks) {
            int kb = ks*8;
            int ka = kk + kb + tig;
            float sc0 = sS[ka],   sh0 = sS[C3 + ka];
            float sc4 = sS[ka+4], sh4 = sS[C3 + ka + 4];
            uint32_t af[2][4];
            #pragma unroll
            for (int m = 0; m < 2; ++m) {
                int mr = w*32 + m*16;
                af[m][0] = cvt_tf32(fmaxf(A[(mr+g)*SA_STR   + kb + tig]*sc0 + sh0, 0.f));
                af[m][1] = cvt_tf32(fmaxf(A[(mr+g+8)*SA_STR + kb + tig]*sc0 + sh0, 0.f));
                af[m][2] = cvt_tf32(fmaxf(A[(mr+g)*SA_STR   + kb + tig + 4]*sc4 + sh4, 0.f));
                af[m][3] = cvt_tf32(fmaxf(A[(mr+g+8)*SA_STR + kb + tig + 4]*sc4 + sh4, 0.f));
            }
            uint32_t bf[8][2];
            #pragma unroll
            for (int n = 0; n < 8; ++n) {
                bf[n][0] = __float_as_uint(B[(kb+tig)*SB_STR   + n*8 + g]);
                bf[n][1] = __float_as_uint(B[(kb+tig+4)*SB_STR + n*8 + g]);
            }
            #pragma unroll
            for (int m = 0; m < 2; ++m)
                #pragma unroll
                for (int n = 0; n < 8; ++n) MMA_TF32(acc[m][n], af[m], bf[n]);
        }
        __syncthreads();
        buf ^= 1;
    }

    #pragma unroll
    for (int m = 0; m < 2; ++m) {
        size_t rA = row0 + w*32 + m*16 + g;
        size_t rB = rA + 8;
        size_t pA = rA / KNBR, pB = rB / KNBR;
        #pragma unroll
        for (int n = 0; n < 8; ++n) {
            int col = n0 + n*8 + 2*tig;
            atomicMax(&keys[pA*CH + col],     fenc(acc[m][n][0]));
            atomicMax(&keys[pA*CH + col + 1], fenc(acc[m][n][1]));
            atomicMax(&keys[pB*CH + col],     fenc(acc[m][n][2]));
            atomicMax(&keys[pB*CH + col + 1], fenc(acc[m][n][3]));
        }
    }
}

// ---------------------------------------------------------------------------
// decode keys in place + add b4
// ---------------------------------------------------------------------------
__global__ void decode_kernel(float* __restrict__ out, const float* __restrict__ b4) {
    int i = blockIdx.x*256 + threadIdx.x;
    if (i < NPTS*CH) {
        int c = i % CH;
        unsigned k = ((const unsigned*)(out + (size_t)BB*NN*3))[i];
        out[(size_t)BB*NN*3 + i] = fdec(k) + b4[c];
    }
}

__global__ void copy_xyz_kernel(const float* __restrict__ xyz,
                                float* __restrict__ out) {
    int i = blockIdx.x*256 + threadIdx.x;
    if (i < BB*NN*3) out[i] = xyz[i];
}

extern "C" void kernel_launch(void* const* d_in, const int* in_sizes, int n_in,
                              void* d_out, int out_size) {
    (void)in_sizes; (void)n_in; (void)out_size;
    const float* xyz = (const float*)d_in[0];
    const float* W1  = (const float*)d_in[1];
    const float* b1  = (const float*)d_in[2];
    const float* g1  = (const float*)d_in[3];
    const float* be1 = (const float*)d_in[4];
    const float* W2  = (const float*)d_in[5];
    const float* b2  = (const float*)d_in[6];
    const float* W3  = (const float*)d_in[7];
    const float* b3  = (const float*)d_in[8];
    const float* g3  = (const float*)d_in[9];
    const float* be3 = (const float*)d_in[10];
    const float* W4  = (const float*)d_in[11];
    const float* b4  = (const float*)d_in[12];
    float* out = (float*)d_out;
    unsigned* keys = (unsigned*)(out + (size_t)BB*NN*3);

    static int smem_set = 0;
    if (!smem_set) {
        cudaFuncSetAttribute(gemm3_kernel, cudaFuncAttributeMaxDynamicSharedMemorySize, G3_SMEM);
        cudaFuncSetAttribute(gemm_final_kernel, cudaFuncAttributeMaxDynamicSharedMemorySize, GF_SMEM);
        smem_set = 1;
    }

    knn_kernel<<<NPTS, 256>>>(xyz);
    stats1_kernel<<<STAT_BLOCKS, 128>>>(xyz, W1, b1);
    fin1_kernel<<<1, C1>>>(g1, be1);
    edge_kernel<<<NROWS/16, 256>>>(xyz, W1, b1);
    w3r_kernel<<<(C2*C3 + 255)/256, 256>>>(W3);
    w4r_kernel<<<(C3*CH + 255)/256, 256>>>(W4);
    {
        dim3 grid2(C2/GM_NT, NROWS/GM_MT);   // (4, 1280) col-fast
        gemm2_kernel<<<grid2, 128>>>(W2, b2);
    }
    gmax_kernel<<<NPTS, C2>>>();
    {
        dim3 gridFA(C3/GM_NT, NPTS/GM_MT);   // (8, 64)
        gemmFA_kernel<<<gridFA, 128>>>(W3, b3);
    }
    {
        dim3 grid3(C3/GM_NT, NROWS/GM_MT);   // (8, 1280)
        gemm3_kernel<<<grid3, 128, G3_SMEM>>>();
    }
    fin3_kernel<<<1, C3>>>(g3, be3);
    initkeys_kernel<<<(NPTS*CH + 255)/256, 256>>>(keys);
    {
        dim3 grid4(CH/GM_NT, NROWS/GM_MT);   // (6, 1280)
        gemm_final_kernel<<<grid4, 128, GF_SMEM>>>(keys);
    }
    decode_kernel<<<(NPTS*CH + 255)/256, 256>>>(out, b4);
    copy_xyz_kernel<<<(BB*NN*3 + 255)/256, 256>>>(xyz, out);
}

// round 9
// speedup vs baseline: 5.8330x; 1.0938x over previous
#include <cuda_runtime.h>
#include <math.h>
#include <float.h>
#include <stdint.h>

// Problem constants
#define BB 2
#define NN 4096
#define KNBR 20
#define NPTS (BB*NN)            // 8192
#define NROWS (NPTS*KNBR)       // 163840
#define C1 128
#define C2 256
#define C3 512
#define CH 384
#define BN_EPS 1e-5f
#define STAT_BLOCKS 1024
#define ROWS_PER_STAT (NROWS/STAT_BLOCKS) // 160

__device__ __forceinline__ uint32_t cvt_tf32(float f) {
    uint32_t r; asm("cvt.rna.tf32.f32 %0, %1;" : "=r"(r) : "f"(f)); return r;
}
__device__ __forceinline__ void cp16(float* dst, const float* src) {
    uint32_t s = (uint32_t)__cvta_generic_to_shared(dst);
    asm volatile("cp.async.cg.shared.global [%0], [%1], 16;" :: "r"(s), "l"(src));
}
#define CP_COMMIT() asm volatile("cp.async.commit_group;" ::: "memory")
#define CP_WAIT(n)  asm volatile("cp.async.wait_group %0;" :: "n"(n) : "memory")

// order-preserving float<->uint for atomicMax
__device__ __forceinline__ unsigned fenc(float f) {
    int b = __float_as_int(f);
    return (b < 0) ? ~((unsigned)b) : (((unsigned)b) | 0x80000000u);
}
__device__ __forceinline__ float fdec(unsigned k) {
    return (k & 0x80000000u) ? __int_as_float((int)(k ^ 0x80000000u))
                             : __int_as_float((int)(~k));
}

// ---------------- scratch (static device globals) ----------------
__device__ int   g_idx[NROWS];
__device__ float g_part1[STAT_BLOCKS*2*C1];
__device__ float g_ss1[2*C1];
__device__ float g_A[(size_t)NROWS*C1];      // tf32-rounded
__device__ float g_H2[(size_t)NROWS*C2];     // tf32-rounded
__device__ float g_gmax[(size_t)NPTS*C2];
__device__ float g_fA[(size_t)NPTS*C3];
__device__ float g_fpre[(size_t)NROWS*C3];   // 335 MB (raw fp32)
__device__ float g_p3[(size_t)(NROWS/128)*2*C3];
__device__ float g_ss3[2*C3];
__device__ float g_w3r[C2*C3];               // rounded W3[256:512]
__device__ float g_w4r[C3*CH];               // rounded W4

// ---------------------------------------------------------------------------
// K1: KNN — persistent per-thread candidates. Full scan once; per round only
// the owner of the extracted element rescans its 16 slots. 2 syncs/round.
// ---------------------------------------------------------------------------
__global__ void knn_kernel(const float* __restrict__ xyz) {
    __shared__ float sd[NN];
    __shared__ float rv[8];
    __shared__ int   ri8[8];
    __shared__ int   swin;
    int p = blockIdx.x;
    int b = p >> 12, n = p & (NN-1);
    int t = threadIdx.x, lane = t & 31, w = t >> 5;
    const float* base = xyz + (size_t)b*NN*3;
    float cx = base[n*3+0], cy = base[n*3+1], cz = base[n*3+2];
    float pp = cx*cx + cy*cy + cz*cz;
    float bv = FLT_MAX; int bi = NN;
    for (int m = t; m < NN; m += 256) {
        float qx = base[m*3+0], qy = base[m*3+1], qz = base[m*3+2];
        float d2 = pp + (qx*qx + qy*qy + qz*qz) - 2.f*(cx*qx + cy*qy + cz*qz);
        sd[m] = d2;
        if (d2 < bv) { bv = d2; bi = m; }
    }
    __syncthreads();
    for (int round = 0; round < KNBR; ++round) {
        float rb = bv; int rx = bi;
        #pragma unroll
        for (int off = 16; off > 0; off >>= 1) {
            float ov = __shfl_down_sync(0xffffffffu, rb, off);
            int   oi = __shfl_down_sync(0xffffffffu, rx, off);
            if (ov < rb || (ov == rb && oi < rx)) { rb = ov; rx = oi; }
        }
        if (lane == 0) { rv[w] = rb; ri8[w] = rx; }
        __syncthreads();
        if (w == 0) {
            float v2 = (lane < 8) ? rv[lane] : FLT_MAX;
            int   i2 = (lane < 8) ? ri8[lane] : NN;
            #pragma unroll
            for (int off = 4; off > 0; off >>= 1) {
                float ov = __shfl_down_sync(0xffffffffu, v2, off);
                int   oi = __shfl_down_sync(0xffffffffu, i2, off);
                if (ov < v2 || (ov == v2 && oi < i2)) { v2 = ov; i2 = oi; }
            }
            if (lane == 0) {
                g_idx[p*KNBR + round] = i2;
                sd[i2] = FLT_MAX;
                swin = i2;
            }
        }
        __syncthreads();
        if (bi == swin) {   // only the owner rescans its 16 slots
            bv = FLT_MAX; bi = NN;
            for (int m = t; m < NN; m += 256) {
                float v = sd[m];
                if (v < bv) { bv = v; bi = m; }
            }
        }
    }
}

// ---------------------------------------------------------------------------
// BN1 stats (unchanged)
// ---------------------------------------------------------------------------
__global__ void stats1_kernel(const float* __restrict__ xyz,
                              const float* __restrict__ W1,
                              const float* __restrict__ b1) {
    __shared__ float se[ROWS_PER_STAT*6];
    int blk = blockIdx.x, t = threadIdx.x;
    int row0 = blk * ROWS_PER_STAT;
    for (int r = t; r < ROWS_PER_STAT; r += 128) {
        int gr = row0 + r;
        int p  = gr / KNBR;
        int b  = p >> 12, n = p & (NN-1);
        int id = g_idx[gr];
        const float* cb = xyz + ((size_t)b*NN + n)*3;
        const float* nb = xyz + ((size_t)b*NN + id)*3;
        se[r*6+0] = nb[0]-cb[0];
        se[r*6+1] = nb[1]-cb[1];
        se[r*6+2] = nb[2]-cb[2];
        se[r*6+3] = cb[0]; se[r*6+4] = cb[1]; se[r*6+5] = cb[2];
    }
    __syncthreads();
    float w0 = W1[0*C1+t], w1 = W1[1*C1+t], w2 = W1[2*C1+t],
          w3 = W1[3*C1+t], w4 = W1[4*C1+t], w5 = W1[5*C1+t], bb = b1[t];
    float s = 0.f, q = 0.f;
    for (int r = 0; r < ROWS_PER_STAT; ++r) {
        float h = bb + se[r*6+0]*w0 + se[r*6+1]*w1 + se[r*6+2]*w2
                     + se[r*6+3]*w3 + se[r*6+4]*w4 + se[r*6+5]*w5;
        s += h; q += h*h;
    }
    g_part1[blk*(2*C1) + t]      = s;
    g_part1[blk*(2*C1) + C1 + t] = q;
}

__global__ void fin1_kernel(const float* __restrict__ g1,
                            const float* __restrict__ be1) {
    int c = threadIdx.x;
    float s = 0.f, q = 0.f;
    for (int i = 0; i < STAT_BLOCKS; ++i) {
        s += g_part1[i*(2*C1)+c];
        q += g_part1[i*(2*C1)+C1+c];
    }
    float mu  = s / (float)NROWS;
    float var = q / (float)NROWS - mu*mu;
    float sc  = g1[c] * rsqrtf(var + BN_EPS);
    g_ss1[c]     = sc;
    g_ss1[C1+c]  = be1[c] - mu*sc;
}

// ---------------------------------------------------------------------------
// edge16 (unchanged)
// ---------------------------------------------------------------------------
__global__ __launch_bounds__(256) void edge_kernel(
    const float* __restrict__ xyz,
    const float* __restrict__ W1, const float* __restrict__ b1) {
    __shared__ float sE[16*6];
    int row0 = blockIdx.x * 16, t = threadIdx.x;
    if (t < 96) {
        int r = t / 6, d = t - r*6;
        int row = row0 + r;
        int p = row / KNBR;
        int b = p >> 12, n = p & (NN-1);
        float v;
        if (d < 3) {
            int id = g_idx[row];
            v = xyz[((size_t)b*NN + id)*3 + d] - xyz[((size_t)b*NN + n)*3 + d];
        } else {
            v = xyz[((size_t)b*NN + n)*3 + (d-3)];
        }
        sE[r*6 + d] = v;
    }
    __syncthreads();
    int c = t & (C1-1), h = t >> 7;
    float w0 = W1[0*C1+c], w1 = W1[1*C1+c], w2 = W1[2*C1+c],
          w3 = W1[3*C1+c], w4 = W1[4*C1+c], w5 = W1[5*C1+c];
    float bb = b1[c], sc = g_ss1[c], sh = g_ss1[C1+c];
    #pragma unroll
    for (int rr = 0; rr < 8; ++rr) {
        int r = h*8 + rr;
        float hv = bb + sE[r*6+0]*w0 + sE[r*6+1]*w1 + sE[r*6+2]*w2
                      + sE[r*6+3]*w3 + sE[r*6+4]*w4 + sE[r*6+5]*w5;
        hv = fmaxf(hv*sc + sh, 0.f);
        g_A[(size_t)(row0 + r)*C1 + c] = __uint_as_float(cvt_tf32(hv));
    }
}

// ---------------------------------------------------------------------------
// weight prep
// ---------------------------------------------------------------------------
__global__ void w3r_kernel(const float* __restrict__ W3) {
    int i = blockIdx.x*256 + threadIdx.x;
    if (i < C2*C3) g_w3r[i] = __uint_as_float(cvt_tf32(W3[(size_t)C2*C3 + i]));
}
__global__ void w4r_kernel(const float* __restrict__ W4) {
    int i = blockIdx.x*256 + threadIdx.x;
    if (i < C3*CH) g_w4r[i] = __uint_as_float(cvt_tf32(W4[i]));
}

// ===========================================================================
// mma tile configs. Small GEMMs: CTA 128x64 (warp 32x64).
// Big GEMMs (gemm3/gemm_final): CTA 256x64 (warp 64x64) — B-fragment LDS
// amortized over 2x the MMAs.
// ===========================================================================
#define GM_MT 128
#define GM_MT2 256
#define GM_NT 64
#define GM_KC 32
#define SA_STR 36
#define SB_STR 72
#define A_BUF  (GM_MT*SA_STR)    // 4608 floats
#define A_BUF2 (GM_MT2*SA_STR)   // 9216 floats
#define B_BUF  (GM_KC*SB_STR)    // 2304 floats

#define MMA_TF32(acc, af, bf) \
    asm volatile( \
        "mma.sync.aligned.m16n8k8.row.col.f32.tf32.tf32.f32 " \
        "{%0,%1,%2,%3}, {%4,%5,%6,%7}, {%8,%9}, {%0,%1,%2,%3};" \
        : "+f"((acc)[0]), "+f"((acc)[1]), "+f"((acc)[2]), "+f"((acc)[3]) \
        : "r"((af)[0]), "r"((af)[1]), "r"((af)[2]), "r"((af)[3]), \
          "r"((bf)[0]), "r"((bf)[1]))

// ---------------------------------------------------------------------------
// gemm2: H2 = A @ W2 + b2, stored tf32-rounded (unchanged)
// ---------------------------------------------------------------------------
__global__ __launch_bounds__(128) void gemm2_kernel(
    const float* __restrict__ W2, const float* __restrict__ b2) {
    __shared__ __align__(16) float sA[GM_MT*SA_STR];
    __shared__ __align__(16) float sB[GM_KC*SB_STR];
    int t = threadIdx.x;
    int w = t >> 5, lane = t & 31;
    int g = lane >> 2, tig = lane & 3;
    size_t row0 = (size_t)blockIdx.y * GM_MT;
    int n0 = blockIdx.x * GM_NT;

    float acc[2][8][4] = {};
    int a_row = t >> 3, a_cb = (t & 7) * 4;
    int b_k = t >> 4, b_nb = (t & 15) * 4;

    for (int kk = 0; kk < C1; kk += GM_KC) {
        #pragma unroll
        for (int pq = 0; pq < 8; ++pq) {
            int r = pq*16 + a_row;
            float4 v = *(const float4*)&g_A[(row0 + r)*C1 + kk + a_cb];
            *(float4*)&sA[r*SA_STR + a_cb] = v;
        }
        #pragma unroll
        for (int pq = 0; pq < 4; ++pq) {
            int k = pq*8 + b_k;
            float4 v = *(const float4*)&W2[(size_t)(kk + k)*C2 + n0 + b_nb];
            uint4 o;
            o.x = cvt_tf32(v.x); o.y = cvt_tf32(v.y);
            o.z = cvt_tf32(v.z); o.w = cvt_tf32(v.w);
            *(uint4*)&sB[k*SB_STR + b_nb] = o;
        }
        __syncthreads();
        #pragma unroll
        for (int ks = 0; ks < 4; ++ks) {
            int kb = ks*8;
            uint32_t af[2][4];
            #pragma unroll
            for (int m = 0; m < 2; ++m) {
                int mr = w*32 + m*16;
                af[m][0] = __float_as_uint(sA[(mr+g)*SA_STR   + kb + tig]);
                af[m][1] = __float_as_uint(sA[(mr+g+8)*SA_STR + kb + tig]);
                af[m][2] = __float_as_uint(sA[(mr+g)*SA_STR   + kb + tig + 4]);
                af[m][3] = __float_as_uint(sA[(mr+g+8)*SA_STR + kb + tig + 4]);
            }
            uint32_t bf[8][2];
            #pragma unroll
            for (int n = 0; n < 8; ++n) {
                bf[n][0] = __float_as_uint(sB[(kb+tig)*SB_STR   + n*8 + g]);
                bf[n][1] = __float_as_uint(sB[(kb+tig+4)*SB_STR + n*8 + g]);
            }
            #pragma unroll
            for (int m = 0; m < 2; ++m)
                #pragma unroll
                for (int n = 0; n < 8; ++n) MMA_TF32(acc[m][n], af[m], bf[n]);
        }
        __syncthreads();
    }
    #pragma unroll
    for (int m = 0; m < 2; ++m) {
        size_t r0 = row0 + w*32 + m*16 + g;
        #pragma unroll
        for (int n = 0; n < 8; ++n) {
            int col = n0 + n*8 + 2*tig;
            float2 bb = *(const float2*)&b2[col];
            uint2 o0 = make_uint2(cvt_tf32(acc[m][n][0]+bb.x), cvt_tf32(acc[m][n][1]+bb.y));
            uint2 o1 = make_uint2(cvt_tf32(acc[m][n][2]+bb.x), cvt_tf32(acc[m][n][3]+bb.y));
            *(uint2*)&g_H2[r0*C2 + col]     = o0;
            *(uint2*)&g_H2[(r0+8)*C2 + col] = o1;
        }
    }
}

// ---------------------------------------------------------------------------
// gmax (unchanged)
// ---------------------------------------------------------------------------
__global__ void gmax_kernel() {
    int p = blockIdx.x, c = threadIdx.x;
    const float* src = g_H2 + (size_t)p*KNBR*C2 + c;
    float m = -FLT_MAX;
    #pragma unroll
    for (int r = 0; r < KNBR; ++r) m = fmaxf(m, src[(size_t)r*C2]);
    g_gmax[(size_t)p*C2 + c] = m;
}

// ---------------------------------------------------------------------------
// gemmFA: fA = gmax @ W3[0:256] + b3 (unchanged)
// ---------------------------------------------------------------------------
__global__ __launch_bounds__(128) void gemmFA_kernel(
    const float* __restrict__ W3, const float* __restrict__ b3) {
    __shared__ __align__(16) float sA[GM_MT*SA_STR];
    __shared__ __align__(16) float sB[GM_KC*SB_STR];
    int t = threadIdx.x;
    int w = t >> 5, lane = t & 31;
    int g = lane >> 2, tig = lane & 3;
    size_t row0 = (size_t)blockIdx.y * GM_MT;
    int n0 = blockIdx.x * GM_NT;

    float acc[2][8][4] = {};
    int a_row = t >> 3, a_cb = (t & 7) * 4;
    int b_k = t >> 4, b_nb = (t & 15) * 4;

    for (int kk = 0; kk < C2; kk += GM_KC) {
        #pragma unroll
        for (int pq = 0; pq < 8; ++pq) {
            int r = pq*16 + a_row;
            float4 v = *(const float4*)&g_gmax[(row0 + r)*C2 + kk + a_cb];
            *(float4*)&sA[r*SA_STR + a_cb] = v;
        }
        #pragma unroll
        for (int pq = 0; pq < 4; ++pq) {
            int k = pq*8 + b_k;
            float4 v = *(const float4*)&W3[(size_t)(kk + k)*C3 + n0 + b_nb];
            uint4 o;
            o.x = cvt_tf32(v.x); o.y = cvt_tf32(v.y);
            o.z = cvt_tf32(v.z); o.w = cvt_tf32(v.w);
            *(uint4*)&sB[k*SB_STR + b_nb] = o;
        }
        __syncthreads();
        #pragma unroll
        for (int ks = 0; ks < 4; ++ks) {
            int kb = ks*8;
            uint32_t af[2][4];
            #pragma unroll
            for (int m = 0; m < 2; ++m) {
                int mr = w*32 + m*16;
                af[m][0] = __float_as_uint(sA[(mr+g)*SA_STR   + kb + tig]);
                af[m][1] = __float_as_uint(sA[(mr+g+8)*SA_STR + kb + tig]);
                af[m][2] = __float_as_uint(sA[(mr+g)*SA_STR   + kb + tig + 4]);
                af[m][3] = __float_as_uint(sA[(mr+g+8)*SA_STR + kb + tig + 4]);
            }
            uint32_t bf[8][2];
            #pragma unroll
            for (int n = 0; n < 8; ++n) {
                bf[n][0] = __float_as_uint(sB[(kb+tig)*SB_STR   + n*8 + g]);
                bf[n][1] = __float_as_uint(sB[(kb+tig+4)*SB_STR + n*8 + g]);
            }
            #pragma unroll
            for (int m = 0; m < 2; ++m)
                #pragma unroll
                for (int n = 0; n < 8; ++n) MMA_TF32(acc[m][n], af[m], bf[n]);
        }
        __syncthreads();
    }
    #pragma unroll
    for (int m = 0; m < 2; ++m) {
        size_t r0 = row0 + w*32 + m*16 + g;
        #pragma unroll
        for (int n = 0; n < 8; ++n) {
            int col = n0 + n*8 + 2*tig;
            float2 bb = *(const float2*)&b3[col];
            *(float2*)&g_fA[r0*C3 + col]     = make_float2(acc[m][n][0]+bb.x, acc[m][n][1]+bb.y);
            *(float2*)&g_fA[(r0+8)*C3 + col] = make_float2(acc[m][n][2]+bb.x, acc[m][n][3]+bb.y);
        }
    }
}

// ---------------------------------------------------------------------------
// gemm3 (cp.async, CTA 256x64, fused BN3-stat partials)
// ---------------------------------------------------------------------------
#define G3_SMEM ((2*A_BUF2 + 2*B_BUF + 4*64*2)*4)
__global__ __launch_bounds__(128) void gemm3_kernel() {
    extern __shared__ __align__(16) float dyn[];
    float* bufA = dyn;                         // 2 x A_BUF2
    float* bufB = dyn + 2*A_BUF2;              // 2 x B_BUF
    float* sstat = dyn + 2*A_BUF2 + 2*B_BUF;   // 512 floats
    int t = threadIdx.x;
    int w = t >> 5, lane = t & 31;
    int g = lane >> 2, tig = lane & 3;
    size_t row0 = (size_t)blockIdx.y * GM_MT2;
    int n0 = blockIdx.x * GM_NT;

    float acc[4][8][4] = {};
    int a_row = t >> 3, a_cb = (t & 7) * 4;
    int b_k = t >> 4, b_nb = (t & 15) * 4;

    const int NC = C2/GM_KC;  // 8

    {
        float* A = bufA; float* B = bufB;
        #pragma unroll
        for (int pq = 0; pq < 16; ++pq) {
            int r = pq*16 + a_row;
            cp16(&A[r*SA_STR + a_cb], &g_H2[(row0 + r)*C2 + a_cb]);
        }
        #pragma unroll
        for (int pq = 0; pq < 4; ++pq) {
            int k = pq*8 + b_k;
            cp16(&B[k*SB_STR + b_nb], &g_w3r[(size_t)k*C3 + n0 + b_nb]);
        }
        CP_COMMIT();
    }

    int buf = 0;
    for (int c = 0; c < NC; ++c) {
        if (c + 1 < NC) {
            int kk = (c+1)*GM_KC;
            float* A = bufA + (buf^1)*A_BUF2;
            float* B = bufB + (buf^1)*B_BUF;
            #pragma unroll
            for (int pq = 0; pq < 16; ++pq) {
                int r = pq*16 + a_row;
                cp16(&A[r*SA_STR + a_cb], &g_H2[(row0 + r)*C2 + kk + a_cb]);
            }
            #pragma unroll
            for (int pq = 0; pq < 4; ++pq) {
                int k = pq*8 + b_k;
                cp16(&B[k*SB_STR + b_nb], &g_w3r[(size_t)(kk + k)*C3 + n0 + b_nb]);
            }
            CP_COMMIT();
            CP_WAIT(1);
        } else {
            CP_WAIT(0);
        }
        __syncthreads();

        float* A = bufA + buf*A_BUF2;
        float* B = bufB + buf*B_BUF;
        #pragma unroll
        for (int ks = 0; ks < 4; ++ks) {
            int kb = ks*8;
            uint32_t bf[8][2];
            #pragma unroll
            for (int n = 0; n < 8; ++n) {
                bf[n][0] = __float_as_uint(B[(kb+tig)*SB_STR   + n*8 + g]);
                bf[n][1] = __float_as_uint(B[(kb+tig+4)*SB_STR + n*8 + g]);
            }
            #pragma unroll
            for (int m = 0; m < 4; ++m) {
                int mr = w*64 + m*16;
                uint32_t af[4];
                af[0] = __float_as_uint(A[(mr+g)*SA_STR   + kb + tig]);
                af[1] = __float_as_uint(A[(mr+g+8)*SA_STR + kb + tig]);
                af[2] = __float_as_uint(A[(mr+g)*SA_STR   + kb + tig + 4]);
                af[3] = __float_as_uint(A[(mr+g+8)*SA_STR + kb + tig + 4]);
                #pragma unroll
                for (int n = 0; n < 8; ++n) MMA_TF32(acc[m][n], af, bf[n]);
            }
        }
        __syncthreads();
        buf ^= 1;
    }

    // epilogue: add fA, write fpre, accumulate column stats
    float sloc[8][2], qloc[8][2];
    #pragma unroll
    for (int n = 0; n < 8; ++n) { sloc[n][0]=0.f; sloc[n][1]=0.f; qloc[n][0]=0.f; qloc[n][1]=0.f; }
    #pragma unroll
    for (int m = 0; m < 4; ++m) {
        size_t rA = row0 + w*64 + m*16 + g;
        size_t rB = rA + 8;
        size_t pA = rA / KNBR, pB = rB / KNBR;
        #pragma unroll
        for (int n = 0; n < 8; ++n) {
            int col = n0 + n*8 + 2*tig;
            float2 fa = *(const float2*)&g_fA[pA*C3 + col];
            float2 fb = *(const float2*)&g_fA[pB*C3 + col];
            float v0 = acc[m][n][0]+fa.x, v1 = acc[m][n][1]+fa.y;
            float v2 = acc[m][n][2]+fb.x, v3 = acc[m][n][3]+fb.y;
            *(float2*)&g_fpre[rA*C3 + col] = make_float2(v0, v1);
            *(float2*)&g_fpre[rB*C3 + col] = make_float2(v2, v3);
            sloc[n][0] += v0 + v2;   qloc[n][0] += v0*v0 + v2*v2;
            sloc[n][1] += v1 + v3;   qloc[n][1] += v1*v1 + v3*v3;
        }
    }
    #pragma unroll
    for (int n = 0; n < 8; ++n)
        #pragma unroll
        for (int j = 0; j < 2; ++j) {
            float s = sloc[n][j], q = qloc[n][j];
            #pragma unroll
            for (int mk = 4; mk <= 16; mk <<= 1) {
                s += __shfl_xor_sync(0xffffffffu, s, mk);
                q += __shfl_xor_sync(0xffffffffu, q, mk);
            }
            if (g == 0) {
                int ci = n*8 + 2*tig + j;
                sstat[(w*64 + ci)*2 + 0] = s;
                sstat[(w*64 + ci)*2 + 1] = q;
            }
        }
    __syncthreads();
    if (t < 128) {
        int ci = t >> 1, which = t & 1;
        float v = sstat[(0*64+ci)*2+which] + sstat[(1*64+ci)*2+which]
                + sstat[(2*64+ci)*2+which] + sstat[(3*64+ci)*2+which];
        g_p3[(size_t)blockIdx.y*(2*C3) + (size_t)which*C3 + n0 + ci] = v;
    }
}

// ---------------------------------------------------------------------------
// fin3: reduce per-row-tile partials (640) into BN3 scale/shift
// ---------------------------------------------------------------------------
__global__ void fin3_kernel(const float* __restrict__ g3,
                            const float* __restrict__ be3) {
    int c = threadIdx.x;   // 512
    float s = 0.f, q = 0.f;
    for (int i = 0; i < NROWS/GM_MT2; ++i) {
        s += g_p3[(size_t)i*(2*C3) + c];
        q += g_p3[(size_t)i*(2*C3) + C3 + c];
    }
    float mu  = s / (float)NROWS;
    float var = q / (float)NROWS - mu*mu;
    float sc  = g3[c] * rsqrtf(var + BN_EPS);
    g_ss3[c]    = sc;
    g_ss3[C3+c] = be3[c] - mu*sc;
}

// ---------------------------------------------------------------------------
// init keys
// ---------------------------------------------------------------------------
__global__ void initkeys_kernel(unsigned* __restrict__ keys) {
    int i = blockIdx.x*256 + threadIdx.x;
    if (i < NPTS*CH) keys[i] = 0u;
}

// ---------------------------------------------------------------------------
// gemm_final (cp.async, CTA 256x64, bn3 at fragment load, fused atomic maxpool)
// ---------------------------------------------------------------------------
#define GF_SMEM ((2*A_BUF2 + 2*B_BUF + 2*C3)*4)
__global__ __launch_bounds__(128) void gemm_final_kernel(unsigned* __restrict__ keys) {
    extern __shared__ __align__(16) float dyn[];
    float* bufA = dyn;
    float* bufB = dyn + 2*A_BUF2;
    float* sS   = dyn + 2*A_BUF2 + 2*B_BUF;
    int t = threadIdx.x;
    int w = t >> 5, lane = t & 31;
    int g = lane >> 2, tig = lane & 3;
    size_t row0 = (size_t)blockIdx.y * GM_MT2;
    int n0 = blockIdx.x * GM_NT;

    float acc[4][8][4] = {};
    int a_row = t >> 3, a_cb = (t & 7) * 4;
    int b_k = t >> 4, b_nb = (t & 15) * 4;

    for (int i = t; i < 2*C3; i += 128) sS[i] = g_ss3[i];

    const int NC = C3/GM_KC;  // 16

    {
        float* A = bufA; float* B = bufB;
        #pragma unroll
        for (int pq = 0; pq < 16; ++pq) {
            int r = pq*16 + a_row;
            cp16(&A[r*SA_STR + a_cb], &g_fpre[(row0 + r)*C3 + a_cb]);
        }
        #pragma unroll
        for (int pq = 0; pq < 4; ++pq) {
            int k = pq*8 + b_k;
            cp16(&B[k*SB_STR + b_nb], &g_w4r[(size_t)k*CH + n0 + b_nb]);
        }
        CP_COMMIT();
    }

    int buf = 0;
    for (int c = 0; c < NC; ++c) {
        if (c + 1 < NC) {
            int kk = (c+1)*GM_KC;
            float* A = bufA + (buf^1)*A_BUF2;
            float* B = bufB + (buf^1)*B_BUF;
            #pragma unroll
            for (int pq = 0; pq < 16; ++pq) {
                int r = pq*16 + a_row;
                cp16(&A[r*SA_STR + a_cb], &g_fpre[(row0 + r)*C3 + kk + a_cb]);
            }
            #pragma unroll
            for (int pq = 0; pq < 4; ++pq) {
                int k = pq*8 + b_k;
                cp16(&B[k*SB_STR + b_nb], &g_w4r[(size_t)(kk + k)*CH + n0 + b_nb]);
            }
            CP_COMMIT();
            CP_WAIT(1);
        } else {
            CP_WAIT(0);
        }
        __syncthreads();

        float* A = bufA + buf*A_BUF2;
        float* B = bufB + buf*B_BUF;
        int kk = c*GM_KC;
        #pragma unroll
        for (int ks = 0; ks < 4; ++ks) {
            int kb = ks*8;
            int ka = kk + kb + tig;
            float sc0 = sS[ka],   sh0 = sS[C3 + ka];
            float sc4 = sS[ka+4], sh4 = sS[C3 + ka + 4];
            uint32_t bf[8][2];
            #pragma unroll
            for (int n = 0; n < 8; ++n) {
                bf[n][0] = __float_as_uint(B[(kb+tig)*SB_STR   + n*8 + g]);
                bf[n][1] = __float_as_uint(B[(kb+tig+4)*SB_STR + n*8 + g]);
            }
            #pragma unroll
            for (int m = 0; m < 4; ++m) {
                int mr = w*64 + m*16;
                uint32_t af[4];
                af[0] = cvt_tf32(fmaxf(A[(mr+g)*SA_STR   + kb + tig]*sc0 + sh0, 0.f));
                af[1] = cvt_tf32(fmaxf(A[(mr+g+8)*SA_STR + kb + tig]*sc0 + sh0, 0.f));
                af[2] = cvt_tf32(fmaxf(A[(mr+g)*SA_STR   + kb + tig + 4]*sc4 + sh4, 0.f));
                af[3] = cvt_tf32(fmaxf(A[(mr+g+8)*SA_STR + kb + tig + 4]*sc4 + sh4, 0.f));
                #pragma unroll
                for (int n = 0; n < 8; ++n) MMA_TF32(acc[m][n], af, bf[n]);
            }
        }
        __syncthreads();
        buf ^= 1;
    }

    #pragma unroll
    for (int m = 0; m < 4; ++m) {
        size_t rA = row0 + w*64 + m*16 + g;
        size_t rB = rA + 8;
        size_t pA = rA / KNBR, pB = rB / KNBR;
        #pragma unroll
        for (int n = 0; n < 8; ++n) {
            int col = n0 + n*8 + 2*tig;
            atomicMax(&keys[pA*CH + col],     fenc(acc[m][n][0]));
            atomicMax(&keys[pA*CH + col + 1], fenc(acc[m][n][1]));
            atomicMax(&keys[pB*CH + col],     fenc(acc[m][n][2]));
            atomicMax(&keys[pB*CH + col + 1], fenc(acc[m][n][3]));
        }
    }
}

// ---------------------------------------------------------------------------
// decode keys in place + add b4
// ---------------------------------------------------------------------------
__global__ void decode_kernel(float* __restrict__ out, const float* __restrict__ b4) {
    int i = blockIdx.x*256 + threadIdx.x;
    if (i < NPTS*CH) {
        int c = i % CH;
        unsigned k = ((const unsigned*)(out + (size_t)BB*NN*3))[i];
        out[(size_t)BB*NN*3 + i] = fdec(k) + b4[c];
    }
}

__global__ void copy_xyz_kernel(const float* __restrict__ xyz,
                                float* __restrict__ out) {
    int i = blockIdx.x*256 + threadIdx.x;
    if (i < BB*NN*3) out[i] = xyz[i];
}

extern "C" void kernel_launch(void* const* d_in, const int* in_sizes, int n_in,
                              void* d_out, int out_size) {
    (void)in_sizes; (void)n_in; (void)out_size;
    const float* xyz = (const float*)d_in[0];
    const float* W1  = (const float*)d_in[1];
    const float* b1  = (const float*)d_in[2];
    const float* g1  = (const float*)d_in[3];
    const float* be1 = (const float*)d_in[4];
    const float* W2  = (const float*)d_in[5];
    const float* b2  = (const float*)d_in[6];
    const float* W3  = (const float*)d_in[7];
    const float* b3  = (const float*)d_in[8];
    const float* g3  = (const float*)d_in[9];
    const float* be3 = (const float*)d_in[10];
    const float* W4  = (const float*)d_in[11];
    const float* b4  = (const float*)d_in[12];
    float* out = (float*)d_out;
    unsigned* keys = (unsigned*)(out + (size_t)BB*NN*3);

    static int smem_set = 0;
    if (!smem_set) {
        cudaFuncSetAttribute(gemm3_kernel, cudaFuncAttributeMaxDynamicSharedMemorySize, G3_SMEM);
        cudaFuncSetAttribute(gemm_final_kernel, cudaFuncAttributeMaxDynamicSharedMemorySize, GF_SMEM);
        smem_set = 1;
    }

    knn_kernel<<<NPTS, 256>>>(xyz);
    stats1_kernel<<<STAT_BLOCKS, 128>>>(xyz, W1, b1);
    fin1_kernel<<<1, C1>>>(g1, be1);
    edge_kernel<<<NROWS/16, 256>>>(xyz, W1, b1);
    w3r_kernel<<<(C2*C3 + 255)/256, 256>>>(W3);
    w4r_kernel<<<(C3*CH + 255)/256, 256>>>(W4);
    {
        dim3 grid2(C2/GM_NT, NROWS/GM_MT);   // (4, 1280)
        gemm2_kernel<<<grid2, 128>>>(W2, b2);
    }
    gmax_kernel<<<NPTS, C2>>>();
    {
        dim3 gridFA(C3/GM_NT, NPTS/GM_MT);   // (8, 64)
        gemmFA_kernel<<<gridFA, 128>>>(W3, b3);
    }
    {
        dim3 grid3(C3/GM_NT, NROWS/GM_MT2);  // (8, 640)
        gemm3_kernel<<<grid3, 128, G3_SMEM>>>();
    }
    fin3_kernel<<<1, C3>>>(g3, be3);
    initkeys_kernel<<<(NPTS*CH + 255)/256, 256>>>(keys);
    {
        dim3 grid4(CH/GM_NT, NROWS/GM_MT2);  // (6, 640)
        gemm_final_kernel<<<grid4, 128, GF_SMEM>>>(keys);
    }
    decode_kernel<<<(NPTS*CH + 255)/256, 256>>>(out, b4);
    copy_xyz_kernel<<<(BB*NN*3 + 255)/256, 256>>>(xyz, out);
}

// round 10
// speedup vs baseline: 7.8832x; 1.3515x over previous
#include <cuda_runtime.h>
#include <cuda_fp16.h>
#include <math.h>
#include <float.h>
#include <stdint.h>

// Problem constants
#define BB 2
#define NN 4096
#define KNBR 20
#define NPTS (BB*NN)            // 8192
#define NROWS (NPTS*KNBR)       // 163840
#define C1 128
#define C2 256
#define C3 512
#define CH 384
#define BN_EPS 1e-5f
#define STAT_BLOCKS 1024
#define ROWS_PER_STAT (NROWS/STAT_BLOCKS) // 160

__device__ __forceinline__ void cp16(void* dst, const void* src) {
    uint32_t s = (uint32_t)__cvta_generic_to_shared(dst);
    asm volatile("cp.async.cg.shared.global [%0], [%1], 16;" :: "r"(s), "l"(src));
}
#define CP_COMMIT() asm volatile("cp.async.commit_group;" ::: "memory")
#define CP_WAIT(n)  asm volatile("cp.async.wait_group %0;" :: "n"(n) : "memory")

__device__ __forceinline__ uint32_t pack_h2(float a, float b) {
    __half2 h = __floats2half2_rn(a, b);
    return *(uint32_t*)&h;
}

// order-preserving float<->uint for atomicMax
__device__ __forceinline__ unsigned fenc(float f) {
    int b = __float_as_int(f);
    return (b < 0) ? ~((unsigned)b) : (((unsigned)b) | 0x80000000u);
}
__device__ __forceinline__ float fdec(unsigned k) {
    return (k & 0x80000000u) ? __int_as_float((int)(k ^ 0x80000000u))
                             : __int_as_float((int)(~k));
}

// ---------------- scratch (static device globals) ----------------
__device__ int      g_idx[NROWS];
__device__ float    g_part1[STAT_BLOCKS*2*C1];
__device__ float    g_ss1[2*C1];
__device__ __half   g_Ah[(size_t)NROWS*C1];      // 42 MB
__device__ __half   g_H2h[(size_t)NROWS*C2];     // 84 MB
__device__ __half   g_gmaxh[(size_t)NPTS*C2];
__device__ float    g_fA[(size_t)NPTS*C3];
__device__ __half   g_fpreh[(size_t)NROWS*C3];   // 168 MB
__device__ __half   g_af16[(size_t)NROWS*C3];    // 168 MB (bn3+relu applied)
__device__ float    g_p3[(size_t)(NROWS/128)*2*C3];
__device__ float    g_ss3[2*C3];
__device__ uint32_t g_w3h[128*C3];               // W3[256:512] packed [k/2][col]
__device__ uint32_t g_w4h[256*CH];               // W4 packed [k/2][col]

// ---------------------------------------------------------------------------
// K1: KNN (unchanged — passing, R9)
// ---------------------------------------------------------------------------
__global__ void knn_kernel(const float* __restrict__ xyz) {
    __shared__ float sd[NN];
    __shared__ float rv[8];
    __shared__ int   ri8[8];
    __shared__ int   swin;
    int p = blockIdx.x;
    int b = p >> 12, n = p & (NN-1);
    int t = threadIdx.x, lane = t & 31, w = t >> 5;
    const float* base = xyz + (size_t)b*NN*3;
    float cx = base[n*3+0], cy = base[n*3+1], cz = base[n*3+2];
    float pp = cx*cx + cy*cy + cz*cz;
    float bv = FLT_MAX; int bi = NN;
    for (int m = t; m < NN; m += 256) {
        float qx = base[m*3+0], qy = base[m*3+1], qz = base[m*3+2];
        float d2 = pp + (qx*qx + qy*qy + qz*qz) - 2.f*(cx*qx + cy*qy + cz*qz);
        sd[m] = d2;
        if (d2 < bv) { bv = d2; bi = m; }
    }
    __syncthreads();
    for (int round = 0; round < KNBR; ++round) {
        float rb = bv; int rx = bi;
        #pragma unroll
        for (int off = 16; off > 0; off >>= 1) {
            float ov = __shfl_down_sync(0xffffffffu, rb, off);
            int   oi = __shfl_down_sync(0xffffffffu, rx, off);
            if (ov < rb || (ov == rb && oi < rx)) { rb = ov; rx = oi; }
        }
        if (lane == 0) { rv[w] = rb; ri8[w] = rx; }
        __syncthreads();
        if (w == 0) {
            float v2 = (lane < 8) ? rv[lane] : FLT_MAX;
            int   i2 = (lane < 8) ? ri8[lane] : NN;
            #pragma unroll
            for (int off = 4; off > 0; off >>= 1) {
                float ov = __shfl_down_sync(0xffffffffu, v2, off);
                int   oi = __shfl_down_sync(0xffffffffu, i2, off);
                if (ov < v2 || (ov == v2 && oi < i2)) { v2 = ov; i2 = oi; }
            }
            if (lane == 0) {
                g_idx[p*KNBR + round] = i2;
                sd[i2] = FLT_MAX;
                swin = i2;
            }
        }
        __syncthreads();
        if (bi == swin) {
            bv = FLT_MAX; bi = NN;
            for (int m = t; m < NN; m += 256) {
                float v = sd[m];
                if (v < bv) { bv = v; bi = m; }
            }
        }
    }
}

// ---------------------------------------------------------------------------
// BN1 stats (unchanged)
// ---------------------------------------------------------------------------
__global__ void stats1_kernel(const float* __restrict__ xyz,
                              const float* __restrict__ W1,
                              const float* __restrict__ b1) {
    __shared__ float se[ROWS_PER_STAT*6];
    int blk = blockIdx.x, t = threadIdx.x;
    int row0 = blk * ROWS_PER_STAT;
    for (int r = t; r < ROWS_PER_STAT; r += 128) {
        int gr = row0 + r;
        int p  = gr / KNBR;
        int b  = p >> 12, n = p & (NN-1);
        int id = g_idx[gr];
        const float* cb = xyz + ((size_t)b*NN + n)*3;
        const float* nb = xyz + ((size_t)b*NN + id)*3;
        se[r*6+0] = nb[0]-cb[0];
        se[r*6+1] = nb[1]-cb[1];
        se[r*6+2] = nb[2]-cb[2];
        se[r*6+3] = cb[0]; se[r*6+4] = cb[1]; se[r*6+5] = cb[2];
    }
    __syncthreads();
    float w0 = W1[0*C1+t], w1 = W1[1*C1+t], w2 = W1[2*C1+t],
          w3 = W1[3*C1+t], w4 = W1[4*C1+t], w5 = W1[5*C1+t], bb = b1[t];
    float s = 0.f, q = 0.f;
    for (int r = 0; r < ROWS_PER_STAT; ++r) {
        float h = bb + se[r*6+0]*w0 + se[r*6+1]*w1 + se[r*6+2]*w2
                     + se[r*6+3]*w3 + se[r*6+4]*w4 + se[r*6+5]*w5;
        s += h; q += h*h;
    }
    g_part1[blk*(2*C1) + t]      = s;
    g_part1[blk*(2*C1) + C1 + t] = q;
}

__global__ void fin1_kernel(const float* __restrict__ g1,
                            const float* __restrict__ be1) {
    int c = threadIdx.x;
    float s = 0.f, q = 0.f;
    for (int i = 0; i < STAT_BLOCKS; ++i) {
        s += g_part1[i*(2*C1)+c];
        q += g_part1[i*(2*C1)+C1+c];
    }
    float mu  = s / (float)NROWS;
    float var = q / (float)NROWS - mu*mu;
    float sc  = g1[c] * rsqrtf(var + BN_EPS);
    g_ss1[c]     = sc;
    g_ss1[C1+c]  = be1[c] - mu*sc;
}

// ---------------------------------------------------------------------------
// edge16: writes fp16 A
// ---------------------------------------------------------------------------
__global__ __launch_bounds__(256) void edge_kernel(
    const float* __restrict__ xyz,
    const float* __restrict__ W1, const float* __restrict__ b1) {
    __shared__ float sE[16*6];
    int row0 = blockIdx.x * 16, t = threadIdx.x;
    if (t < 96) {
        int r = t / 6, d = t - r*6;
        int row = row0 + r;
        int p = row / KNBR;
        int b = p >> 12, n = p & (NN-1);
        float v;
        if (d < 3) {
            int id = g_idx[row];
            v = xyz[((size_t)b*NN + id)*3 + d] - xyz[((size_t)b*NN + n)*3 + d];
        } else {
            v = xyz[((size_t)b*NN + n)*3 + (d-3)];
        }
        sE[r*6 + d] = v;
    }
    __syncthreads();
    int c = t & (C1-1), h = t >> 7;
    float w0 = W1[0*C1+c], w1 = W1[1*C1+c], w2 = W1[2*C1+c],
          w3 = W1[3*C1+c], w4 = W1[4*C1+c], w5 = W1[5*C1+c];
    float bb = b1[c], sc = g_ss1[c], sh = g_ss1[C1+c];
    #pragma unroll
    for (int rr = 0; rr < 8; ++rr) {
        int r = h*8 + rr;
        float hv = bb + sE[r*6+0]*w0 + sE[r*6+1]*w1 + sE[r*6+2]*w2
                      + sE[r*6+3]*w3 + sE[r*6+4]*w4 + sE[r*6+5]*w5;
        hv = fmaxf(hv*sc + sh, 0.f);
        g_Ah[(size_t)(row0 + r)*C1 + c] = __float2half_rn(hv);
    }
}

// ---------------------------------------------------------------------------
// weight prep: half2-packed [k/2][col]
// ---------------------------------------------------------------------------
__global__ void w3h_kernel(const float* __restrict__ W3) {
    int i = blockIdx.x*256 + threadIdx.x;        // 128*512
    if (i < 128*C3) {
        int kp = i / C3, col = i - kp*C3;
        g_w3h[i] = pack_h2(W3[(size_t)(C2 + 2*kp)*C3 + col],
                           W3[(size_t)(C2 + 2*kp + 1)*C3 + col]);
    }
}
__global__ void w4h_kernel(const float* __restrict__ W4) {
    int i = blockIdx.x*256 + threadIdx.x;        // 256*384
    if (i < 256*CH) {
        int kp = i / CH, col = i - kp*CH;
        g_w4h[i] = pack_h2(W4[(size_t)(2*kp)*CH + col],
                           W4[(size_t)(2*kp + 1)*CH + col]);
    }
}

// ===========================================================================
// fp16 m16n8k16 tile configs.
// smem A: uint32 half2 [row][kpair], stride 20 (16 used) — conflict-free.
// smem B: uint32 half2 [kpair][col], stride 72 — conflict-free.
// ===========================================================================
#define GM_MT 128
#define GM_MT2 256
#define GM_NT 64
#define GM_KC 32
#define SAH 20
#define SBH 72
#define A_BUFH  (GM_MT*SAH)     // 2560 u32
#define A_BUFH2 (GM_MT2*SAH)    // 5120 u32
#define B_BUFH  (16*SBH)        // 1152 u32

#define MMA_F16(acc, af, bf) \
    asm volatile( \
        "mma.sync.aligned.m16n8k16.row.col.f32.f16.f16.f32 " \
        "{%0,%1,%2,%3}, {%4,%5,%6,%7}, {%8,%9}, {%0,%1,%2,%3};" \
        : "+f"((acc)[0]), "+f"((acc)[1]), "+f"((acc)[2]), "+f"((acc)[3]) \
        : "r"((af)[0]), "r"((af)[1]), "r"((af)[2]), "r"((af)[3]), \
          "r"((bf)[0]), "r"((bf)[1]))

// ---------------------------------------------------------------------------
// gemm2: H2 = A @ W2 + b2 (fp16 in, fp16 out). CTA 128x64.
// ---------------------------------------------------------------------------
__global__ __launch_bounds__(128) void gemm2_kernel(
    const float* __restrict__ W2, const float* __restrict__ b2) {
    __shared__ __align__(16) uint32_t sA[GM_MT*SAH];
    __shared__ __align__(16) uint32_t sB[16*SBH];
    int t = threadIdx.x;
    int w = t >> 5, lane = t & 31;
    int g = lane >> 2, tig = lane & 3;
    size_t row0 = (size_t)blockIdx.y * GM_MT;
    int n0 = blockIdx.x * GM_NT;

    float acc[2][8][4] = {};

    for (int kk = 0; kk < C1; kk += GM_KC) {
        #pragma unroll
        for (int pq = 0; pq < 4; ++pq) {
            int r = pq*32 + (t>>2), seg = t&3;
            uint4 v = *(const uint4*)(g_Ah + (row0 + r)*C1 + kk + seg*8);
            *(uint4*)&sA[r*SAH + seg*4] = v;
        }
        #pragma unroll
        for (int pq = 0; pq < 2; ++pq) {
            int kp = pq*8 + (t>>4), colb = (t&15)*4;
            const float* s0 = &W2[(size_t)(kk + 2*kp)*C2 + n0 + colb];
            float4 va = *(const float4*)s0;
            float4 vb = *(const float4*)(s0 + C2);
            uint4 o = make_uint4(pack_h2(va.x, vb.x), pack_h2(va.y, vb.y),
                                 pack_h2(va.z, vb.z), pack_h2(va.w, vb.w));
            *(uint4*)&sB[kp*SBH + colb] = o;
        }
        __syncthreads();
        #pragma unroll
        for (int ks = 0; ks < 2; ++ks) {
            int kb = ks*8;
            uint32_t bf[8][2];
            #pragma unroll
            for (int n = 0; n < 8; ++n) {
                bf[n][0] = sB[(kb+tig)*SBH   + n*8 + g];
                bf[n][1] = sB[(kb+tig+4)*SBH + n*8 + g];
            }
            #pragma unroll
            for (int m = 0; m < 2; ++m) {
                int mr = w*32 + m*16;
                uint32_t af[4];
                af[0] = sA[(mr+g)*SAH   + kb + tig];
                af[1] = sA[(mr+g+8)*SAH + kb + tig];
                af[2] = sA[(mr+g)*SAH   + kb + tig + 4];
                af[3] = sA[(mr+g+8)*SAH + kb + tig + 4];
                #pragma unroll
                for (int n = 0; n < 8; ++n) MMA_F16(acc[m][n], af, bf[n]);
            }
        }
        __syncthreads();
    }
    uint32_t* H2v = (uint32_t*)g_H2h;
    #pragma unroll
    for (int m = 0; m < 2; ++m) {
        size_t r0 = row0 + w*32 + m*16 + g;
        #pragma unroll
        for (int n = 0; n < 8; ++n) {
            int col = n0 + n*8 + 2*tig;
            float2 bb = *(const float2*)&b2[col];
            H2v[r0*(C2/2) + col/2]     = pack_h2(acc[m][n][0]+bb.x, acc[m][n][1]+bb.y);
            H2v[(r0+8)*(C2/2) + col/2] = pack_h2(acc[m][n][2]+bb.x, acc[m][n][3]+bb.y);
        }
    }
}

// ---------------------------------------------------------------------------
// gmax over fp16 pairs
// ---------------------------------------------------------------------------
__global__ void gmax_kernel() {
    int p = blockIdx.x, t = threadIdx.x;   // 128 threads
    const __half2* src = (const __half2*)g_H2h + (size_t)p*KNBR*(C2/2) + t;
    __half2 m = src[0];
    #pragma unroll
    for (int r = 1; r < KNBR; ++r) m = __hmax2(m, src[(size_t)r*(C2/2)]);
    ((__half2*)g_gmaxh)[(size_t)p*(C2/2) + t] = m;
}

// ---------------------------------------------------------------------------
// gemmFA: fA = gmax @ W3[0:256] + b3 (fp16 in, fp32 out). CTA 128x64.
// ---------------------------------------------------------------------------
__global__ __launch_bounds__(128) void gemmFA_kernel(
    const float* __restrict__ W3, const float* __restrict__ b3) {
    __shared__ __align__(16) uint32_t sA[GM_MT*SAH];
    __shared__ __align__(16) uint32_t sB[16*SBH];
    int t = threadIdx.x;
    int w = t >> 5, lane = t & 31;
    int g = lane >> 2, tig = lane & 3;
    size_t row0 = (size_t)blockIdx.y * GM_MT;
    int n0 = blockIdx.x * GM_NT;

    float acc[2][8][4] = {};

    for (int kk = 0; kk < C2; kk += GM_KC) {
        #pragma unroll
        for (int pq = 0; pq < 4; ++pq) {
            int r = pq*32 + (t>>2), seg = t&3;
            uint4 v = *(const uint4*)(g_gmaxh + (row0 + r)*C2 + kk + seg*8);
            *(uint4*)&sA[r*SAH + seg*4] = v;
        }
        #pragma unroll
        for (int pq = 0; pq < 2; ++pq) {
            int kp = pq*8 + (t>>4), colb = (t&15)*4;
            const float* s0 = &W3[(size_t)(kk + 2*kp)*C3 + n0 + colb];
            float4 va = *(const float4*)s0;
            float4 vb = *(const float4*)(s0 + C3);
            uint4 o = make_uint4(pack_h2(va.x, vb.x), pack_h2(va.y, vb.y),
                                 pack_h2(va.z, vb.z), pack_h2(va.w, vb.w));
            *(uint4*)&sB[kp*SBH + colb] = o;
        }
        __syncthreads();
        #pragma unroll
        for (int ks = 0; ks < 2; ++ks) {
            int kb = ks*8;
            uint32_t bf[8][2];
            #pragma unroll
            for (int n = 0; n < 8; ++n) {
                bf[n][0] = sB[(kb+tig)*SBH   + n*8 + g];
                bf[n][1] = sB[(kb+tig+4)*SBH + n*8 + g];
            }
            #pragma unroll
            for (int m = 0; m < 2; ++m) {
                int mr = w*32 + m*16;
                uint32_t af[4];
                af[0] = sA[(mr+g)*SAH   + kb + tig];
                af[1] = sA[(mr+g+8)*SAH + kb + tig];
                af[2] = sA[(mr+g)*SAH   + kb + tig + 4];
                af[3] = sA[(mr+g+8)*SAH + kb + tig + 4];
                #pragma unroll
                for (int n = 0; n < 8; ++n) MMA_F16(acc[m][n], af, bf[n]);
            }
        }
        __syncthreads();
    }
    #pragma unroll
    for (int m = 0; m < 2; ++m) {
        size_t r0 = row0 + w*32 + m*16 + g;
        #pragma unroll
        for (int n = 0; n < 8; ++n) {
            int col = n0 + n*8 + 2*tig;
            float2 bb = *(const float2*)&b3[col];
            *(float2*)&g_fA[r0*C3 + col]     = make_float2(acc[m][n][0]+bb.x, acc[m][n][1]+bb.y);
            *(float2*)&g_fA[(r0+8)*C3 + col] = make_float2(acc[m][n][2]+bb.x, acc[m][n][3]+bb.y);
        }
    }
}

// ---------------------------------------------------------------------------
// gemm3 (cp.async, CTA 256x64, fp16, fused BN3-stat partials)
//   fpre = H2 @ W3b + fA[row/20] -> g_fpreh (fp16); stats from fp32 pre-round
// ---------------------------------------------------------------------------
#define G3_SMEM ((2*A_BUFH2 + 2*B_BUFH + 512)*4)
__global__ __launch_bounds__(128) void gemm3_kernel() {
    extern __shared__ __align__(16) uint32_t dyn[];
    uint32_t* bufA = dyn;                          // 2 x A_BUFH2
    uint32_t* bufB = dyn + 2*A_BUFH2;              // 2 x B_BUFH
    float* sstat = (float*)(dyn + 2*A_BUFH2 + 2*B_BUFH);
    int t = threadIdx.x;
    int w = t >> 5, lane = t & 31;
    int g = lane >> 2, tig = lane & 3;
    size_t row0 = (size_t)blockIdx.y * GM_MT2;
    int n0 = blockIdx.x * GM_NT;

    float acc[4][8][4] = {};
    const int NC = C2/GM_KC;  // 8

    {
        uint32_t* A = bufA; uint32_t* B = bufB;
        #pragma unroll
        for (int pq = 0; pq < 8; ++pq) {
            int r = pq*32 + (t>>2), seg = t&3;
            cp16(&A[r*SAH + seg*4], g_H2h + (row0 + r)*C2 + seg*8);
        }
        {
            int kp = t>>3, s0 = t&7;
            cp16(&B[kp*SBH + s0*4],     &g_w3h[(size_t)kp*C3 + n0 + s0*4]);
            cp16(&B[kp*SBH + (s0+8)*4], &g_w3h[(size_t)kp*C3 + n0 + (s0+8)*4]);
        }
        CP_COMMIT();
    }

    int buf = 0;
    for (int c = 0; c < NC; ++c) {
        if (c + 1 < NC) {
            int kk = (c+1)*GM_KC;
            uint32_t* A = bufA + (buf^1)*A_BUFH2;
            uint32_t* B = bufB + (buf^1)*B_BUFH;
            #pragma unroll
            for (int pq = 0; pq < 8; ++pq) {
                int r = pq*32 + (t>>2), seg = t&3;
                cp16(&A[r*SAH + seg*4], g_H2h + (row0 + r)*C2 + kk + seg*8);
            }
            {
                int kp = t>>3, s0 = t&7;
                int kpg = (c+1)*16 + kp;
                cp16(&B[kp*SBH + s0*4],     &g_w3h[(size_t)kpg*C3 + n0 + s0*4]);
                cp16(&B[kp*SBH + (s0+8)*4], &g_w3h[(size_t)kpg*C3 + n0 + (s0+8)*4]);
            }
            CP_COMMIT();
            CP_WAIT(1);
        } else {
            CP_WAIT(0);
        }
        __syncthreads();

        uint32_t* A = bufA + buf*A_BUFH2;
        uint32_t* B = bufB + buf*B_BUFH;
        #pragma unroll
        for (int ks = 0; ks < 2; ++ks) {
            int kb = ks*8;
            uint32_t bf[8][2];
            #pragma unroll
            for (int n = 0; n < 8; ++n) {
                bf[n][0] = B[(kb+tig)*SBH   + n*8 + g];
                bf[n][1] = B[(kb+tig+4)*SBH + n*8 + g];
            }
            #pragma unroll
            for (int m = 0; m < 4; ++m) {
                int mr = w*64 + m*16;
                uint32_t af[4];
                af[0] = A[(mr+g)*SAH   + kb + tig];
                af[1] = A[(mr+g+8)*SAH + kb + tig];
                af[2] = A[(mr+g)*SAH   + kb + tig + 4];
                af[3] = A[(mr+g+8)*SAH + kb + tig + 4];
                #pragma unroll
                for (int n = 0; n < 8; ++n) MMA_F16(acc[m][n], af, bf[n]);
            }
        }
        __syncthreads();
        buf ^= 1;
    }

    // epilogue: add fA, write fp16 fpre, accumulate column stats (fp32)
    uint32_t* FPv = (uint32_t*)g_fpreh;
    float sloc[8][2], qloc[8][2];
    #pragma unroll
    for (int n = 0; n < 8; ++n) { sloc[n][0]=0.f; sloc[n][1]=0.f; qloc[n][0]=0.f; qloc[n][1]=0.f; }
    #pragma unroll
    for (int m = 0; m < 4; ++m) {
        size_t rA = row0 + w*64 + m*16 + g;
        size_t rB = rA + 8;
        size_t pA = rA / KNBR, pB = rB / KNBR;
        #pragma unroll
        for (int n = 0; n < 8; ++n) {
            int col = n0 + n*8 + 2*tig;
            float2 fa = *(const float2*)&g_fA[pA*C3 + col];
            float2 fb = *(const float2*)&g_fA[pB*C3 + col];
            float v0 = acc[m][n][0]+fa.x, v1 = acc[m][n][1]+fa.y;
            float v2 = acc[m][n][2]+fb.x, v3 = acc[m][n][3]+fb.y;
            FPv[rA*(C3/2) + col/2] = pack_h2(v0, v1);
            FPv[rB*(C3/2) + col/2] = pack_h2(v2, v3);
            sloc[n][0] += v0 + v2;   qloc[n][0] += v0*v0 + v2*v2;
            sloc[n][1] += v1 + v3;   qloc[n][1] += v1*v1 + v3*v3;
        }
    }
    #pragma unroll
    for (int n = 0; n < 8; ++n)
        #pragma unroll
        for (int j = 0; j < 2; ++j) {
            float s = sloc[n][j], q = qloc[n][j];
            #pragma unroll
            for (int mk = 4; mk <= 16; mk <<= 1) {
                s += __shfl_xor_sync(0xffffffffu, s, mk);
                q += __shfl_xor_sync(0xffffffffu, q, mk);
            }
            if (g == 0) {
                int ci = n*8 + 2*tig + j;
                sstat[(w*64 + ci)*2 + 0] = s;
                sstat[(w*64 + ci)*2 + 1] = q;
            }
        }
    __syncthreads();
    if (t < 128) {
        int ci = t >> 1, which = t & 1;
        float v = sstat[(0*64+ci)*2+which] + sstat[(1*64+ci)*2+which]
                + sstat[(2*64+ci)*2+which] + sstat[(3*64+ci)*2+which];
        g_p3[(size_t)blockIdx.y*(2*C3) + (size_t)which*C3 + n0 + ci] = v;
    }
}

// ---------------------------------------------------------------------------
// fin3: reduce per-row-tile partials (640) into BN3 scale/shift
// ---------------------------------------------------------------------------
__global__ void fin3_kernel(const float* __restrict__ g3,
                            const float* __restrict__ be3) {
    int c = threadIdx.x;   // 512
    float s = 0.f, q = 0.f;
    for (int i = 0; i < NROWS/GM_MT2; ++i) {
        s += g_p3[(size_t)i*(2*C3) + c];
        q += g_p3[(size_t)i*(2*C3) + C3 + c];
    }
    float mu  = s / (float)NROWS;
    float var = q / (float)NROWS - mu*mu;
    float sc  = g3[c] * rsqrtf(var + BN_EPS);
    g_ss3[c]    = sc;
    g_ss3[C3+c] = be3[c] - mu*sc;
}

// ---------------------------------------------------------------------------
// bnapply: g_af16 = fp16(relu(bn3(g_fpreh)))  — 1 uint4 (8 halves) per thread
// ---------------------------------------------------------------------------
__global__ __launch_bounds__(256) void bnapply_kernel() {
    __shared__ float sS[2*C3];
    int t = threadIdx.x;
    for (int i = t; i < 2*C3; i += 256) sS[i] = g_ss3[i];
    __syncthreads();
    size_t i = (size_t)blockIdx.x*256 + t;   // uint4 index; total NROWS*C3/8
    uint4 v = ((const uint4*)g_fpreh)[i];
    int cb = (int)((i*8) & (C3-1));
    uint32_t in[4] = {v.x, v.y, v.z, v.w};
    uint32_t outv[4];
    #pragma unroll
    for (int j = 0; j < 4; ++j) {
        int c = cb + 2*j;
        float2 f = __half22float2(*(__half2*)&in[j]);
        float a = fmaxf(f.x*sS[c]   + sS[C3+c],   0.f);
        float b = fmaxf(f.y*sS[c+1] + sS[C3+c+1], 0.f);
        outv[j] = pack_h2(a, b);
    }
    ((uint4*)g_af16)[i] = make_uint4(outv[0], outv[1], outv[2], outv[3]);
}

// ---------------------------------------------------------------------------
// init keys
// ---------------------------------------------------------------------------
__global__ void initkeys_kernel(unsigned* __restrict__ keys) {
    int i = blockIdx.x*256 + threadIdx.x;
    if (i < NPTS*CH) keys[i] = 0u;
}

// ---------------------------------------------------------------------------
// gemm_final (cp.async, CTA 256x64, fp16, fused atomic maxpool)
// ---------------------------------------------------------------------------
#define GF_SMEM ((2*A_BUFH2 + 2*B_BUFH)*4)
__global__ __launch_bounds__(128) void gemm_final_kernel(unsigned* __restrict__ keys) {
    extern __shared__ __align__(16) uint32_t dyn[];
    uint32_t* bufA = dyn;
    uint32_t* bufB = dyn + 2*A_BUFH2;
    int t = threadIdx.x;
    int w = t >> 5, lane = t & 31;
    int g = lane >> 2, tig = lane & 3;
    size_t row0 = (size_t)blockIdx.y * GM_MT2;
    int n0 = blockIdx.x * GM_NT;

    float acc[4][8][4] = {};
    const int NC = C3/GM_KC;  // 16

    {
        uint32_t* A = bufA; uint32_t* B = bufB;
        #pragma unroll
        for (int pq = 0; pq < 8; ++pq) {
            int r = pq*32 + (t>>2), seg = t&3;
            cp16(&A[r*SAH + seg*4], g_af16 + (row0 + r)*C3 + seg*8);
        }
        {
            int kp = t>>3, s0 = t&7;
            cp16(&B[kp*SBH + s0*4],     &g_w4h[(size_t)kp*CH + n0 + s0*4]);
            cp16(&B[kp*SBH + (s0+8)*4], &g_w4h[(size_t)kp*CH + n0 + (s0+8)*4]);
        }
        CP_COMMIT();
    }

    int buf = 0;
    for (int c = 0; c < NC; ++c) {
        if (c + 1 < NC) {
            int kk = (c+1)*GM_KC;
            uint32_t* A = bufA + (buf^1)*A_BUFH2;
            uint32_t* B = bufB + (buf^1)*B_BUFH;
            #pragma unroll
            for (int pq = 0; pq < 8; ++pq) {
                int r = pq*32 + (t>>2), seg = t&3;
                cp16(&A[r*SAH + seg*4], g_af16 + (row0 + r)*C3 + kk + seg*8);
            }
            {
                int kp = t>>3, s0 = t&7;
                int kpg = (c+1)*16 + kp;
                cp16(&B[kp*SBH + s0*4],     &g_w4h[(size_t)kpg*CH + n0 + s0*4]);
                cp16(&B[kp*SBH + (s0+8)*4], &g_w4h[(size_t)kpg*CH + n0 + (s0+8)*4]);
            }
            CP_COMMIT();
            CP_WAIT(1);
        } else {
            CP_WAIT(0);
        }
        __syncthreads();

        uint32_t* A = bufA + buf*A_BUFH2;
        uint32_t* B = bufB + buf*B_BUFH;
        #pragma unroll
        for (int ks = 0; ks < 2; ++ks) {
            int kb = ks*8;
            uint32_t bf[8][2];
            #pragma unroll
            for (int n = 0; n < 8; ++n) {
                bf[n][0] = B[(kb+tig)*SBH   + n*8 + g];
                bf[n][1] = B[(kb+tig+4)*SBH + n*8 + g];
            }
            #pragma unroll
            for (int m = 0; m < 4; ++m) {
                int mr = w*64 + m*16;
                uint32_t af[4];
                af[0] = A[(mr+g)*SAH   + kb + tig];
                af[1] = A[(mr+g+8)*SAH + kb + tig];
                af[2] = A[(mr+g)*SAH   + kb + tig + 4];
                af[3] = A[(mr+g+8)*SAH + kb + tig + 4];
                #pragma unroll
                for (int n = 0; n < 8; ++n) MMA_F16(acc[m][n], af, bf[n]);
            }
        }
        __syncthreads();
        buf ^= 1;
    }

    #pragma unroll
    for (int m = 0; m < 4; ++m) {
        size_t rA = row0 + w*64 + m*16 + g;
        size_t rB = rA + 8;
        size_t pA = rA / KNBR, pB = rB / KNBR;
        #pragma unroll
        for (int n = 0; n < 8; ++n) {
            int col = n0 + n*8 + 2*tig;
            atomicMax(&keys[pA*CH + col],     fenc(acc[m][n][0]));
            atomicMax(&keys[pA*CH + col + 1], fenc(acc[m][n][1]));
            atomicMax(&keys[pB*CH + col],     fenc(acc[m][n][2]));
            atomicMax(&keys[pB*CH + col + 1], fenc(acc[m][n][3]));
        }
    }
}

// ---------------------------------------------------------------------------
// decode keys in place + add b4
// ---------------------------------------------------------------------------
__global__ void decode_kernel(float* __restrict__ out, const float* __restrict__ b4) {
    int i = blockIdx.x*256 + threadIdx.x;
    if (i < NPTS*CH) {
        int c = i % CH;
        unsigned k = ((const unsigned*)(out + (size_t)BB*NN*3))[i];
        out[(size_t)BB*NN*3 + i] = fdec(k) + b4[c];
    }
}

__global__ void copy_xyz_kernel(const float* __restrict__ xyz,
                                float* __restrict__ out) {
    int i = blockIdx.x*256 + threadIdx.x;
    if (i < BB*NN*3) out[i] = xyz[i];
}

extern "C" void kernel_launch(void* const* d_in, const int* in_sizes, int n_in,
                              void* d_out, int out_size) {
    (void)in_sizes; (void)n_in; (void)out_size;
    const float* xyz = (const float*)d_in[0];
    const float* W1  = (const float*)d_in[1];
    const float* b1  = (const float*)d_in[2];
    const float* g1  = (const float*)d_in[3];
    const float* be1 = (const float*)d_in[4];
    const float* W2  = (const float*)d_in[5];
    const float* b2  = (const float*)d_in[6];
    const float* W3  = (const float*)d_in[7];
    const float* b3  = (const float*)d_in[8];
    const float* g3  = (const float*)d_in[9];
    const float* be3 = (const float*)d_in[10];
    const float* W4  = (const float*)d_in[11];
    const float* b4  = (const float*)d_in[12];
    float* out = (float*)d_out;
    unsigned* keys = (unsigned*)(out + (size_t)BB*NN*3);

    static int smem_set = 0;
    if (!smem_set) {
        cudaFuncSetAttribute(gemm3_kernel, cudaFuncAttributeMaxDynamicSharedMemorySize, G3_SMEM);
        cudaFuncSetAttribute(gemm_final_kernel, cudaFuncAttributeMaxDynamicSharedMemorySize, GF_SMEM);
        smem_set = 1;
    }

    knn_kernel<<<NPTS, 256>>>(xyz);
    stats1_kernel<<<STAT_BLOCKS, 128>>>(xyz, W1, b1);
    fin1_kernel<<<1, C1>>>(g1, be1);
    edge_kernel<<<NROWS/16, 256>>>(xyz, W1, b1);
    w3h_kernel<<<(128*C3 + 255)/256, 256>>>(W3);
    w4h_kernel<<<(256*CH + 255)/256, 256>>>(W4);
    {
        dim3 grid2(C2/GM_NT, NROWS/GM_MT);   // (4, 1280)
        gemm2_kernel<<<grid2, 128>>>(W2, b2);
    }
    gmax_kernel<<<NPTS, 128>>>();
    {
        dim3 gridFA(C3/GM_NT, NPTS/GM_MT);   // (8, 64)
        gemmFA_kernel<<<gridFA, 128>>>(W3, b3);
    }
    {
        dim3 grid3(C3/GM_NT, NROWS/GM_MT2);  // (8, 640)
        gemm3_kernel<<<grid3, 128, G3_SMEM>>>();
    }
    fin3_kernel<<<1, C3>>>(g3, be3);
    bnapply_kernel<<<(int)(((size_t)NROWS*C3/8 + 255)/256), 256>>>();
    initkeys_kernel<<<(NPTS*CH + 255)/256, 256>>>(keys);
    {
        dim3 grid4(CH/GM_NT, NROWS/GM_MT2);  // (6, 640)
        gemm_final_kernel<<<grid4, 128, GF_SMEM>>>(keys);
    }
    decode_kernel<<<(NPTS*CH + 255)/256, 256>>>(out, b4);
    copy_xyz_kernel<<<(BB*NN*3 + 255)/256, 256>>>(xyz, out);
}

// round 11
// speedup vs baseline: 7.9086x; 1.0032x over previous
#include <cuda_runtime.h>
#include <cuda_fp16.h>
#include <math.h>
#include <float.h>
#include <stdint.h>

// Problem constants
#define BB 2
#define NN 4096
#define KNBR 20
#define NPTS (BB*NN)            // 8192
#define NROWS (NPTS*KNBR)       // 163840
#define C1 128
#define C2 256
#define C3 512
#define CH 384
#define BN_EPS 1e-5f
#define STAT_BLOCKS 1024
#define ROWS_PER_STAT (NROWS/STAT_BLOCKS) // 160

__device__ __forceinline__ void cp16(void* dst, const void* src) {
    uint32_t s = (uint32_t)__cvta_generic_to_shared(dst);
    asm volatile("cp.async.cg.shared.global [%0], [%1], 16;" :: "r"(s), "l"(src));
}
#define CP_COMMIT() asm volatile("cp.async.commit_group;" ::: "memory")
#define CP_WAIT(n)  asm volatile("cp.async.wait_group %0;" :: "n"(n) : "memory")

__device__ __forceinline__ uint32_t pack_h2(float a, float b) {
    __half2 h = __floats2half2_rn(a, b);
    return *(uint32_t*)&h;
}

// order-preserving float<->uint for atomicMax
__device__ __forceinline__ unsigned fenc(float f) {
    int b = __float_as_int(f);
    return (b < 0) ? ~((unsigned)b) : (((unsigned)b) | 0x80000000u);
}
__device__ __forceinline__ float fdec(unsigned k) {
    return (k & 0x80000000u) ? __int_as_float((int)(k ^ 0x80000000u))
                             : __int_as_float((int)(~k));
}

// bn3+relu applied to an fp16x2 fragment in fp32 (bit-identical to bnapply)
__device__ __forceinline__ uint32_t bnfrag(uint32_t a, float2 sc, float2 sh) {
    float2 f = __half22float2(*(__half2*)&a);
    float x = fmaxf(f.x*sc.x + sh.x, 0.f);
    float y = fmaxf(f.y*sc.y + sh.y, 0.f);
    return pack_h2(x, y);
}

// ---------------- scratch (static device globals) ----------------
__device__ int      g_idx[NROWS];
__device__ float    g_part1[STAT_BLOCKS*2*C1];
__device__ float    g_ss1[2*C1];
__device__ __half   g_Ah[(size_t)NROWS*C1];      // 42 MB
__device__ __half   g_H2h[(size_t)NROWS*C2];     // 84 MB
__device__ __half   g_gmaxh[(size_t)NPTS*C2];
__device__ float    g_fA[(size_t)NPTS*C3];
__device__ __half   g_fpreh[(size_t)NROWS*C3];   // 168 MB
__device__ float    g_p3[(size_t)(NROWS/128)*2*C3];
__device__ float    g_ss3[2*C3];
__device__ uint32_t g_w3h[128*C3];               // W3[256:512] packed [k/2][col]
__device__ uint32_t g_w4h[256*CH];               // W4 packed [k/2][col]

// ---------------------------------------------------------------------------
// K1: KNN (unchanged — passing, R9)
// ---------------------------------------------------------------------------
__global__ void knn_kernel(const float* __restrict__ xyz) {
    __shared__ float sd[NN];
    __shared__ float rv[8];
    __shared__ int   ri8[8];
    __shared__ int   swin;
    int p = blockIdx.x;
    int b = p >> 12, n = p & (NN-1);
    int t = threadIdx.x, lane = t & 31, w = t >> 5;
    const float* base = xyz + (size_t)b*NN*3;
    float cx = base[n*3+0], cy = base[n*3+1], cz = base[n*3+2];
    float pp = cx*cx + cy*cy + cz*cz;
    float bv = FLT_MAX; int bi = NN;
    for (int m = t; m < NN; m += 256) {
        float qx = base[m*3+0], qy = base[m*3+1], qz = base[m*3+2];
        float d2 = pp + (qx*qx + qy*qy + qz*qz) - 2.f*(cx*qx + cy*qy + cz*qz);
        sd[m] = d2;
        if (d2 < bv) { bv = d2; bi = m; }
    }
    __syncthreads();
    for (int round = 0; round < KNBR; ++round) {
        float rb = bv; int rx = bi;
        #pragma unroll
        for (int off = 16; off > 0; off >>= 1) {
            float ov = __shfl_down_sync(0xffffffffu, rb, off);
            int   oi = __shfl_down_sync(0xffffffffu, rx, off);
            if (ov < rb || (ov == rb && oi < rx)) { rb = ov; rx = oi; }
        }
        if (lane == 0) { rv[w] = rb; ri8[w] = rx; }
        __syncthreads();
        if (w == 0) {
            float v2 = (lane < 8) ? rv[lane] : FLT_MAX;
            int   i2 = (lane < 8) ? ri8[lane] : NN;
            #pragma unroll
            for (int off = 4; off > 0; off >>= 1) {
                float ov = __shfl_down_sync(0xffffffffu, v2, off);
                int   oi = __shfl_down_sync(0xffffffffu, i2, off);
                if (ov < v2 || (ov == v2 && oi < i2)) { v2 = ov; i2 = oi; }
            }
            if (lane == 0) {
                g_idx[p*KNBR + round] = i2;
                sd[i2] = FLT_MAX;
                swin = i2;
            }
        }
        __syncthreads();
        if (bi == swin) {
            bv = FLT_MAX; bi = NN;
            for (int m = t; m < NN; m += 256) {
                float v = sd[m];
                if (v < bv) { bv = v; bi = m; }
            }
        }
    }
}

// ---------------------------------------------------------------------------
// BN1 stats (unchanged)
// ---------------------------------------------------------------------------
__global__ void stats1_kernel(const float* __restrict__ xyz,
                              const float* __restrict__ W1,
                              const float* __restrict__ b1) {
    __shared__ float se[ROWS_PER_STAT*6];
    int blk = blockIdx.x, t = threadIdx.x;
    int row0 = blk * ROWS_PER_STAT;
    for (int r = t; r < ROWS_PER_STAT; r += 128) {
        int gr = row0 + r;
        int p  = gr / KNBR;
        int b  = p >> 12, n = p & (NN-1);
        int id = g_idx[gr];
        const float* cb = xyz + ((size_t)b*NN + n)*3;
        const float* nb = xyz + ((size_t)b*NN + id)*3;
        se[r*6+0] = nb[0]-cb[0];
        se[r*6+1] = nb[1]-cb[1];
        se[r*6+2] = nb[2]-cb[2];
        se[r*6+3] = cb[0]; se[r*6+4] = cb[1]; se[r*6+5] = cb[2];
    }
    __syncthreads();
    float w0 = W1[0*C1+t], w1 = W1[1*C1+t], w2 = W1[2*C1+t],
          w3 = W1[3*C1+t], w4 = W1[4*C1+t], w5 = W1[5*C1+t], bb = b1[t];
    float s = 0.f, q = 0.f;
    for (int r = 0; r < ROWS_PER_STAT; ++r) {
        float h = bb + se[r*6+0]*w0 + se[r*6+1]*w1 + se[r*6+2]*w2
                     + se[r*6+3]*w3 + se[r*6+4]*w4 + se[r*6+5]*w5;
        s += h; q += h*h;
    }
    g_part1[blk*(2*C1) + t]      = s;
    g_part1[blk*(2*C1) + C1 + t] = q;
}

__global__ void fin1_kernel(const float* __restrict__ g1,
                            const float* __restrict__ be1) {
    int c = threadIdx.x;
    float s = 0.f, q = 0.f;
    for (int i = 0; i < STAT_BLOCKS; ++i) {
        s += g_part1[i*(2*C1)+c];
        q += g_part1[i*(2*C1)+C1+c];
    }
    float mu  = s / (float)NROWS;
    float var = q / (float)NROWS - mu*mu;
    float sc  = g1[c] * rsqrtf(var + BN_EPS);
    g_ss1[c]     = sc;
    g_ss1[C1+c]  = be1[c] - mu*sc;
}

// ---------------------------------------------------------------------------
// edge16: writes fp16 A (unchanged)
// ---------------------------------------------------------------------------
__global__ __launch_bounds__(256) void edge_kernel(
    const float* __restrict__ xyz,
    const float* __restrict__ W1, const float* __restrict__ b1) {
    __shared__ float sE[16*6];
    int row0 = blockIdx.x * 16, t = threadIdx.x;
    if (t < 96) {
        int r = t / 6, d = t - r*6;
        int row = row0 + r;
        int p = row / KNBR;
        int b = p >> 12, n = p & (NN-1);
        float v;
        if (d < 3) {
            int id = g_idx[row];
            v = xyz[((size_t)b*NN + id)*3 + d] - xyz[((size_t)b*NN + n)*3 + d];
        } else {
            v = xyz[((size_t)b*NN + n)*3 + (d-3)];
        }
        sE[r*6 + d] = v;
    }
    __syncthreads();
    int c = t & (C1-1), h = t >> 7;
    float w0 = W1[0*C1+c], w1 = W1[1*C1+c], w2 = W1[2*C1+c],
          w3 = W1[3*C1+c], w4 = W1[4*C1+c], w5 = W1[5*C1+c];
    float bb = b1[c], sc = g_ss1[c], sh = g_ss1[C1+c];
    #pragma unroll
    for (int rr = 0; rr < 8; ++rr) {
        int r = h*8 + rr;
        float hv = bb + sE[r*6+0]*w0 + sE[r*6+1]*w1 + sE[r*6+2]*w2
                      + sE[r*6+3]*w3 + sE[r*6+4]*w4 + sE[r*6+5]*w5;
        hv = fmaxf(hv*sc + sh, 0.f);
        g_Ah[(size_t)(row0 + r)*C1 + c] = __float2half_rn(hv);
    }
}

// ---------------------------------------------------------------------------
// weight prep: half2-packed [k/2][col]
// ---------------------------------------------------------------------------
__global__ void w3h_kernel(const float* __restrict__ W3) {
    int i = blockIdx.x*256 + threadIdx.x;
    if (i < 128*C3) {
        int kp = i / C3, col = i - kp*C3;
        g_w3h[i] = pack_h2(W3[(size_t)(C2 + 2*kp)*C3 + col],
                           W3[(size_t)(C2 + 2*kp + 1)*C3 + col]);
    }
}
__global__ void w4h_kernel(const float* __restrict__ W4) {
    int i = blockIdx.x*256 + threadIdx.x;
    if (i < 256*CH) {
        int kp = i / CH, col = i - kp*CH;
        g_w4h[i] = pack_h2(W4[(size_t)(2*kp)*CH + col],
                           W4[(size_t)(2*kp + 1)*CH + col]);
    }
}

// ===========================================================================
// fp16 m16n8k16 tile configs
// ===========================================================================
#define GM_MT 128
#define GM_MT2 256
#define GM_NT 64
#define GM_KC 32
#define SAH 20
#define SBH 72
#define A_BUFH  (GM_MT*SAH)     // 2560 u32
#define A_BUFH2 (GM_MT2*SAH)    // 5120 u32
#define B_BUFH  (16*SBH)        // 1152 u32

#define MMA_F16(acc, af, bf) \
    asm volatile( \
        "mma.sync.aligned.m16n8k16.row.col.f32.f16.f16.f32 " \
        "{%0,%1,%2,%3}, {%4,%5,%6,%7}, {%8,%9}, {%0,%1,%2,%3};" \
        : "+f"((acc)[0]), "+f"((acc)[1]), "+f"((acc)[2]), "+f"((acc)[3]) \
        : "r"((af)[0]), "r"((af)[1]), "r"((af)[2]), "r"((af)[3]), \
          "r"((bf)[0]), "r"((bf)[1]))

// ---------------------------------------------------------------------------
// gemm2: H2 = A @ W2 + b2 (fp16 in, fp16 out). CTA 128x64. (unchanged)
// ---------------------------------------------------------------------------
__global__ __launch_bounds__(128) void gemm2_kernel(
    const float* __restrict__ W2, const float* __restrict__ b2) {
    __shared__ __align__(16) uint32_t sA[GM_MT*SAH];
    __shared__ __align__(16) uint32_t sB[16*SBH];
    int t = threadIdx.x;
    int w = t >> 5, lane = t & 31;
    int g = lane >> 2, tig = lane & 3;
    size_t row0 = (size_t)blockIdx.y * GM_MT;
    int n0 = blockIdx.x * GM_NT;

    float acc[2][8][4] = {};

    for (int kk = 0; kk < C1; kk += GM_KC) {
        #pragma unroll
        for (int pq = 0; pq < 4; ++pq) {
            int r = pq*32 + (t>>2), seg = t&3;
            uint4 v = *(const uint4*)(g_Ah + (row0 + r)*C1 + kk + seg*8);
            *(uint4*)&sA[r*SAH + seg*4] = v;
        }
        #pragma unroll
        for (int pq = 0; pq < 2; ++pq) {
            int kp = pq*8 + (t>>4), colb = (t&15)*4;
            const float* s0 = &W2[(size_t)(kk + 2*kp)*C2 + n0 + colb];
            float4 va = *(const float4*)s0;
            float4 vb = *(const float4*)(s0 + C2);
            uint4 o = make_uint4(pack_h2(va.x, vb.x), pack_h2(va.y, vb.y),
                                 pack_h2(va.z, vb.z), pack_h2(va.w, vb.w));
            *(uint4*)&sB[kp*SBH + colb] = o;
        }
        __syncthreads();
        #pragma unroll
        for (int ks = 0; ks < 2; ++ks) {
            int kb = ks*8;
            uint32_t bf[8][2];
            #pragma unroll
            for (int n = 0; n < 8; ++n) {
                bf[n][0] = sB[(kb+tig)*SBH   + n*8 + g];
                bf[n][1] = sB[(kb+tig+4)*SBH + n*8 + g];
            }
            #pragma unroll
            for (int m = 0; m < 2; ++m) {
                int mr = w*32 + m*16;
                uint32_t af[4];
                af[0] = sA[(mr+g)*SAH   + kb + tig];
                af[1] = sA[(mr+g+8)*SAH + kb + tig];
                af[2] = sA[(mr+g)*SAH   + kb + tig + 4];
                af[3] = sA[(mr+g+8)*SAH + kb + tig + 4];
                #pragma unroll
                for (int n = 0; n < 8; ++n) MMA_F16(acc[m][n], af, bf[n]);
            }
        }
        __syncthreads();
    }
    uint32_t* H2v = (uint32_t*)g_H2h;
    #pragma unroll
    for (int m = 0; m < 2; ++m) {
        size_t r0 = row0 + w*32 + m*16 + g;
        #pragma unroll
        for (int n = 0; n < 8; ++n) {
            int col = n0 + n*8 + 2*tig;
            float2 bb = *(const float2*)&b2[col];
            H2v[r0*(C2/2) + col/2]     = pack_h2(acc[m][n][0]+bb.x, acc[m][n][1]+bb.y);
            H2v[(r0+8)*(C2/2) + col/2] = pack_h2(acc[m][n][2]+bb.x, acc[m][n][3]+bb.y);
        }
    }
}

// ---------------------------------------------------------------------------
// gmax over fp16 pairs (unchanged)
// ---------------------------------------------------------------------------
__global__ void gmax_kernel() {
    int p = blockIdx.x, t = threadIdx.x;   // 128 threads
    const __half2* src = (const __half2*)g_H2h + (size_t)p*KNBR*(C2/2) + t;
    __half2 m = src[0];
    #pragma unroll
    for (int r = 1; r < KNBR; ++r) m = __hmax2(m, src[(size_t)r*(C2/2)]);
    ((__half2*)g_gmaxh)[(size_t)p*(C2/2) + t] = m;
}

// ---------------------------------------------------------------------------
// gemmFA: fA = gmax @ W3[0:256] + b3 (unchanged)
// ---------------------------------------------------------------------------
__global__ __launch_bounds__(128) void gemmFA_kernel(
    const float* __restrict__ W3, const float* __restrict__ b3) {
    __shared__ __align__(16) uint32_t sA[GM_MT*SAH];
    __shared__ __align__(16) uint32_t sB[16*SBH];
    int t = threadIdx.x;
    int w = t >> 5, lane = t & 31;
    int g = lane >> 2, tig = lane & 3;
    size_t row0 = (size_t)blockIdx.y * GM_MT;
    int n0 = blockIdx.x * GM_NT;

    float acc[2][8][4] = {};

    for (int kk = 0; kk < C2; kk += GM_KC) {
        #pragma unroll
        for (int pq = 0; pq < 4; ++pq) {
            int r = pq*32 + (t>>2), seg = t&3;
            uint4 v = *(const uint4*)(g_gmaxh + (row0 + r)*C2 + kk + seg*8);
            *(uint4*)&sA[r*SAH + seg*4] = v;
        }
        #pragma unroll
        for (int pq = 0; pq < 2; ++pq) {
            int kp = pq*8 + (t>>4), colb = (t&15)*4;
            const float* s0 = &W3[(size_t)(kk + 2*kp)*C3 + n0 + colb];
            float4 va = *(const float4*)s0;
            float4 vb = *(const float4*)(s0 + C3);
            uint4 o = make_uint4(pack_h2(va.x, vb.x), pack_h2(va.y, vb.y),
                                 pack_h2(va.z, vb.z), pack_h2(va.w, vb.w));
            *(uint4*)&sB[kp*SBH + colb] = o;
        }
        __syncthreads();
        #pragma unroll
        for (int ks = 0; ks < 2; ++ks) {
            int kb = ks*8;
            uint32_t bf[8][2];
            #pragma unroll
            for (int n = 0; n < 8; ++n) {
                bf[n][0] = sB[(kb+tig)*SBH   + n*8 + g];
                bf[n][1] = sB[(kb+tig+4)*SBH + n*8 + g];
            }
            #pragma unroll
            for (int m = 0; m < 2; ++m) {
                int mr = w*32 + m*16;
                uint32_t af[4];
                af[0] = sA[(mr+g)*SAH   + kb + tig];
                af[1] = sA[(mr+g+8)*SAH + kb + tig];
                af[2] = sA[(mr+g)*SAH   + kb + tig + 4];
                af[3] = sA[(mr+g+8)*SAH + kb + tig + 4];
                #pragma unroll
                for (int n = 0; n < 8; ++n) MMA_F16(acc[m][n], af, bf[n]);
            }
        }
        __syncthreads();
    }
    #pragma unroll
    for (int m = 0; m < 2; ++m) {
        size_t r0 = row0 + w*32 + m*16 + g;
        #pragma unroll
        for (int n = 0; n < 8; ++n) {
            int col = n0 + n*8 + 2*tig;
            float2 bb = *(const float2*)&b3[col];
            *(float2*)&g_fA[r0*C3 + col]     = make_float2(acc[m][n][0]+bb.x, acc[m][n][1]+bb.y);
            *(float2*)&g_fA[(r0+8)*C3 + col] = make_float2(acc[m][n][2]+bb.x, acc[m][n][3]+bb.y);
        }
    }
}

// ---------------------------------------------------------------------------
// gemm3 load helper (one pipeline stage)
// ---------------------------------------------------------------------------
__device__ __forceinline__ void g3_load(uint32_t* A, uint32_t* B,
                                        size_t row0, int n0, int kk, int t) {
    #pragma unroll
    for (int pq = 0; pq < 8; ++pq) {
        int r = pq*32 + (t>>2), seg = t&3;
        cp16(&A[r*SAH + seg*4], g_H2h + (row0 + r)*C2 + kk + seg*8);
    }
    int kp = t>>3, s0 = t&7;
    int kpg = (kk>>1) + kp;
    cp16(&B[kp*SBH + s0*4],     &g_w3h[(size_t)kpg*C3 + n0 + s0*4]);
    cp16(&B[kp*SBH + (s0+8)*4], &g_w3h[(size_t)kpg*C3 + n0 + (s0+8)*4]);
}

// ---------------------------------------------------------------------------
// gemm3 (3-stage cp.async, CTA 256x64, fp16, fused BN3-stat partials)
// ---------------------------------------------------------------------------
#define G3_SMEM ((3*A_BUFH2 + 3*B_BUFH + 512)*4)
__global__ __launch_bounds__(128) void gemm3_kernel() {
    extern __shared__ __align__(16) uint32_t dyn[];
    uint32_t* bufA = dyn;                          // 3 x A_BUFH2
    uint32_t* bufB = dyn + 3*A_BUFH2;              // 3 x B_BUFH
    float* sstat = (float*)(dyn + 3*A_BUFH2 + 3*B_BUFH);
    int t = threadIdx.x;
    int w = t >> 5, lane = t & 31;
    int g = lane >> 2, tig = lane & 3;
    size_t row0 = (size_t)blockIdx.y * GM_MT2;
    int n0 = blockIdx.x * GM_NT;

    float acc[4][8][4] = {};
    const int NC = C2/GM_KC;  // 8

    g3_load(bufA, bufB, row0, n0, 0, t);                      CP_COMMIT();
    g3_load(bufA + A_BUFH2, bufB + B_BUFH, row0, n0, 32, t);  CP_COMMIT();

    for (int c = 0; c < NC; ++c) {
        int cur = c % 3;
        if (c + 2 < NC) {
            int st = (c+2) % 3;
            g3_load(bufA + st*A_BUFH2, bufB + st*B_BUFH, row0, n0, (c+2)*GM_KC, t);
            CP_COMMIT();
            CP_WAIT(2);
        } else if (c + 1 < NC) {
            CP_WAIT(1);
        } else {
            CP_WAIT(0);
        }
        __syncthreads();

        uint32_t* A = bufA + cur*A_BUFH2;
        uint32_t* B = bufB + cur*B_BUFH;
        #pragma unroll
        for (int ks = 0; ks < 2; ++ks) {
            int kb = ks*8;
            uint32_t bf[8][2];
            #pragma unroll
            for (int n = 0; n < 8; ++n) {
                bf[n][0] = B[(kb+tig)*SBH   + n*8 + g];
                bf[n][1] = B[(kb+tig+4)*SBH + n*8 + g];
            }
            #pragma unroll
            for (int m = 0; m < 4; ++m) {
                int mr = w*64 + m*16;
                uint32_t af[4];
                af[0] = A[(mr+g)*SAH   + kb + tig];
                af[1] = A[(mr+g+8)*SAH + kb + tig];
                af[2] = A[(mr+g)*SAH   + kb + tig + 4];
                af[3] = A[(mr+g+8)*SAH + kb + tig + 4];
                #pragma unroll
                for (int n = 0; n < 8; ++n) MMA_F16(acc[m][n], af, bf[n]);
            }
        }
        __syncthreads();
    }

    // epilogue: add fA, write fp16 fpre, accumulate column stats (fp32)
    uint32_t* FPv = (uint32_t*)g_fpreh;
    float sloc[8][2], qloc[8][2];
    #pragma unroll
    for (int n = 0; n < 8; ++n) { sloc[n][0]=0.f; sloc[n][1]=0.f; qloc[n][0]=0.f; qloc[n][1]=0.f; }
    #pragma unroll
    for (int m = 0; m < 4; ++m) {
        size_t rA = row0 + w*64 + m*16 + g;
        size_t rB = rA + 8;
        size_t pA = rA / KNBR, pB = rB / KNBR;
        #pragma unroll
        for (int n = 0; n < 8; ++n) {
            int col = n0 + n*8 + 2*tig;
            float2 fa = *(const float2*)&g_fA[pA*C3 + col];
            float2 fb = *(const float2*)&g_fA[pB*C3 + col];
            float v0 = acc[m][n][0]+fa.x, v1 = acc[m][n][1]+fa.y;
            float v2 = acc[m][n][2]+fb.x, v3 = acc[m][n][3]+fb.y;
            FPv[rA*(C3/2) + col/2] = pack_h2(v0, v1);
            FPv[rB*(C3/2) + col/2] = pack_h2(v2, v3);
            sloc[n][0] += v0 + v2;   qloc[n][0] += v0*v0 + v2*v2;
            sloc[n][1] += v1 + v3;   qloc[n][1] += v1*v1 + v3*v3;
        }
    }
    #pragma unroll
    for (int n = 0; n < 8; ++n)
        #pragma unroll
        for (int j = 0; j < 2; ++j) {
            float s = sloc[n][j], q = qloc[n][j];
            #pragma unroll
            for (int mk = 4; mk <= 16; mk <<= 1) {
                s += __shfl_xor_sync(0xffffffffu, s, mk);
                q += __shfl_xor_sync(0xffffffffu, q, mk);
            }
            if (g == 0) {
                int ci = n*8 + 2*tig + j;
                sstat[(w*64 + ci)*2 + 0] = s;
                sstat[(w*64 + ci)*2 + 1] = q;
            }
        }
    __syncthreads();
    if (t < 128) {
        int ci = t >> 1, which = t & 1;
        float v = sstat[(0*64+ci)*2+which] + sstat[(1*64+ci)*2+which]
                + sstat[(2*64+ci)*2+which] + sstat[(3*64+ci)*2+which];
        g_p3[(size_t)blockIdx.y*(2*C3) + (size_t)which*C3 + n0 + ci] = v;
    }
}

// ---------------------------------------------------------------------------
// fin3 (unchanged)
// ---------------------------------------------------------------------------
__global__ void fin3_kernel(const float* __restrict__ g3,
                            const float* __restrict__ be3) {
    int c = threadIdx.x;   // 512
    float s = 0.f, q = 0.f;
    for (int i = 0; i < NROWS/GM_MT2; ++i) {
        s += g_p3[(size_t)i*(2*C3) + c];
        q += g_p3[(size_t)i*(2*C3) + C3 + c];
    }
    float mu  = s / (float)NROWS;
    float var = q / (float)NROWS - mu*mu;
    float sc  = g3[c] * rsqrtf(var + BN_EPS);
    g_ss3[c]    = sc;
    g_ss3[C3+c] = be3[c] - mu*sc;
}

// ---------------------------------------------------------------------------
// init keys
// ---------------------------------------------------------------------------
__global__ void initkeys_kernel(unsigned* __restrict__ keys) {
    int i = blockIdx.x*256 + threadIdx.x;
    if (i < NPTS*CH) keys[i] = 0u;
}

// ---------------------------------------------------------------------------
// gemm_final load helper
// ---------------------------------------------------------------------------
__device__ __forceinline__ void g4_load(uint32_t* A, uint32_t* B,
                                        size_t row0, int n0, int kk, int t) {
    #pragma unroll
    for (int pq = 0; pq < 8; ++pq) {
        int r = pq*32 + (t>>2), seg = t&3;
        cp16(&A[r*SAH + seg*4], g_fpreh + (row0 + r)*C3 + kk + seg*8);
    }
    int kp = t>>3, s0 = t&7;
    int kpg = (kk>>1) + kp;
    cp16(&B[kp*SBH + s0*4],     &g_w4h[(size_t)kpg*CH + n0 + s0*4]);
    cp16(&B[kp*SBH + (s0+8)*4], &g_w4h[(size_t)kpg*CH + n0 + (s0+8)*4]);
}

// ---------------------------------------------------------------------------
// gemm_final: 3-stage cp.async, CTA 256x64, fp16, bn3+relu fused at fragment
// load (fp32 math — bit-identical to the former bnapply pass), grouped
// atomicMax maxpool epilogue.
// ---------------------------------------------------------------------------
#define GF_SMEM ((3*A_BUFH2 + 3*B_BUFH + 2*C3)*4)
__global__ __launch_bounds__(128) void gemm_final_kernel(unsigned* __restrict__ keys) {
    extern __shared__ __align__(16) uint32_t dyn[];
    uint32_t* bufA = dyn;
    uint32_t* bufB = dyn + 3*A_BUFH2;
    float* sS = (float*)(dyn + 3*A_BUFH2 + 3*B_BUFH);   // [scale 512][shift 512]
    int t = threadIdx.x;
    int w = t >> 5, lane = t & 31;
    int g = lane >> 2, tig = lane & 3;
    size_t row0 = (size_t)blockIdx.y * GM_MT2;
    int n0 = blockIdx.x * GM_NT;

    float acc[4][8][4] = {};
    const int NC = C3/GM_KC;  // 16

    for (int i = t; i < 2*C3; i += 128) sS[i] = g_ss3[i];

    g4_load(bufA, bufB, row0, n0, 0, t);                      CP_COMMIT();
    g4_load(bufA + A_BUFH2, bufB + B_BUFH, row0, n0, 32, t);  CP_COMMIT();

    for (int c = 0; c < NC; ++c) {
        int cur = c % 3;
        if (c + 2 < NC) {
            int st = (c+2) % 3;
            g4_load(bufA + st*A_BUFH2, bufB + st*B_BUFH, row0, n0, (c+2)*GM_KC, t);
            CP_COMMIT();
            CP_WAIT(2);
        } else if (c + 1 < NC) {
            CP_WAIT(1);
        } else {
            CP_WAIT(0);
        }
        __syncthreads();

        uint32_t* A = bufA + cur*A_BUFH2;
        uint32_t* B = bufB + cur*B_BUFH;
        int kk = c*GM_KC;
        #pragma unroll
        for (int ks = 0; ks < 2; ++ks) {
            int kb = ks*8;
            int kpg0 = (kk>>1) + kb + tig;
            float2 sc0 = *(const float2*)&sS[2*kpg0];
            float2 sh0 = *(const float2*)&sS[C3 + 2*kpg0];
            float2 sc4 = *(const float2*)&sS[2*(kpg0+4)];
            float2 sh4 = *(const float2*)&sS[C3 + 2*(kpg0+4)];
            uint32_t bf[8][2];
            #pragma unroll
            for (int n = 0; n < 8; ++n) {
                bf[n][0] = B[(kb+tig)*SBH   + n*8 + g];
                bf[n][1] = B[(kb+tig+4)*SBH + n*8 + g];
            }
            #pragma unroll
            for (int m = 0; m < 4; ++m) {
                int mr = w*64 + m*16;
                uint32_t af[4];
                af[0] = bnfrag(A[(mr+g)*SAH   + kb + tig],     sc0, sh0);
                af[1] = bnfrag(A[(mr+g+8)*SAH + kb + tig],     sc0, sh0);
                af[2] = bnfrag(A[(mr+g)*SAH   + kb + tig + 4], sc4, sh4);
                af[3] = bnfrag(A[(mr+g+8)*SAH + kb + tig + 4], sc4, sh4);
                #pragma unroll
                for (int n = 0; n < 8; ++n) MMA_F16(acc[m][n], af, bf[n]);
            }
        }
        __syncthreads();
    }

    // grouped-atomic maxpool epilogue: thread's 8 rows per col are
    // row0+w*64+g+8j (j=0..7); run-length combine by point before atomicMax.
    #pragma unroll
    for (int n = 0; n < 8; ++n) {
        #pragma unroll
        for (int cc = 0; cc < 2; ++cc) {
            int col = n0 + n*8 + 2*tig + cc;
            size_t curp = (row0 + w*64 + g) / KNBR;
            float rm = -FLT_MAX;
            #pragma unroll
            for (int j = 0; j < 8; ++j) {
                size_t row = row0 + w*64 + g + 8*j;
                size_t pj = row / KNBR;
                float v = acc[j>>1][n][((j&1)<<1) + cc];
                if (pj != curp) {
                    atomicMax(&keys[curp*CH + col], fenc(rm));
                    curp = pj; rm = v;
                } else {
                    rm = fmaxf(rm, v);
                }
            }
            atomicMax(&keys[curp*CH + col], fenc(rm));
        }
    }
}

// ---------------------------------------------------------------------------
// decode keys in place + add b4
// ---------------------------------------------------------------------------
__global__ void decode_kernel(float* __restrict__ out, const float* __restrict__ b4) {
    int i = blockIdx.x*256 + threadIdx.x;
    if (i < NPTS*CH) {
        int c = i % CH;
        unsigned k = ((const unsigned*)(out + (size_t)BB*NN*3))[i];
        out[(size_t)BB*NN*3 + i] = fdec(k) + b4[c];
    }
}

__global__ void copy_xyz_kernel(const float* __restrict__ xyz,
                                float* __restrict__ out) {
    int i = blockIdx.x*256 + threadIdx.x;
    if (i < BB*NN*3) out[i] = xyz[i];
}

extern "C" void kernel_launch(void* const* d_in, const int* in_sizes, int n_in,
                              void* d_out, int out_size) {
    (void)in_sizes; (void)n_in; (void)out_size;
    const float* xyz = (const float*)d_in[0];
    const float* W1  = (const float*)d_in[1];
    const float* b1  = (const float*)d_in[2];
    const float* g1  = (const float*)d_in[3];
    const float* be1 = (const float*)d_in[4];
    const float* W2  = (const float*)d_in[5];
    const float* b2  = (const float*)d_in[6];
    const float* W3  = (const float*)d_in[7];
    const float* b3  = (const float*)d_in[8];
    const float* g3  = (const float*)d_in[9];
    const float* be3 = (const float*)d_in[10];
    const float* W4  = (const float*)d_in[11];
    const float* b4  = (const float*)d_in[12];
    float* out = (float*)d_out;
    unsigned* keys = (unsigned*)(out + (size_t)BB*NN*3);

    static int smem_set = 0;
    if (!smem_set) {
        cudaFuncSetAttribute(gemm3_kernel, cudaFuncAttributeMaxDynamicSharedMemorySize, G3_SMEM);
        cudaFuncSetAttribute(gemm_final_kernel, cudaFuncAttributeMaxDynamicSharedMemorySize, GF_SMEM);
        smem_set = 1;
    }

    knn_kernel<<<NPTS, 256>>>(xyz);
    stats1_kernel<<<STAT_BLOCKS, 128>>>(xyz, W1, b1);
    fin1_kernel<<<1, C1>>>(g1, be1);
    edge_kernel<<<NROWS/16, 256>>>(xyz, W1, b1);
    w3h_kernel<<<(128*C3 + 255)/256, 256>>>(W3);
    w4h_kernel<<<(256*CH + 255)/256, 256>>>(W4);
    {
        dim3 grid2(C2/GM_NT, NROWS/GM_MT);   // (4, 1280)
        gemm2_kernel<<<grid2, 128>>>(W2, b2);
    }
    gmax_kernel<<<NPTS, 128>>>();
    {
        dim3 gridFA(C3/GM_NT, NPTS/GM_MT);   // (8, 64)
        gemmFA_kernel<<<gridFA, 128>>>(W3, b3);
    }
    {
        dim3 grid3(C3/GM_NT, NROWS/GM_MT2);  // (8, 640)
        gemm3_kernel<<<grid3, 128, G3_SMEM>>>();
    }
    fin3_kernel<<<1, C3>>>(g3, be3);
    initkeys_kernel<<<(NPTS*CH + 255)/256, 256>>>(keys);
    {
        dim3 grid4(CH/GM_NT, NROWS/GM_MT2);  // (6, 640)
        gemm_final_kernel<<<grid4, 128, GF_SMEM>>>(keys);
    }
    decode_kernel<<<(NPTS*CH + 255)/256, 256>>>(out, b4);
    copy_xyz_kernel<<<(BB*NN*3 + 255)/256, 256>>>(xyz, out);
}

// round 12
// speedup vs baseline: 8.2359x; 1.0414x over previous
#include <cuda_runtime.h>
#include <cuda_fp16.h>
#include <math.h>
#include <float.h>
#include <stdint.h>

// Problem constants
#define BB 2
#define NN 4096
#define KNBR 20
#define NPTS (BB*NN)            // 8192
#define NROWS (NPTS*KNBR)       // 163840
#define C1 128
#define C2 256
#define C3 512
#define CH 384
#define BN_EPS 1e-5f
#define STAT_BLOCKS 1024
#define ROWS_PER_STAT (NROWS/STAT_BLOCKS) // 160

__device__ __forceinline__ void cp16(void* dst, const void* src) {
    uint32_t s = (uint32_t)__cvta_generic_to_shared(dst);
    asm volatile("cp.async.cg.shared.global [%0], [%1], 16;" :: "r"(s), "l"(src));
}
#define CP_COMMIT() asm volatile("cp.async.commit_group;" ::: "memory")
#define CP_WAIT(n)  asm volatile("cp.async.wait_group %0;" :: "n"(n) : "memory")

__device__ __forceinline__ uint32_t pack_h2(float a, float b) {
    __half2 h = __floats2half2_rn(a, b);
    return *(uint32_t*)&h;
}

// ldmatrix x4: loads a full m16k16 fp16 A fragment in one instruction
__device__ __forceinline__ void ldsm4(uint32_t* r, uint32_t saddr) {
    asm volatile("ldmatrix.sync.aligned.m8n8.x4.shared.b16 {%0,%1,%2,%3}, [%4];"
        : "=r"(r[0]), "=r"(r[1]), "=r"(r[2]), "=r"(r[3]) : "r"(saddr));
}

// order-preserving float<->uint for atomicMax
__device__ __forceinline__ unsigned fenc(float f) {
    int b = __float_as_int(f);
    return (b < 0) ? ~((unsigned)b) : (((unsigned)b) | 0x80000000u);
}
__device__ __forceinline__ float fdec(unsigned k) {
    return (k & 0x80000000u) ? __int_as_float((int)(k ^ 0x80000000u))
                             : __int_as_float((int)(~k));
}

// bn3+relu on an fp16x2 fragment in half2 math (2 instrs: HFMA2 + HMAX2)
__device__ __forceinline__ uint32_t bnfrag_h2(uint32_t a, uint32_t sc2, uint32_t sh2) {
    __half2 r = __hfma2(*(__half2*)&a, *(__half2*)&sc2, *(__half2*)&sh2);
    r = __hmax2(r, __float2half2_rn(0.f));
    return *(uint32_t*)&r;
}

// ---------------- scratch (static device globals) ----------------
__device__ int      g_idx[NROWS];
__device__ float    g_part1[STAT_BLOCKS*2*C1];
__device__ float    g_ss1[2*C1];
__device__ __half   g_Ah[(size_t)NROWS*C1];      // 42 MB
__device__ __half   g_H2h[(size_t)NROWS*C2];     // 84 MB
__device__ __half   g_gmaxh[(size_t)NPTS*C2];
__device__ float    g_fA[(size_t)NPTS*C3];
__device__ __half   g_fpreh[(size_t)NROWS*C3];   // 168 MB
__device__ float    g_p3[(size_t)(NROWS/128)*2*C3];
__device__ float    g_ss3[2*C3];
__device__ uint32_t g_ss3h[2*(C3/2)];            // half2-packed: [sc 256][sh 256]
__device__ uint32_t g_w3h[128*C3];               // W3[256:512] packed [k/2][col]
__device__ uint32_t g_w4h[256*CH];               // W4 packed [k/2][col]

// ---------------------------------------------------------------------------
// K1: KNN (unchanged — passing, R9)
// ---------------------------------------------------------------------------
__global__ void knn_kernel(const float* __restrict__ xyz) {
    __shared__ float sd[NN];
    __shared__ float rv[8];
    __shared__ int   ri8[8];
    __shared__ int   swin;
    int p = blockIdx.x;
    int b = p >> 12, n = p & (NN-1);
    int t = threadIdx.x, lane = t & 31, w = t >> 5;
    const float* base = xyz + (size_t)b*NN*3;
    float cx = base[n*3+0], cy = base[n*3+1], cz = base[n*3+2];
    float pp = cx*cx + cy*cy + cz*cz;
    float bv = FLT_MAX; int bi = NN;
    for (int m = t; m < NN; m += 256) {
        float qx = base[m*3+0], qy = base[m*3+1], qz = base[m*3+2];
        float d2 = pp + (qx*qx + qy*qy + qz*qz) - 2.f*(cx*qx + cy*qy + cz*qz);
        sd[m] = d2;
        if (d2 < bv) { bv = d2; bi = m; }
    }
    __syncthreads();
    for (int round = 0; round < KNBR; ++round) {
        float rb = bv; int rx = bi;
        #pragma unroll
        for (int off = 16; off > 0; off >>= 1) {
            float ov = __shfl_down_sync(0xffffffffu, rb, off);
            int   oi = __shfl_down_sync(0xffffffffu, rx, off);
            if (ov < rb || (ov == rb && oi < rx)) { rb = ov; rx = oi; }
        }
        if (lane == 0) { rv[w] = rb; ri8[w] = rx; }
        __syncthreads();
        if (w == 0) {
            float v2 = (lane < 8) ? rv[lane] : FLT_MAX;
            int   i2 = (lane < 8) ? ri8[lane] : NN;
            #pragma unroll
            for (int off = 4; off > 0; off >>= 1) {
                float ov = __shfl_down_sync(0xffffffffu, v2, off);
                int   oi = __shfl_down_sync(0xffffffffu, i2, off);
                if (ov < v2 || (ov == v2 && oi < i2)) { v2 = ov; i2 = oi; }
            }
            if (lane == 0) {
                g_idx[p*KNBR + round] = i2;
                sd[i2] = FLT_MAX;
                swin = i2;
            }
        }
        __syncthreads();
        if (bi == swin) {
            bv = FLT_MAX; bi = NN;
            for (int m = t; m < NN; m += 256) {
                float v = sd[m];
                if (v < bv) { bv = v; bi = m; }
            }
        }
    }
}

// ---------------------------------------------------------------------------
// BN1 stats (unchanged)
// ---------------------------------------------------------------------------
__global__ void stats1_kernel(const float* __restrict__ xyz,
                              const float* __restrict__ W1,
                              const float* __restrict__ b1) {
    __shared__ float se[ROWS_PER_STAT*6];
    int blk = blockIdx.x, t = threadIdx.x;
    int row0 = blk * ROWS_PER_STAT;
    for (int r = t; r < ROWS_PER_STAT; r += 128) {
        int gr = row0 + r;
        int p  = gr / KNBR;
        int b  = p >> 12, n = p & (NN-1);
        int id = g_idx[gr];
        const float* cb = xyz + ((size_t)b*NN + n)*3;
        const float* nb = xyz + ((size_t)b*NN + id)*3;
        se[r*6+0] = nb[0]-cb[0];
        se[r*6+1] = nb[1]-cb[1];
        se[r*6+2] = nb[2]-cb[2];
        se[r*6+3] = cb[0]; se[r*6+4] = cb[1]; se[r*6+5] = cb[2];
    }
    __syncthreads();
    float w0 = W1[0*C1+t], w1 = W1[1*C1+t], w2 = W1[2*C1+t],
          w3 = W1[3*C1+t], w4 = W1[4*C1+t], w5 = W1[5*C1+t], bb = b1[t];
    float s = 0.f, q = 0.f;
    for (int r = 0; r < ROWS_PER_STAT; ++r) {
        float h = bb + se[r*6+0]*w0 + se[r*6+1]*w1 + se[r*6+2]*w2
                     + se[r*6+3]*w3 + se[r*6+4]*w4 + se[r*6+5]*w5;
        s += h; q += h*h;
    }
    g_part1[blk*(2*C1) + t]      = s;
    g_part1[blk*(2*C1) + C1 + t] = q;
}

__global__ void fin1_kernel(const float* __restrict__ g1,
                            const float* __restrict__ be1) {
    int c = threadIdx.x;
    float s = 0.f, q = 0.f;
    for (int i = 0; i < STAT_BLOCKS; ++i) {
        s += g_part1[i*(2*C1)+c];
        q += g_part1[i*(2*C1)+C1+c];
    }
    float mu  = s / (float)NROWS;
    float var = q / (float)NROWS - mu*mu;
    float sc  = g1[c] * rsqrtf(var + BN_EPS);
    g_ss1[c]     = sc;
    g_ss1[C1+c]  = be1[c] - mu*sc;
}

// ---------------------------------------------------------------------------
// edge16: writes fp16 A (unchanged)
// ---------------------------------------------------------------------------
__global__ __launch_bounds__(256) void edge_kernel(
    const float* __restrict__ xyz,
    const float* __restrict__ W1, const float* __restrict__ b1) {
    __shared__ float sE[16*6];
    int row0 = blockIdx.x * 16, t = threadIdx.x;
    if (t < 96) {
        int r = t / 6, d = t - r*6;
        int row = row0 + r;
        int p = row / KNBR;
        int b = p >> 12, n = p & (NN-1);
        float v;
        if (d < 3) {
            int id = g_idx[row];
            v = xyz[((size_t)b*NN + id)*3 + d] - xyz[((size_t)b*NN + n)*3 + d];
        } else {
            v = xyz[((size_t)b*NN + n)*3 + (d-3)];
        }
        sE[r*6 + d] = v;
    }
    __syncthreads();
    int c = t & (C1-1), h = t >> 7;
    float w0 = W1[0*C1+c], w1 = W1[1*C1+c], w2 = W1[2*C1+c],
          w3 = W1[3*C1+c], w4 = W1[4*C1+c], w5 = W1[5*C1+c];
    float bb = b1[c], sc = g_ss1[c], sh = g_ss1[C1+c];
    #pragma unroll
    for (int rr = 0; rr < 8; ++rr) {
        int r = h*8 + rr;
        float hv = bb + sE[r*6+0]*w0 + sE[r*6+1]*w1 + sE[r*6+2]*w2
                      + sE[r*6+3]*w3 + sE[r*6+4]*w4 + sE[r*6+5]*w5;
        hv = fmaxf(hv*sc + sh, 0.f);
        g_Ah[(size_t)(row0 + r)*C1 + c] = __float2half_rn(hv);
    }
}

// ---------------------------------------------------------------------------
// weight prep: half2-packed [k/2][col]
// ---------------------------------------------------------------------------
__global__ void w3h_kernel(const float* __restrict__ W3) {
    int i = blockIdx.x*256 + threadIdx.x;
    if (i < 128*C3) {
        int kp = i / C3, col = i - kp*C3;
        g_w3h[i] = pack_h2(W3[(size_t)(C2 + 2*kp)*C3 + col],
                           W3[(size_t)(C2 + 2*kp + 1)*C3 + col]);
    }
}
__global__ void w4h_kernel(const float* __restrict__ W4) {
    int i = blockIdx.x*256 + threadIdx.x;
    if (i < 256*CH) {
        int kp = i / CH, col = i - kp*CH;
        g_w4h[i] = pack_h2(W4[(size_t)(2*kp)*CH + col],
                           W4[(size_t)(2*kp + 1)*CH + col]);
    }
}

// ===========================================================================
// fp16 m16n8k16 tile configs
// ===========================================================================
#define GM_MT 128
#define GM_MT2 256
#define GM_NT 64
#define GM_KC 32
#define SAH 20
#define SBH 72
#define A_BUFH  (GM_MT*SAH)     // 2560 u32
#define A_BUFH2 (GM_MT2*SAH)    // 5120 u32
#define B_BUFH  (16*SBH)        // 1152 u32

#define MMA_F16(acc, af, bf) \
    asm volatile( \
        "mma.sync.aligned.m16n8k16.row.col.f32.f16.f16.f32 " \
        "{%0,%1,%2,%3}, {%4,%5,%6,%7}, {%8,%9}, {%0,%1,%2,%3};" \
        : "+f"((acc)[0]), "+f"((acc)[1]), "+f"((acc)[2]), "+f"((acc)[3]) \
        : "r"((af)[0]), "r"((af)[1]), "r"((af)[2]), "r"((af)[3]), \
          "r"((bf)[0]), "r"((bf)[1]))

// ---------------------------------------------------------------------------
// gemm2: H2 = A @ W2 + b2 (fp16 in, fp16 out). CTA 128x64. (unchanged)
// ---------------------------------------------------------------------------
__global__ __launch_bounds__(128) void gemm2_kernel(
    const float* __restrict__ W2, const float* __restrict__ b2) {
    __shared__ __align__(16) uint32_t sA[GM_MT*SAH];
    __shared__ __align__(16) uint32_t sB[16*SBH];
    int t = threadIdx.x;
    int w = t >> 5, lane = t & 31;
    int g = lane >> 2, tig = lane & 3;
    size_t row0 = (size_t)blockIdx.y * GM_MT;
    int n0 = blockIdx.x * GM_NT;

    float acc[2][8][4] = {};

    for (int kk = 0; kk < C1; kk += GM_KC) {
        #pragma unroll
        for (int pq = 0; pq < 4; ++pq) {
            int r = pq*32 + (t>>2), seg = t&3;
            uint4 v = *(const uint4*)(g_Ah + (row0 + r)*C1 + kk + seg*8);
            *(uint4*)&sA[r*SAH + seg*4] = v;
        }
        #pragma unroll
        for (int pq = 0; pq < 2; ++pq) {
            int kp = pq*8 + (t>>4), colb = (t&15)*4;
            const float* s0 = &W2[(size_t)(kk + 2*kp)*C2 + n0 + colb];
            float4 va = *(const float4*)s0;
            float4 vb = *(const float4*)(s0 + C2);
            uint4 o = make_uint4(pack_h2(va.x, vb.x), pack_h2(va.y, vb.y),
                                 pack_h2(va.z, vb.z), pack_h2(va.w, vb.w));
            *(uint4*)&sB[kp*SBH + colb] = o;
        }
        __syncthreads();
        #pragma unroll
        for (int ks = 0; ks < 2; ++ks) {
            int kb = ks*8;
            uint32_t bf[8][2];
            #pragma unroll
            for (int n = 0; n < 8; ++n) {
                bf[n][0] = sB[(kb+tig)*SBH   + n*8 + g];
                bf[n][1] = sB[(kb+tig+4)*SBH + n*8 + g];
            }
            #pragma unroll
            for (int m = 0; m < 2; ++m) {
                int mr = w*32 + m*16;
                uint32_t af[4];
                af[0] = sA[(mr+g)*SAH   + kb + tig];
                af[1] = sA[(mr+g+8)*SAH + kb + tig];
                af[2] = sA[(mr+g)*SAH   + kb + tig + 4];
                af[3] = sA[(mr+g+8)*SAH + kb + tig + 4];
                #pragma unroll
                for (int n = 0; n < 8; ++n) MMA_F16(acc[m][n], af, bf[n]);
            }
        }
        __syncthreads();
    }
    uint32_t* H2v = (uint32_t*)g_H2h;
    #pragma unroll
    for (int m = 0; m < 2; ++m) {
        size_t r0 = row0 + w*32 + m*16 + g;
        #pragma unroll
        for (int n = 0; n < 8; ++n) {
            int col = n0 + n*8 + 2*tig;
            float2 bb = *(const float2*)&b2[col];
            H2v[r0*(C2/2) + col/2]     = pack_h2(acc[m][n][0]+bb.x, acc[m][n][1]+bb.y);
            H2v[(r0+8)*(C2/2) + col/2] = pack_h2(acc[m][n][2]+bb.x, acc[m][n][3]+bb.y);
        }
    }
}

// ---------------------------------------------------------------------------
// gmax over fp16 pairs (unchanged)
// ---------------------------------------------------------------------------
__global__ void gmax_kernel() {
    int p = blockIdx.x, t = threadIdx.x;   // 128 threads
    const __half2* src = (const __half2*)g_H2h + (size_t)p*KNBR*(C2/2) + t;
    __half2 m = src[0];
    #pragma unroll
    for (int r = 1; r < KNBR; ++r) m = __hmax2(m, src[(size_t)r*(C2/2)]);
    ((__half2*)g_gmaxh)[(size_t)p*(C2/2) + t] = m;
}

// ---------------------------------------------------------------------------
// gemmFA: fA = gmax @ W3[0:256] + b3 (unchanged)
// ---------------------------------------------------------------------------
__global__ __launch_bounds__(128) void gemmFA_kernel(
    const float* __restrict__ W3, const float* __restrict__ b3) {
    __shared__ __align__(16) uint32_t sA[GM_MT*SAH];
    __shared__ __align__(16) uint32_t sB[16*SBH];
    int t = threadIdx.x;
    int w = t >> 5, lane = t & 31;
    int g = lane >> 2, tig = lane & 3;
    size_t row0 = (size_t)blockIdx.y * GM_MT;
    int n0 = blockIdx.x * GM_NT;

    float acc[2][8][4] = {};

    for (int kk = 0; kk < C2; kk += GM_KC) {
        #pragma unroll
        for (int pq = 0; pq < 4; ++pq) {
            int r = pq*32 + (t>>2), seg = t&3;
            uint4 v = *(const uint4*)(g_gmaxh + (row0 + r)*C2 + kk + seg*8);
            *(uint4*)&sA[r*SAH + seg*4] = v;
        }
        #pragma unroll
        for (int pq = 0; pq < 2; ++pq) {
            int kp = pq*8 + (t>>4), colb = (t&15)*4;
            const float* s0 = &W3[(size_t)(kk + 2*kp)*C3 + n0 + colb];
            float4 va = *(const float4*)s0;
            float4 vb = *(const float4*)(s0 + C3);
            uint4 o = make_uint4(pack_h2(va.x, vb.x), pack_h2(va.y, vb.y),
                                 pack_h2(va.z, vb.z), pack_h2(va.w, vb.w));
            *(uint4*)&sB[kp*SBH + colb] = o;
        }
        __syncthreads();
        #pragma unroll
        for (int ks = 0; ks < 2; ++ks) {
            int kb = ks*8;
            uint32_t bf[8][2];
            #pragma unroll
            for (int n = 0; n < 8; ++n) {
                bf[n][0] = sB[(kb+tig)*SBH   + n*8 + g];
                bf[n][1] = sB[(kb+tig+4)*SBH + n*8 + g];
            }
            #pragma unroll
            for (int m = 0; m < 2; ++m) {
                int mr = w*32 + m*16;
                uint32_t af[4];
                af[0] = sA[(mr+g)*SAH   + kb + tig];
                af[1] = sA[(mr+g+8)*SAH + kb + tig];
                af[2] = sA[(mr+g)*SAH   + kb + tig + 4];
                af[3] = sA[(mr+g+8)*SAH + kb + tig + 4];
                #pragma unroll
                for (int n = 0; n < 8; ++n) MMA_F16(acc[m][n], af, bf[n]);
            }
        }
        __syncthreads();
    }
    #pragma unroll
    for (int m = 0; m < 2; ++m) {
        size_t r0 = row0 + w*32 + m*16 + g;
        #pragma unroll
        for (int n = 0; n < 8; ++n) {
            int col = n0 + n*8 + 2*tig;
            float2 bb = *(const float2*)&b3[col];
            *(float2*)&g_fA[r0*C3 + col]     = make_float2(acc[m][n][0]+bb.x, acc[m][n][1]+bb.y);
            *(float2*)&g_fA[(r0+8)*C3 + col] = make_float2(acc[m][n][2]+bb.x, acc[m][n][3]+bb.y);
        }
    }
}

// ---------------------------------------------------------------------------
// gemm3 load helper (one pipeline stage)
// ---------------------------------------------------------------------------
__device__ __forceinline__ void g3_load(uint32_t* A, uint32_t* B,
                                        size_t row0, int n0, int kk, int t) {
    #pragma unroll
    for (int pq = 0; pq < 8; ++pq) {
        int r = pq*32 + (t>>2), seg = t&3;
        cp16(&A[r*SAH + seg*4], g_H2h + (row0 + r)*C2 + kk + seg*8);
    }
    int kp = t>>3, s0 = t&7;
    int kpg = (kk>>1) + kp;
    cp16(&B[kp*SBH + s0*4],     &g_w3h[(size_t)kpg*C3 + n0 + s0*4]);
    cp16(&B[kp*SBH + (s0+8)*4], &g_w3h[(size_t)kpg*C3 + n0 + (s0+8)*4]);
}

// ---------------------------------------------------------------------------
// gemm3 (3-stage cp.async, CTA 256x64, fp16, ldmatrix A, fused BN3 partials)
// ---------------------------------------------------------------------------
#define G3_SMEM ((3*A_BUFH2 + 3*B_BUFH + 512)*4)
__global__ __launch_bounds__(128) void gemm3_kernel() {
    extern __shared__ __align__(16) uint32_t dyn[];
    uint32_t* bufA = dyn;                          // 3 x A_BUFH2
    uint32_t* bufB = dyn + 3*A_BUFH2;              // 3 x B_BUFH
    float* sstat = (float*)(dyn + 3*A_BUFH2 + 3*B_BUFH);
    int t = threadIdx.x;
    int w = t >> 5, lane = t & 31;
    int g = lane >> 2, tig = lane & 3;
    int roff = lane & 15, koff = (lane >> 4) * 4;   // ldmatrix per-lane offsets
    size_t row0 = (size_t)blockIdx.y * GM_MT2;
    int n0 = blockIdx.x * GM_NT;
    uint32_t sbA0 = (uint32_t)__cvta_generic_to_shared(bufA);

    float acc[4][8][4] = {};
    const int NC = C2/GM_KC;  // 8

    g3_load(bufA, bufB, row0, n0, 0, t);                      CP_COMMIT();
    g3_load(bufA + A_BUFH2, bufB + B_BUFH, row0, n0, 32, t);  CP_COMMIT();

    for (int c = 0; c < NC; ++c) {
        int cur = c % 3;
        if (c + 2 < NC) {
            int st = (c+2) % 3;
            g3_load(bufA + st*A_BUFH2, bufB + st*B_BUFH, row0, n0, (c+2)*GM_KC, t);
            CP_COMMIT();
            CP_WAIT(2);
        } else if (c + 1 < NC) {
            CP_WAIT(1);
        } else {
            CP_WAIT(0);
        }
        __syncthreads();

        uint32_t sbA = sbA0 + cur*A_BUFH2*4;
        uint32_t* B = bufB + cur*B_BUFH;
        #pragma unroll
        for (int ks = 0; ks < 2; ++ks) {
            int kb = ks*8;
            uint32_t bf[8][2];
            #pragma unroll
            for (int n = 0; n < 8; ++n) {
                bf[n][0] = B[(kb+tig)*SBH   + n*8 + g];
                bf[n][1] = B[(kb+tig+4)*SBH + n*8 + g];
            }
            #pragma unroll
            for (int m = 0; m < 4; ++m) {
                int mr = w*64 + m*16;
                uint32_t af[4];
                ldsm4(af, sbA + ((mr + roff)*SAH + kb + koff)*4);
                #pragma unroll
                for (int n = 0; n < 8; ++n) MMA_F16(acc[m][n], af, bf[n]);
            }
        }
        __syncthreads();
    }

    // epilogue: add fA, write fp16 fpre, accumulate column stats (fp32)
    uint32_t* FPv = (uint32_t*)g_fpreh;
    float sloc[8][2], qloc[8][2];
    #pragma unroll
    for (int n = 0; n < 8; ++n) { sloc[n][0]=0.f; sloc[n][1]=0.f; qloc[n][0]=0.f; qloc[n][1]=0.f; }
    #pragma unroll
    for (int m = 0; m < 4; ++m) {
        size_t rA = row0 + w*64 + m*16 + g;
        size_t rB = rA + 8;
        size_t pA = rA / KNBR, pB = rB / KNBR;
        #pragma unroll
        for (int n = 0; n < 8; ++n) {
            int col = n0 + n*8 + 2*tig;
            float2 fa = *(const float2*)&g_fA[pA*C3 + col];
            float2 fb = *(const float2*)&g_fA[pB*C3 + col];
            float v0 = acc[m][n][0]+fa.x, v1 = acc[m][n][1]+fa.y;
            float v2 = acc[m][n][2]+fb.x, v3 = acc[m][n][3]+fb.y;
            FPv[rA*(C3/2) + col/2] = pack_h2(v0, v1);
            FPv[rB*(C3/2) + col/2] = pack_h2(v2, v3);
            sloc[n][0] += v0 + v2;   qloc[n][0] += v0*v0 + v2*v2;
            sloc[n][1] += v1 + v3;   qloc[n][1] += v1*v1 + v3*v3;
        }
    }
    #pragma unroll
    for (int n = 0; n < 8; ++n)
        #pragma unroll
        for (int j = 0; j < 2; ++j) {
            float s = sloc[n][j], q = qloc[n][j];
            #pragma unroll
            for (int mk = 4; mk <= 16; mk <<= 1) {
                s += __shfl_xor_sync(0xffffffffu, s, mk);
                q += __shfl_xor_sync(0xffffffffu, q, mk);
            }
            if (g == 0) {
                int ci = n*8 + 2*tig + j;
                sstat[(w*64 + ci)*2 + 0] = s;
                sstat[(w*64 + ci)*2 + 1] = q;
            }
        }
    __syncthreads();
    if (t < 128) {
        int ci = t >> 1, which = t & 1;
        float v = sstat[(0*64+ci)*2+which] + sstat[(1*64+ci)*2+which]
                + sstat[(2*64+ci)*2+which] + sstat[(3*64+ci)*2+which];
        g_p3[(size_t)blockIdx.y*(2*C3) + (size_t)which*C3 + n0 + ci] = v;
    }
}

// ---------------------------------------------------------------------------
// fin3: reduce partials, emit fp32 and half2-packed BN params
// ---------------------------------------------------------------------------
__global__ void fin3_kernel(const float* __restrict__ g3,
                            const float* __restrict__ be3) {
    __shared__ float tmp[2*C3];
    int c = threadIdx.x;   // 512
    float s = 0.f, q = 0.f;
    for (int i = 0; i < NROWS/GM_MT2; ++i) {
        s += g_p3[(size_t)i*(2*C3) + c];
        q += g_p3[(size_t)i*(2*C3) + C3 + c];
    }
    float mu  = s / (float)NROWS;
    float var = q / (float)NROWS - mu*mu;
    float sc  = g3[c] * rsqrtf(var + BN_EPS);
    float sh  = be3[c] - mu*sc;
    g_ss3[c]    = sc;
    g_ss3[C3+c] = sh;
    tmp[c] = sc; tmp[C3+c] = sh;
    __syncthreads();
    if (c < C3/2) {
        g_ss3h[c]          = pack_h2(tmp[2*c],      tmp[2*c+1]);
        g_ss3h[C3/2 + c]   = pack_h2(tmp[C3+2*c],   tmp[C3+2*c+1]);
    }
}

// ---------------------------------------------------------------------------
// init keys
// ---------------------------------------------------------------------------
__global__ void initkeys_kernel(unsigned* __restrict__ keys) {
    int i = blockIdx.x*256 + threadIdx.x;
    if (i < NPTS*CH) keys[i] = 0u;
}

// ---------------------------------------------------------------------------
// gemm_final load helper
// ---------------------------------------------------------------------------
__device__ __forceinline__ void g4_load(uint32_t* A, uint32_t* B,
                                        size_t row0, int n0, int kk, int t) {
    #pragma unroll
    for (int pq = 0; pq < 8; ++pq) {
        int r = pq*32 + (t>>2), seg = t&3;
        cp16(&A[r*SAH + seg*4], g_fpreh + (row0 + r)*C3 + kk + seg*8);
    }
    int kp = t>>3, s0 = t&7;
    int kpg = (kk>>1) + kp;
    cp16(&B[kp*SBH + s0*4],     &g_w4h[(size_t)kpg*CH + n0 + s0*4]);
    cp16(&B[kp*SBH + (s0+8)*4], &g_w4h[(size_t)kpg*CH + n0 + (s0+8)*4]);
}

// ---------------------------------------------------------------------------
// gemm_final: 3-stage cp.async, CTA 256x64, fp16, ldmatrix A + half2 BN at
// fragment load (HFMA2+HMAX2), grouped atomicMax maxpool epilogue.
// ---------------------------------------------------------------------------
#define GF_SMEM ((3*A_BUFH2 + 3*B_BUFH + 512)*4)
__global__ __launch_bounds__(128) void gemm_final_kernel(unsigned* __restrict__ keys) {
    extern __shared__ __align__(16) uint32_t dyn[];
    uint32_t* bufA = dyn;
    uint32_t* bufB = dyn + 3*A_BUFH2;
    uint32_t* sSh = dyn + 3*A_BUFH2 + 3*B_BUFH;   // [sc2 256][sh2 256]
    int t = threadIdx.x;
    int w = t >> 5, lane = t & 31;
    int g = lane >> 2, tig = lane & 3;
    int roff = lane & 15, koff = (lane >> 4) * 4;
    size_t row0 = (size_t)blockIdx.y * GM_MT2;
    int n0 = blockIdx.x * GM_NT;
    uint32_t sbA0 = (uint32_t)__cvta_generic_to_shared(bufA);

    float acc[4][8][4] = {};
    const int NC = C3/GM_KC;  // 16

    for (int i = t; i < 2*(C3/2); i += 128) sSh[i] = g_ss3h[i];

    g4_load(bufA, bufB, row0, n0, 0, t);                      CP_COMMIT();
    g4_load(bufA + A_BUFH2, bufB + B_BUFH, row0, n0, 32, t);  CP_COMMIT();

    for (int c = 0; c < NC; ++c) {
        int cur = c % 3;
        if (c + 2 < NC) {
            int st = (c+2) % 3;
            g4_load(bufA + st*A_BUFH2, bufB + st*B_BUFH, row0, n0, (c+2)*GM_KC, t);
            CP_COMMIT();
            CP_WAIT(2);
        } else if (c + 1 < NC) {
            CP_WAIT(1);
        } else {
            CP_WAIT(0);
        }
        __syncthreads();

        uint32_t sbA = sbA0 + cur*A_BUFH2*4;
        uint32_t* B = bufB + cur*B_BUFH;
        int kk = c*GM_KC;
        #pragma unroll
        for (int ks = 0; ks < 2; ++ks) {
            int kb = ks*8;
            int kpg0 = (kk>>1) + kb + tig;
            uint32_t sc0 = sSh[kpg0],     sh0 = sSh[C3/2 + kpg0];
            uint32_t sc4 = sSh[kpg0 + 4], sh4 = sSh[C3/2 + kpg0 + 4];
            uint32_t bf[8][2];
            #pragma unroll
            for (int n = 0; n < 8; ++n) {
                bf[n][0] = B[(kb+tig)*SBH   + n*8 + g];
                bf[n][1] = B[(kb+tig+4)*SBH + n*8 + g];
            }
            #pragma unroll
            for (int m = 0; m < 4; ++m) {
                int mr = w*64 + m*16;
                uint32_t af[4];
                ldsm4(af, sbA + ((mr + roff)*SAH + kb + koff)*4);
                af[0] = bnfrag_h2(af[0], sc0, sh0);
                af[1] = bnfrag_h2(af[1], sc0, sh0);
                af[2] = bnfrag_h2(af[2], sc4, sh4);
                af[3] = bnfrag_h2(af[3], sc4, sh4);
                #pragma unroll
                for (int n = 0; n < 8; ++n) MMA_F16(acc[m][n], af, bf[n]);
            }
        }
        __syncthreads();
    }

    // grouped-atomic maxpool epilogue
    #pragma unroll
    for (int n = 0; n < 8; ++n) {
        #pragma unroll
        for (int cc = 0; cc < 2; ++cc) {
            int col = n0 + n*8 + 2*tig + cc;
            size_t curp = (row0 + w*64 + g) / KNBR;
            float rm = -FLT_MAX;
            #pragma unroll
            for (int j = 0; j < 8; ++j) {
                size_t row = row0 + w*64 + g + 8*j;
                size_t pj = row / KNBR;
                float v = acc[j>>1][n][((j&1)<<1) + cc];
                if (pj != curp) {
                    atomicMax(&keys[curp*CH + col], fenc(rm));
                    curp = pj; rm = v;
                } else {
                    rm = fmaxf(rm, v);
                }
            }
            atomicMax(&keys[curp*CH + col], fenc(rm));
        }
    }
}

// ---------------------------------------------------------------------------
// decode keys in place + add b4
// ---------------------------------------------------------------------------
__global__ void decode_kernel(float* __restrict__ out, const float* __restrict__ b4) {
    int i = blockIdx.x*256 + threadIdx.x;
    if (i < NPTS*CH) {
        int c = i % CH;
        unsigned k = ((const unsigned*)(out + (size_t)BB*NN*3))[i];
        out[(size_t)BB*NN*3 + i] = fdec(k) + b4[c];
    }
}

__global__ void copy_xyz_kernel(const float* __restrict__ xyz,
                                float* __restrict__ out) {
    int i = blockIdx.x*256 + threadIdx.x;
    if (i < BB*NN*3) out[i] = xyz[i];
}

extern "C" void kernel_launch(void* const* d_in, const int* in_sizes, int n_in,
                              void* d_out, int out_size) {
    (void)in_sizes; (void)n_in; (void)out_size;
    const float* xyz = (const float*)d_in[0];
    const float* W1  = (const float*)d_in[1];
    const float* b1  = (const float*)d_in[2];
    const float* g1  = (const float*)d_in[3];
    const float* be1 = (const float*)d_in[4];
    const float* W2  = (const float*)d_in[5];
    const float* b2  = (const float*)d_in[6];
    const float* W3  = (const float*)d_in[7];
    const float* b3  = (const float*)d_in[8];
    const float* g3  = (const float*)d_in[9];
    const float* be3 = (const float*)d_in[10];
    const float* W4  = (const float*)d_in[11];
    const float* b4  = (const float*)d_in[12];
    float* out = (float*)d_out;
    unsigned* keys = (unsigned*)(out + (size_t)BB*NN*3);

    static int smem_set = 0;
    if (!smem_set) {
        cudaFuncSetAttribute(gemm3_kernel, cudaFuncAttributeMaxDynamicSharedMemorySize, G3_SMEM);
        cudaFuncSetAttribute(gemm_final_kernel, cudaFuncAttributeMaxDynamicSharedMemorySize, GF_SMEM);
        smem_set = 1;
    }

    knn_kernel<<<NPTS, 256>>>(xyz);
    stats1_kernel<<<STAT_BLOCKS, 128>>>(xyz, W1, b1);
    fin1_kernel<<<1, C1>>>(g1, be1);
    edge_kernel<<<NROWS/16, 256>>>(xyz, W1, b1);
    w3h_kernel<<<(128*C3 + 255)/256, 256>>>(W3);
    w4h_kernel<<<(256*CH + 255)/256, 256>>>(W4);
    {
        dim3 grid2(C2/GM_NT, NROWS/GM_MT);   // (4, 1280)
        gemm2_kernel<<<grid2, 128>>>(W2, b2);
    }
    gmax_kernel<<<NPTS, 128>>>();
    {
        dim3 gridFA(C3/GM_NT, NPTS/GM_MT);   // (8, 64)
        gemmFA_kernel<<<gridFA, 128>>>(W3, b3);
    }
    {
        dim3 grid3(C3/GM_NT, NROWS/GM_MT2);  // (8, 640)
        gemm3_kernel<<<grid3, 128, G3_SMEM>>>();
    }
    fin3_kernel<<<1, C3>>>(g3, be3);
    initkeys_kernel<<<(NPTS*CH + 255)/256, 256>>>(keys);
    {
        dim3 grid4(CH/GM_NT, NROWS/GM_MT2);  // (6, 640)
        gemm_final_kernel<<<grid4, 128, GF_SMEM>>>(keys);
    }
    decode_kernel<<<(NPTS*CH + 255)/256, 256>>>(out, b4);
    copy_xyz_kernel<<<(BB*NN*3 + 255)/256, 256>>>(xyz, out);
}